// round 7
// baseline (speedup 1.0000x reference)
#include <cuda_runtime.h>
#include <cuda_fp16.h>
#include <cstdint>

// ---------------- problem constants ----------------
#define BDIM     4
#define SEQ      8192
#define CDIM     512
#define NH       8
#define HD       64
#define NLM      64
#define LMSTRIDE 128           // SEQ / NLM
#define BN_TOK   (BDIM*SEQ)    // 32768
#define QKV_N    (3*CDIM)      // 1536
#define NBH      (BDIM*NH)     // 32
#define NCH      32            // key chunks for kernel_3 flash
#define KEYS_PER_CH (SEQ/NCH)  // 256
#define SCALE    0.125f        // hd^-0.5

// ---------------- device scratch (no runtime allocs allowed) ----------------
__device__ __half gXh[(size_t)BN_TOK * CDIM];    // x in fp16
__device__ __half gWqkvh[QKV_N * CDIM];          // Wqkv in fp16
__device__ __half gWph[CDIM * CDIM];             // Wproj in fp16
__device__ __half gYh[(size_t)BN_TOK * QKV_N];   // qkv activations fp16
__device__ __half gATh[(size_t)BN_TOK * CDIM];   // attention output fp16
__device__ float  gW2inv[NBH*64*64];
__device__ __half gTth[NBH*64*64];               // (W2inv @ F)^T fp16, [bh][hd][lm]
__device__ float  gFp[(size_t)NBH*NCH*64*64];    // flash partial accumulators
__device__ float  gMp[NBH*NCH*64];
__device__ float  gSp[NBH*NCH*64];

// ---------------- ptx helpers ------------------------------------------------
__device__ __forceinline__ uint32_t smem_u32(const void* p) {
    uint32_t a;
    asm("{ .reg .u64 t; cvta.to.shared.u64 t, %1; cvt.u32.u64 %0, t; }" : "=r"(a) : "l"(p));
    return a;
}
__device__ __forceinline__ void mma_f16(float* d, const uint32_t* a, const uint32_t* b) {
    asm volatile(
        "mma.sync.aligned.m16n8k16.row.col.f32.f16.f16.f32 "
        "{%0,%1,%2,%3}, {%4,%5,%6,%7}, {%8,%9}, {%0,%1,%2,%3};"
        : "+f"(d[0]), "+f"(d[1]), "+f"(d[2]), "+f"(d[3])
        : "r"(a[0]), "r"(a[1]), "r"(a[2]), "r"(a[3]),
          "r"(b[0]), "r"(b[1]));
}
__device__ __forceinline__ void ldsm_x4(uint32_t* r, uint32_t addr) {
    asm volatile("ldmatrix.sync.aligned.m8n8.x4.shared.b16 {%0,%1,%2,%3}, [%4];"
                 : "=r"(r[0]), "=r"(r[1]), "=r"(r[2]), "=r"(r[3]) : "r"(addr));
}
__device__ __forceinline__ void ldsm_x4_t(uint32_t* r, uint32_t addr) {
    asm volatile("ldmatrix.sync.aligned.m8n8.x4.trans.shared.b16 {%0,%1,%2,%3}, [%4];"
                 : "=r"(r[0]), "=r"(r[1]), "=r"(r[2]), "=r"(r[3]) : "r"(addr));
}
#define CP_ASYNC16(dst, src) \
    asm volatile("cp.async.cg.shared.global [%0], [%1], 16;" :: "r"(dst), "l"(src) : "memory")
#define CP_COMMIT() asm volatile("cp.async.commit_group;" ::: "memory")
#define CP_WAIT1()  asm volatile("cp.async.wait_group 1;" ::: "memory")
#define CP_WAIT0()  asm volatile("cp.async.wait_group 0;" ::: "memory")

// ---------------- fp32 -> fp16 conversion ------------------------------------
__global__ void __launch_bounds__(256) cvtf2h(const float* __restrict__ s,
                                              __half* __restrict__ d, int n)
{
    int i = (blockIdx.x * blockDim.x + threadIdx.x) * 8;
    if (i < n) {
        float4 a = *(const float4*)(s + i);
        float4 b = *(const float4*)(s + i + 4);
        __half2 h0 = __floats2half2_rn(a.x, a.y);
        __half2 h1 = __floats2half2_rn(a.z, a.w);
        __half2 h2 = __floats2half2_rn(b.x, b.y);
        __half2 h3 = __floats2half2_rn(b.z, b.w);
        uint4 o;
        o.x = *(uint32_t*)&h0; o.y = *(uint32_t*)&h1;
        o.z = *(uint32_t*)&h2; o.w = *(uint32_t*)&h3;
        *(uint4*)(d + i) = o;
    }
}

// ---------------- fp16 tensor-core GEMM: C = A[M,K]h @ B[N,K]h^T + bias -----
// block tile 128x256, 8 warps (2x4) of 64x64; 3-stage cp.async ring.
#define STG2 49152               // 16KB A + 32KB B per stage
#define SMEM_G2 (3 * STG2)       // 147456

__device__ __forceinline__ void stage_copy2(uint32_t sbase, const __half* A,
                                            const __half* B, int bm, int bn,
                                            int K, int k0, int tid)
{
    #pragma unroll
    for (int i = 0; i < 4; i++) {            // A: 128 rows x 8 chunks
        int lin = tid + i * 256;
        int row = lin >> 3;
        int c   = lin & 7;
        CP_ASYNC16(sbase + row * 128 + ((c ^ (row & 7)) << 4),
                   A + (size_t)(bm + row) * K + k0 + c * 8);
    }
    #pragma unroll
    for (int i = 0; i < 8; i++) {            // B: 256 rows x 8 chunks
        int lin = tid + i * 256;
        int row = lin >> 3;
        int c   = lin & 7;
        CP_ASYNC16(sbase + 16384 + row * 128 + ((c ^ (row & 7)) << 4),
                   B + (size_t)(bn + row) * K + k0 + c * 8);
    }
}

__global__ void __launch_bounds__(256) gemm_h(const __half* __restrict__ A,
                                              const __half* __restrict__ B,
                                              const float* __restrict__ bias,
                                              void* __restrict__ Cv,
                                              int M, int N, int K, int half_out)
{
    extern __shared__ __align__(128) char smg[];
    const uint32_t sb = smem_u32(smg);

    const int bm = blockIdx.y * 128;
    const int bn = blockIdx.x * 256;
    const int tid  = threadIdx.x;
    const int lane = tid & 31;
    const int warp = tid >> 5;
    const int wm = (warp & 1) * 64;      // 2 M-warps
    const int wn = (warp >> 1) * 64;     // 4 N-warps
    const int g = lane >> 2;
    const int c = lane & 3;
    const int lrow = lane & 15;
    const int lhalf = lane >> 4;

    float acc[4][8][4];
    #pragma unroll
    for (int mi = 0; mi < 4; mi++)
        #pragma unroll
        for (int t = 0; t < 8; t++)
            #pragma unroll
            for (int r = 0; r < 4; r++) acc[mi][t][r] = 0.f;

    const int KT = K >> 6;

    stage_copy2(sb, A, B, bm, bn, K, 0, tid);
    CP_COMMIT();
    stage_copy2(sb + STG2, A, B, bm, bn, K, 64, tid);
    CP_COMMIT();

    for (int kt = 0; kt < KT; kt++) {
        CP_WAIT1();
        __syncthreads();

        if (kt + 2 < KT)
            stage_copy2(sb + ((kt + 2) % 3) * STG2, A, B, bm, bn, K, (kt + 2) * 64, tid);
        CP_COMMIT();

        const uint32_t aBase = sb + (kt % 3) * STG2;
        const uint32_t bBase = aBase + 16384;

        #pragma unroll
        for (int ks = 0; ks < 4; ks++) {
            uint32_t af[4][4], bf[4][4];
            #pragma unroll
            for (int mi = 0; mi < 4; mi++) {
                const int row = wm + mi * 16 + lrow;
                const int ch  = (ks * 2 + lhalf) ^ (row & 7);
                ldsm_x4(af[mi], aBase + row * 128 + (ch << 4));
            }
            #pragma unroll
            for (int nj = 0; nj < 4; nj++) {
                const int row = wn + nj * 16 + lrow;
                const int ch  = (ks * 2 + lhalf) ^ (row & 7);
                ldsm_x4(bf[nj], bBase + row * 128 + (ch << 4));
            }
            #pragma unroll
            for (int mi = 0; mi < 4; mi++) {
                #pragma unroll
                for (int t = 0; t < 8; t++) {
                    const int nj = t >> 1, sub = t & 1;
                    uint32_t b2[2] = { bf[nj][sub], bf[nj][sub + 2] };
                    mma_f16(acc[mi][t], af[mi], b2);
                }
            }
        }
    }

    if (half_out) {
        __half* C = (__half*)Cv;
        #pragma unroll
        for (int mi = 0; mi < 4; mi++) {
            const int row = bm + wm + mi * 16 + g;
            #pragma unroll
            for (int t = 0; t < 8; t++) {
                const int col = bn + wn + (t >> 1) * 16 + (t & 1) * 8 + 2 * c;
                const float b0 = bias[col], b1 = bias[col + 1];
                __half2 o0 = __floats2half2_rn(acc[mi][t][0] + b0, acc[mi][t][1] + b1);
                __half2 o1 = __floats2half2_rn(acc[mi][t][2] + b0, acc[mi][t][3] + b1);
                *(uint32_t*)(C + (size_t)row * N + col)       = *(uint32_t*)&o0;
                *(uint32_t*)(C + (size_t)(row + 8) * N + col) = *(uint32_t*)&o1;
            }
        }
    } else {
        float* C = (float*)Cv;
        #pragma unroll
        for (int mi = 0; mi < 4; mi++) {
            const int row = bm + wm + mi * 16 + g;
            #pragma unroll
            for (int t = 0; t < 8; t++) {
                const int col = bn + wn + (t >> 1) * 16 + (t & 1) * 8 + 2 * c;
                const float b0 = bias[col], b1 = bias[col + 1];
                float2 o0 = make_float2(acc[mi][t][0] + b0, acc[mi][t][1] + b1);
                float2 o1 = make_float2(acc[mi][t][2] + b0, acc[mi][t][3] + b1);
                *(float2*)(C + (size_t)row * N + col)       = o0;
                *(float2*)(C + (size_t)(row + 8) * N + col) = o1;
            }
        }
    }
}

// ---------------- small 64x64 fp32 helpers (k2/combine only) -----------------
__device__ __forceinline__ void mm64_nt(float* C, int ldc,
                                        const float* A, int lda,
                                        const float* B, int ldb,
                                        float scale, int tid)
{
    const int i0 = (tid >> 4) * 4, j0 = (tid & 15) * 4;
    float c[4][4] = {};
    #pragma unroll 8
    for (int d = 0; d < 64; d++) {
        float a[4], bv[4];
        #pragma unroll
        for (int ii = 0; ii < 4; ii++) a[ii]  = A[(i0+ii)*lda + d];
        #pragma unroll
        for (int jj = 0; jj < 4; jj++) bv[jj] = B[(j0+jj)*ldb + d];
        #pragma unroll
        for (int ii = 0; ii < 4; ii++)
            #pragma unroll
            for (int jj = 0; jj < 4; jj++)
                c[ii][jj] += a[ii] * bv[jj];
    }
    #pragma unroll
    for (int ii = 0; ii < 4; ii++)
        #pragma unroll
        for (int jj = 0; jj < 4; jj++)
            C[(i0+ii)*ldc + j0+jj] = scale * c[ii][jj];
}

__device__ __forceinline__ void mm64_nn(float* C, int ldc,
                                        const float* A, int lda,
                                        const float* B, int ldb, int tid)
{
    const int i0 = (tid >> 4) * 4, j0 = (tid & 15) * 4;
    float c[4][4] = {};
    #pragma unroll 8
    for (int k = 0; k < 64; k++) {
        float a[4], bv[4];
        #pragma unroll
        for (int ii = 0; ii < 4; ii++) a[ii]  = A[(i0+ii)*lda + k];
        #pragma unroll
        for (int jj = 0; jj < 4; jj++) bv[jj] = B[k*ldb + j0+jj];
        #pragma unroll
        for (int ii = 0; ii < 4; ii++)
            #pragma unroll
            for (int jj = 0; jj < 4; jj++)
                c[ii][jj] += a[ii] * bv[jj];
    }
    #pragma unroll
    for (int ii = 0; ii < 4; ii++)
        #pragma unroll
        for (int jj = 0; jj < 4; jj++)
            C[(i0+ii)*ldc + j0+jj] = c[ii][jj];
}

// ---------------- kernel_2 softmax + Newton pseudo-inverse -------------------
__global__ void __launch_bounds__(256) k2_newton()
{
    extern __shared__ float sm2[];
    float* S  = sm2;
    float* Z  = S  + 4160;
    float* T1 = Z  + 4160;
    float* T2 = T1 + 4160;
    __shared__ float red[8];

    const int bh = blockIdx.x;
    const int b = bh >> 3, h = bh & 7;
    const int tid = threadIdx.x;

    for (int e = tid; e < 4096; e += 256) {
        int l = e >> 6, d = e & 63;
        size_t base = (size_t)(b * SEQ + l * LMSTRIDE) * QKV_N + h * HD + d;
        Z [l*65 + d] = __half2float(gYh[base]);
        T1[l*65 + d] = __half2float(gYh[base + CDIM]);
    }
    __syncthreads();

    mm64_nt(S, 65, Z, 65, T1, 65, SCALE, tid);
    __syncthreads();
    if (tid < 64) {
        float mx = -1e30f;
        for (int j = 0; j < 64; j++) mx = fmaxf(mx, S[tid*65 + j]);
        float s = 0.f;
        for (int j = 0; j < 64; j++) { float p = __expf(S[tid*65+j] - mx); S[tid*65+j] = p; s += p; }
        float inv = 1.f / s;
        for (int j = 0; j < 64; j++) S[tid*65 + j] *= inv;
    }
    __syncthreads();

    float part = 0.f;
    for (int e = tid; e < 4096; e += 256) {
        int i = e >> 6, j = e & 63;
        float v = S[i*65 + j];
        part += v * v;
    }
    #pragma unroll
    for (int o = 16; o; o >>= 1) part += __shfl_xor_sync(0xffffffffu, part, o);
    if ((tid & 31) == 0) red[tid >> 5] = part;
    __syncthreads();
    float fro2 = red[0]+red[1]+red[2]+red[3]+red[4]+red[5]+red[6]+red[7];
    fro2 = fmaxf(fro2, 1e-12f);
    float invf = 1.f / fro2;

    for (int e = tid; e < 4096; e += 256) {
        int i = e >> 6, j = e & 63;
        Z[j*65 + i] = S[i*65 + j] * invf;
    }
    __syncthreads();

    for (int it = 0; it < 6; it++) {
        mm64_nn(T1, 65, S, 65, Z, 65, tid);
        __syncthreads();
        mm64_nn(T2, 65, Z, 65, T1, 65, tid);
        __syncthreads();
        for (int e = tid; e < 4096; e += 256) {
            int i = e >> 6, j = e & 63;
            Z[i*65 + j] = 2.f * Z[i*65 + j] - T2[i*65 + j];
        }
        __syncthreads();
    }

    for (int e = tid; e < 4096; e += 256) {
        int i = e >> 6, j = e & 63;
        gW2inv[bh*4096 + i*64 + j] = Z[i*65 + j];
    }
}

// ---------------- kernel_3 flash (tensor-core): partials ---------------------
#define K3_SMEM (8192 + 2*16384)

__global__ void __launch_bounds__(128) k3_flash()
{
    extern __shared__ __align__(128) char sm3[];
    const uint32_t sQ  = smem_u32(sm3);
    const uint32_t sKV = sQ + 8192;

    const int bh = blockIdx.x;
    const int ch = blockIdx.y;
    const int b = bh >> 3, h = bh & 7;
    const int tid = threadIdx.x;
    const int lane = tid & 31;
    const int w = tid >> 5;
    const int g = lane >> 2, c = lane & 3;
    const int lrow = lane & 15, lhalf = lane >> 4;
    const int n0base = ch * KEYS_PER_CH;

    for (int i = tid; i < 512; i += 128) {
        int row = i >> 3, c4 = i & 7;
        CP_ASYNC16(sQ + row*128 + ((c4 ^ (row&7)) << 4),
                   gYh + ((size_t)(b*SEQ + row*LMSTRIDE))*QKV_N + h*HD + c4*8);
    }
    #pragma unroll
    for (int st = 0; st < 2; st++) {
        uint32_t base = sKV + st * 16384;
        for (int i = tid; i < 1024; i += 128) {
            int sel = i >> 9;
            int row = (i >> 3) & 63;
            int c4 = i & 7;
            CP_ASYNC16(base + sel*8192 + row*128 + ((c4 ^ (row&7)) << 4),
                       gYh + ((size_t)(b*SEQ + n0base + st*64 + row))*QKV_N
                           + (sel ? 2*CDIM : CDIM) + h*HD + c4*8);
        }
        CP_COMMIT();
    }

    float m0 = -1e30f, m1 = -1e30f, s0 = 0.f, s1 = 0.f;
    float oc[8][4];
    #pragma unroll
    for (int u = 0; u < 8; u++) { oc[u][0]=oc[u][1]=oc[u][2]=oc[u][3]=0.f; }

    for (int t = 0; t < 4; t++) {
        CP_WAIT1();
        __syncthreads();
        const uint32_t kb = sKV + (t & 1) * 16384;
        const uint32_t vb = kb + 8192;

        float sc[8][4];
        #pragma unroll
        for (int u = 0; u < 8; u++) { sc[u][0]=sc[u][1]=sc[u][2]=sc[u][3]=0.f; }
        #pragma unroll
        for (int ks = 0; ks < 4; ks++) {
            uint32_t af[4];
            const int qr = w*16 + lrow;
            ldsm_x4(af, sQ + qr*128 + (((ks*2+lhalf) ^ (qr&7)) << 4));
            #pragma unroll
            for (int nj = 0; nj < 4; nj++) {
                uint32_t bf[4];
                const int kr = nj*16 + lrow;
                ldsm_x4(bf, kb + kr*128 + (((ks*2+lhalf) ^ (kr&7)) << 4));
                uint32_t b2a[2] = { bf[0], bf[2] };
                mma_f16(sc[nj*2+0], af, b2a);
                uint32_t b2b[2] = { bf[1], bf[3] };
                mma_f16(sc[nj*2+1], af, b2b);
            }
        }
        float tm0 = -1e30f, tm1 = -1e30f;
        #pragma unroll
        for (int u = 0; u < 8; u++) {
            sc[u][0]*=SCALE; sc[u][1]*=SCALE; sc[u][2]*=SCALE; sc[u][3]*=SCALE;
            tm0 = fmaxf(tm0, fmaxf(sc[u][0], sc[u][1]));
            tm1 = fmaxf(tm1, fmaxf(sc[u][2], sc[u][3]));
        }
        tm0 = fmaxf(tm0, __shfl_xor_sync(0xffffffffu, tm0, 1));
        tm0 = fmaxf(tm0, __shfl_xor_sync(0xffffffffu, tm0, 2));
        tm1 = fmaxf(tm1, __shfl_xor_sync(0xffffffffu, tm1, 1));
        tm1 = fmaxf(tm1, __shfl_xor_sync(0xffffffffu, tm1, 2));
        const float mn0 = fmaxf(m0, tm0), mn1 = fmaxf(m1, tm1);
        const float cr0 = __expf(m0 - mn0), cr1 = __expf(m1 - mn1);
        float rs0 = 0.f, rs1 = 0.f;
        uint32_t pa[4][4];
        #pragma unroll
        for (int u = 0; u < 8; u++) {
            float p0 = __expf(sc[u][0]-mn0), p1 = __expf(sc[u][1]-mn0);
            float p2 = __expf(sc[u][2]-mn1), p3 = __expf(sc[u][3]-mn1);
            rs0 += p0 + p1; rs1 += p2 + p3;
            __half2 hA = __floats2half2_rn(p0, p1);
            __half2 hB = __floats2half2_rn(p2, p3);
            pa[u>>1][(u&1)*2+0] = *(uint32_t*)&hA;
            pa[u>>1][(u&1)*2+1] = *(uint32_t*)&hB;
        }
        rs0 += __shfl_xor_sync(0xffffffffu, rs0, 1);
        rs0 += __shfl_xor_sync(0xffffffffu, rs0, 2);
        rs1 += __shfl_xor_sync(0xffffffffu, rs1, 1);
        rs1 += __shfl_xor_sync(0xffffffffu, rs1, 2);
        s0 = s0*cr0 + rs0; s1 = s1*cr1 + rs1;
        m0 = mn0; m1 = mn1;
        #pragma unroll
        for (int u = 0; u < 8; u++) {
            oc[u][0]*=cr0; oc[u][1]*=cr0; oc[u][2]*=cr1; oc[u][3]*=cr1;
        }
        #pragma unroll
        for (int ks = 0; ks < 4; ks++) {
            #pragma unroll
            for (int nj = 0; nj < 4; nj++) {
                uint32_t bf[4];
                const int rk = ks*16 + (lane&7) + ((lane>>4)&1)*8;
                const int cn = nj*2 + ((lane>>3)&1);
                ldsm_x4_t(bf, vb + rk*128 + (((cn ^ (rk&7))) << 4));
                uint32_t b2a[2] = { bf[0], bf[2] };
                mma_f16(oc[nj*2+0], pa[ks], b2a);
                uint32_t b2b[2] = { bf[1], bf[3] };
                mma_f16(oc[nj*2+1], pa[ks], b2b);
            }
        }
        __syncthreads();
        if (t + 2 < 4) {
            uint32_t base = sKV + (t & 1) * 16384;
            int n0 = n0base + (t + 2) * 64;
            for (int i = tid; i < 1024; i += 128) {
                int sel = i >> 9;
                int row = (i >> 3) & 63;
                int c4 = i & 7;
                CP_ASYNC16(base + sel*8192 + row*128 + ((c4 ^ (row&7)) << 4),
                           gYh + ((size_t)(b*SEQ + n0 + row))*QKV_N
                               + (sel ? 2*CDIM : CDIM) + h*HD + c4*8);
            }
        }
        CP_COMMIT();
    }

    const size_t fbase = ((size_t)bh*NCH + ch)*4096;
    const int r0a = w*16 + g, r1a = r0a + 8;
    #pragma unroll
    for (int u = 0; u < 8; u++) {
        int col = u*8 + 2*c;
        *(float2*)&gFp[fbase + (size_t)r0a*64 + col] = make_float2(oc[u][0], oc[u][1]);
        *(float2*)&gFp[fbase + (size_t)r1a*64 + col] = make_float2(oc[u][2], oc[u][3]);
    }
    if (c == 0) {
        gMp[(bh*NCH+ch)*64 + r0a] = m0;
        gMp[(bh*NCH+ch)*64 + r1a] = m1;
        gSp[(bh*NCH+ch)*64 + r0a] = s0;
        gSp[(bh*NCH+ch)*64 + r1a] = s1;
    }
}

// ---------------- combine flash partials + T^T = (W2inv @ F)^T ---------------
__global__ void __launch_bounds__(256) k3_combine()
{
    __shared__ float wgt[NCH*64];
    __shared__ float sF[64*65];
    __shared__ float sW[64*64];
    const int bh = blockIdx.x;
    const int tid = threadIdx.x;

    if (tid < 64) {
        float M = -1e30f;
        for (int c = 0; c < NCH; c++) M = fmaxf(M, gMp[(bh*NCH + c)*64 + tid]);
        float denom = 0.f;
        for (int c = 0; c < NCH; c++)
            denom += __expf(gMp[(bh*NCH + c)*64 + tid] - M) * gSp[(bh*NCH + c)*64 + tid];
        float invd = 1.f / denom;
        for (int c = 0; c < NCH; c++)
            wgt[c*64 + tid] = __expf(gMp[(bh*NCH + c)*64 + tid] - M) * invd;
    }
    for (int e = tid; e < 4096; e += 256) sW[e] = gW2inv[bh*4096 + e];
    __syncthreads();

    for (int e = tid; e < 4096; e += 256) {
        int l = e >> 6, d = e & 63;
        float f = 0.f;
        for (int c = 0; c < NCH; c++)
            f += gFp[((size_t)bh * NCH + c) * 4096 + e] * wgt[c*64 + l];
        sF[l*65 + d] = f;
    }
    __syncthreads();

    const int i0 = (tid >> 4) * 4, j0 = (tid & 15) * 4;
    float cc[4][4] = {};
    #pragma unroll 8
    for (int k = 0; k < 64; k++) {
        float a[4], bv[4];
        #pragma unroll
        for (int ii = 0; ii < 4; ii++) a[ii] = sW[(i0+ii)*64 + k];
        #pragma unroll
        for (int jj = 0; jj < 4; jj++) bv[jj] = sF[k*65 + j0+jj];
        #pragma unroll
        for (int ii = 0; ii < 4; ii++)
            #pragma unroll
            for (int jj = 0; jj < 4; jj++)
                cc[ii][jj] += a[ii] * bv[jj];
    }
    #pragma unroll
    for (int ii = 0; ii < 4; ii++)
        #pragma unroll
        for (int jj = 0; jj < 4; jj++)
            gTth[bh*4096 + (j0+jj)*64 + (i0+ii)] = __float2half(cc[ii][jj]);
}

// ---------------- kernel_1 @ T (tensor-core) -> gATh -------------------------
#define K4_SMEM (3*8192)

__global__ void __launch_bounds__(128) k4_out()
{
    extern __shared__ __align__(128) char sm4[];
    const uint32_t sQ = smem_u32(sm4);
    const uint32_t sK = sQ + 8192;
    const uint32_t sT = sK + 8192;

    const int qt = blockIdx.x;
    const int bh = blockIdx.y;
    const int b = bh >> 3, h = bh & 7;
    const int n0 = qt * 64;
    const int tid = threadIdx.x;
    const int lane = tid & 31;
    const int w = tid >> 5;
    const int g = lane >> 2, c = lane & 3;
    const int lrow = lane & 15, lhalf = lane >> 4;

    for (int i = tid; i < 512; i += 128) {
        int row = i >> 3, c4 = i & 7;
        uint32_t swz = (uint32_t)((c4 ^ (row & 7)) << 4);
        CP_ASYNC16(sQ + row*128 + swz,
                   gYh + ((size_t)(b*SEQ + n0 + row))*QKV_N + h*HD + c4*8);
        CP_ASYNC16(sK + row*128 + swz,
                   gYh + ((size_t)(b*SEQ + row*LMSTRIDE))*QKV_N + CDIM + h*HD + c4*8);
        CP_ASYNC16(sT + row*128 + swz,
                   gTth + bh*4096 + row*64 + c4*8);
    }
    CP_COMMIT();
    CP_WAIT0();
    __syncthreads();

    float sc[8][4];
    #pragma unroll
    for (int u = 0; u < 8; u++) { sc[u][0]=sc[u][1]=sc[u][2]=sc[u][3]=0.f; }
    #pragma unroll
    for (int ks = 0; ks < 4; ks++) {
        uint32_t af[4];
        const int qr = w*16 + lrow;
        ldsm_x4(af, sQ + qr*128 + (((ks*2+lhalf) ^ (qr&7)) << 4));
        #pragma unroll
        for (int nj = 0; nj < 4; nj++) {
            uint32_t bf[4];
            const int kr = nj*16 + lrow;
            ldsm_x4(bf, sK + kr*128 + (((ks*2+lhalf) ^ (kr&7)) << 4));
            uint32_t b2a[2] = { bf[0], bf[2] };
            mma_f16(sc[nj*2+0], af, b2a);
            uint32_t b2b[2] = { bf[1], bf[3] };
            mma_f16(sc[nj*2+1], af, b2b);
        }
    }
    float tm0 = -1e30f, tm1 = -1e30f;
    #pragma unroll
    for (int u = 0; u < 8; u++) {
        sc[u][0]*=SCALE; sc[u][1]*=SCALE; sc[u][2]*=SCALE; sc[u][3]*=SCALE;
        tm0 = fmaxf(tm0, fmaxf(sc[u][0], sc[u][1]));
        tm1 = fmaxf(tm1, fmaxf(sc[u][2], sc[u][3]));
    }
    tm0 = fmaxf(tm0, __shfl_xor_sync(0xffffffffu, tm0, 1));
    tm0 = fmaxf(tm0, __shfl_xor_sync(0xffffffffu, tm0, 2));
    tm1 = fmaxf(tm1, __shfl_xor_sync(0xffffffffu, tm1, 1));
    tm1 = fmaxf(tm1, __shfl_xor_sync(0xffffffffu, tm1, 2));
    float rs0 = 0.f, rs1 = 0.f;
    uint32_t pa[4][4];
    #pragma unroll
    for (int u = 0; u < 8; u++) {
        float p0 = __expf(sc[u][0]-tm0), p1 = __expf(sc[u][1]-tm0);
        float p2 = __expf(sc[u][2]-tm1), p3 = __expf(sc[u][3]-tm1);
        rs0 += p0 + p1; rs1 += p2 + p3;
        __half2 hA = __floats2half2_rn(p0, p1);
        __half2 hB = __floats2half2_rn(p2, p3);
        pa[u>>1][(u&1)*2+0] = *(uint32_t*)&hA;
        pa[u>>1][(u&1)*2+1] = *(uint32_t*)&hB;
    }
    rs0 += __shfl_xor_sync(0xffffffffu, rs0, 1);
    rs0 += __shfl_xor_sync(0xffffffffu, rs0, 2);
    rs1 += __shfl_xor_sync(0xffffffffu, rs1, 1);
    rs1 += __shfl_xor_sync(0xffffffffu, rs1, 2);
    const float inv0 = 1.f / rs0, inv1 = 1.f / rs1;

    float oc[8][4];
    #pragma unroll
    for (int u = 0; u < 8; u++) { oc[u][0]=oc[u][1]=oc[u][2]=oc[u][3]=0.f; }
    #pragma unroll
    for (int ks = 0; ks < 4; ks++) {
        #pragma unroll
        for (int nj = 0; nj < 4; nj++) {
            uint32_t bf[4];
            const int tr = nj*16 + lrow;
            ldsm_x4(bf, sT + tr*128 + (((ks*2+lhalf) ^ (tr&7)) << 4));
            uint32_t b2a[2] = { bf[0], bf[2] };
            mma_f16(oc[nj*2+0], pa[ks], b2a);
            uint32_t b2b[2] = { bf[1], bf[3] };
            mma_f16(oc[nj*2+1], pa[ks], b2b);
        }
    }

    const int r0a = w*16 + g;
    #pragma unroll
    for (int u = 0; u < 8; u++) {
        int col = u*8 + 2*c;
        __half2 hA = __floats2half2_rn(oc[u][0]*inv0, oc[u][1]*inv0);
        __half2 hB = __floats2half2_rn(oc[u][2]*inv1, oc[u][3]*inv1);
        *(uint32_t*)&gATh[((size_t)(b*SEQ + n0 + r0a))*CDIM + h*HD + col]     = *(uint32_t*)&hA;
        *(uint32_t*)&gATh[((size_t)(b*SEQ + n0 + r0a + 8))*CDIM + h*HD + col] = *(uint32_t*)&hB;
    }
}

// ---------------- launcher ---------------------------------------------------
extern "C" void kernel_launch(void* const* d_in, const int* in_sizes, int n_in,
                              void* d_out, int out_size)
{
    const float* x     = (const float*)d_in[0];
    const float* Wqkv  = (const float*)d_in[1];
    const float* bqkv  = (const float*)d_in[2];
    const float* Wproj = (const float*)d_in[3];
    const float* bproj = (const float*)d_in[4];
    float* out = (float*)d_out;

    const int SMEM_K2 = 4 * 4160 * 4;
    cudaFuncSetAttribute(gemm_h,    cudaFuncAttributeMaxDynamicSharedMemorySize, SMEM_G2);
    cudaFuncSetAttribute(k2_newton, cudaFuncAttributeMaxDynamicSharedMemorySize, SMEM_K2);
    cudaFuncSetAttribute(k3_flash,  cudaFuncAttributeMaxDynamicSharedMemorySize, K3_SMEM);
    cudaFuncSetAttribute(k4_out,    cudaFuncAttributeMaxDynamicSharedMemorySize, K4_SMEM);

    __half *pXh, *pWqkvh, *pWph, *pYh, *pATh;
    cudaGetSymbolAddress((void**)&pXh,    gXh);
    cudaGetSymbolAddress((void**)&pWqkvh, gWqkvh);
    cudaGetSymbolAddress((void**)&pWph,   gWph);
    cudaGetSymbolAddress((void**)&pYh,    gYh);
    cudaGetSymbolAddress((void**)&pATh,   gATh);

    // 0. fp32 -> fp16 conversions
    {
        int nx = BN_TOK * CDIM;
        cvtf2h<<<(nx/8 + 255)/256, 256>>>(x, pXh, nx);
        int nw = QKV_N * CDIM;
        cvtf2h<<<(nw/8 + 255)/256, 256>>>(Wqkv, pWqkvh, nw);
        int np = CDIM * CDIM;
        cvtf2h<<<(np/8 + 255)/256, 256>>>(Wproj, pWph, np);
    }

    // 1. QKV projection -> fp16 gYh (128x256 tiles)
    gemm_h<<<dim3(QKV_N/256, BN_TOK/128), 256, SMEM_G2>>>(pXh, pWqkvh, bqkv, pYh, BN_TOK, QKV_N, CDIM, 1);
    // 2. kernel_2 softmax + Newton inverse
    k2_newton<<<NBH, 256, SMEM_K2>>>();
    // 3. flash partials (tensor cores), combine + T^T fp16
    k3_flash<<<dim3(NBH, NCH), 128, K3_SMEM>>>();
    k3_combine<<<NBH, 256>>>();
    // 4. out = softmax(q k_lm^T) @ T (tensor cores) -> gATh fp16
    k4_out<<<dim3(SEQ/64, NBH), 128, K4_SMEM>>>();
    // 5. projection: out = gATh @ Wproj^T + bproj (fp32 out)
    gemm_h<<<dim3(CDIM/256, BN_TOK/128), 256, SMEM_G2>>>(pATh, pWph, bproj, out, BN_TOK, CDIM, CDIM, 0);
}

// round 8
// speedup vs baseline: 1.0970x; 1.0970x over previous
#include <cuda_runtime.h>
#include <cuda_fp16.h>
#include <cstdint>

// ---------------- problem constants ----------------
#define BDIM     4
#define SEQ      8192
#define CDIM     512
#define NH       8
#define HD       64
#define NLM      64
#define LMSTRIDE 128           // SEQ / NLM
#define BN_TOK   (BDIM*SEQ)    // 32768
#define QKV_N    (3*CDIM)      // 1536
#define NBH      (BDIM*NH)     // 32
#define NCH      32            // key chunks for kernel_3 flash
#define KEYS_PER_CH (SEQ/NCH)  // 256
#define SCALE    0.125f        // hd^-0.5

// ---------------- device scratch (no runtime allocs allowed) ----------------
__device__ __half gXh[(size_t)BN_TOK * CDIM];    // x in fp16
__device__ __half gWqkvh[QKV_N * CDIM];          // Wqkv in fp16
__device__ __half gWph[CDIM * CDIM];             // Wproj in fp16
__device__ __half gYh[(size_t)BN_TOK * QKV_N];   // qkv activations fp16
__device__ __half gATh[(size_t)BN_TOK * CDIM];   // attention output fp16
__device__ float  gW2inv[NBH*64*64];
__device__ __half gTth[NBH*64*64];               // (W2inv @ F)^T fp16, [bh][hd][lm]
__device__ float  gFp[(size_t)NBH*NCH*64*64];    // flash partial accumulators
__device__ float  gMp[NBH*NCH*64];
__device__ float  gSp[NBH*NCH*64];

// ---------------- ptx helpers ------------------------------------------------
__device__ __forceinline__ uint32_t smem_u32(const void* p) {
    uint32_t a;
    asm("{ .reg .u64 t; cvta.to.shared.u64 t, %1; cvt.u32.u64 %0, t; }" : "=r"(a) : "l"(p));
    return a;
}
__device__ __forceinline__ void mma_f16(float* d, const uint32_t* a, const uint32_t* b) {
    asm volatile(
        "mma.sync.aligned.m16n8k16.row.col.f32.f16.f16.f32 "
        "{%0,%1,%2,%3}, {%4,%5,%6,%7}, {%8,%9}, {%0,%1,%2,%3};"
        : "+f"(d[0]), "+f"(d[1]), "+f"(d[2]), "+f"(d[3])
        : "r"(a[0]), "r"(a[1]), "r"(a[2]), "r"(a[3]),
          "r"(b[0]), "r"(b[1]));
}
__device__ __forceinline__ void ldsm_x4(uint32_t* r, uint32_t addr) {
    asm volatile("ldmatrix.sync.aligned.m8n8.x4.shared.b16 {%0,%1,%2,%3}, [%4];"
                 : "=r"(r[0]), "=r"(r[1]), "=r"(r[2]), "=r"(r[3]) : "r"(addr));
}
__device__ __forceinline__ void ldsm_x4_t(uint32_t* r, uint32_t addr) {
    asm volatile("ldmatrix.sync.aligned.m8n8.x4.trans.shared.b16 {%0,%1,%2,%3}, [%4];"
                 : "=r"(r[0]), "=r"(r[1]), "=r"(r[2]), "=r"(r[3]) : "r"(addr));
}
#define CP_ASYNC16(dst, src) \
    asm volatile("cp.async.cg.shared.global [%0], [%1], 16;" :: "r"(dst), "l"(src) : "memory")
#define CP_COMMIT() asm volatile("cp.async.commit_group;" ::: "memory")
#define CP_WAIT1()  asm volatile("cp.async.wait_group 1;" ::: "memory")
#define CP_WAIT0()  asm volatile("cp.async.wait_group 0;" ::: "memory")

// ---------------- fp32 -> fp16 conversion ------------------------------------
__global__ void __launch_bounds__(256) cvtf2h(const float* __restrict__ s,
                                              __half* __restrict__ d, int n)
{
    int i = (blockIdx.x * blockDim.x + threadIdx.x) * 8;
    if (i < n) {
        float4 a = *(const float4*)(s + i);
        float4 b = *(const float4*)(s + i + 4);
        __half2 h0 = __floats2half2_rn(a.x, a.y);
        __half2 h1 = __floats2half2_rn(a.z, a.w);
        __half2 h2 = __floats2half2_rn(b.x, b.y);
        __half2 h3 = __floats2half2_rn(b.z, b.w);
        uint4 o;
        o.x = *(uint32_t*)&h0; o.y = *(uint32_t*)&h1;
        o.z = *(uint32_t*)&h2; o.w = *(uint32_t*)&h3;
        *(uint4*)(d + i) = o;
    }
}

// ---------------- fp16 tensor-core GEMM: C = A[M,K]h @ B[N,K]h^T + bias -----
// block tile 128x128 with FOUR warps (2x2) of 64x64; 3-stage cp.async ring.
// 2 CTAs/SM (96KB smem, ~210 regs x 128 thr): independent sync domains keep
// the tensor pipe fed across barriers.
#define STG3 32768               // 16KB A + 16KB B per stage
#define SMEM_G3 (3 * STG3)       // 98304

__device__ __forceinline__ void stage_copy3(uint32_t sbase, const __half* A,
                                            const __half* B, int bm, int bn,
                                            int K, int k0, int tid)
{
    #pragma unroll
    for (int i = 0; i < 8; i++) {            // A: 128 rows x 8 chunks
        int lin = tid + i * 128;
        int row = lin >> 3;
        int c   = lin & 7;
        CP_ASYNC16(sbase + row * 128 + ((c ^ (row & 7)) << 4),
                   A + (size_t)(bm + row) * K + k0 + c * 8);
    }
    #pragma unroll
    for (int i = 0; i < 8; i++) {            // B: 128 rows x 8 chunks
        int lin = tid + i * 128;
        int row = lin >> 3;
        int c   = lin & 7;
        CP_ASYNC16(sbase + 16384 + row * 128 + ((c ^ (row & 7)) << 4),
                   B + (size_t)(bn + row) * K + k0 + c * 8);
    }
}

__global__ void __launch_bounds__(128) gemm_h(const __half* __restrict__ A,
                                              const __half* __restrict__ B,
                                              const float* __restrict__ bias,
                                              void* __restrict__ Cv,
                                              int M, int N, int K, int half_out)
{
    extern __shared__ __align__(128) char smg[];
    const uint32_t sb = smem_u32(smg);

    const int bm = blockIdx.y * 128;
    const int bn = blockIdx.x * 128;
    const int tid  = threadIdx.x;
    const int lane = tid & 31;
    const int warp = tid >> 5;
    const int wm = (warp & 1) * 64;      // 2 M-warps
    const int wn = (warp >> 1) * 64;     // 2 N-warps
    const int g = lane >> 2;
    const int c = lane & 3;
    const int lrow = lane & 15;
    const int lhalf = lane >> 4;

    float acc[4][8][4];
    #pragma unroll
    for (int mi = 0; mi < 4; mi++)
        #pragma unroll
        for (int t = 0; t < 8; t++)
            #pragma unroll
            for (int r = 0; r < 4; r++) acc[mi][t][r] = 0.f;

    const int KT = K >> 6;

    stage_copy3(sb, A, B, bm, bn, K, 0, tid);
    CP_COMMIT();
    stage_copy3(sb + STG3, A, B, bm, bn, K, 64, tid);
    CP_COMMIT();

    for (int kt = 0; kt < KT; kt++) {
        CP_WAIT1();
        __syncthreads();

        if (kt + 2 < KT)
            stage_copy3(sb + ((kt + 2) % 3) * STG3, A, B, bm, bn, K, (kt + 2) * 64, tid);
        CP_COMMIT();

        const uint32_t aBase = sb + (kt % 3) * STG3;
        const uint32_t bBase = aBase + 16384;

        #pragma unroll
        for (int ks = 0; ks < 4; ks++) {
            uint32_t af[4][4], bf[4][4];
            #pragma unroll
            for (int mi = 0; mi < 4; mi++) {
                const int row = wm + mi * 16 + lrow;
                const int ch  = (ks * 2 + lhalf) ^ (row & 7);
                ldsm_x4(af[mi], aBase + row * 128 + (ch << 4));
            }
            #pragma unroll
            for (int nj = 0; nj < 4; nj++) {
                const int row = wn + nj * 16 + lrow;
                const int ch  = (ks * 2 + lhalf) ^ (row & 7);
                ldsm_x4(bf[nj], bBase + row * 128 + (ch << 4));
            }
            #pragma unroll
            for (int mi = 0; mi < 4; mi++) {
                #pragma unroll
                for (int t = 0; t < 8; t++) {
                    const int nj = t >> 1, sub = t & 1;
                    uint32_t b2[2] = { bf[nj][sub], bf[nj][sub + 2] };
                    mma_f16(acc[mi][t], af[mi], b2);
                }
            }
        }
    }

    if (half_out) {
        __half* C = (__half*)Cv;
        #pragma unroll
        for (int mi = 0; mi < 4; mi++) {
            const int row = bm + wm + mi * 16 + g;
            #pragma unroll
            for (int t = 0; t < 8; t++) {
                const int col = bn + wn + (t >> 1) * 16 + (t & 1) * 8 + 2 * c;
                const float b0 = bias[col], b1 = bias[col + 1];
                __half2 o0 = __floats2half2_rn(acc[mi][t][0] + b0, acc[mi][t][1] + b1);
                __half2 o1 = __floats2half2_rn(acc[mi][t][2] + b0, acc[mi][t][3] + b1);
                *(uint32_t*)(C + (size_t)row * N + col)       = *(uint32_t*)&o0;
                *(uint32_t*)(C + (size_t)(row + 8) * N + col) = *(uint32_t*)&o1;
            }
        }
    } else {
        float* C = (float*)Cv;
        #pragma unroll
        for (int mi = 0; mi < 4; mi++) {
            const int row = bm + wm + mi * 16 + g;
            #pragma unroll
            for (int t = 0; t < 8; t++) {
                const int col = bn + wn + (t >> 1) * 16 + (t & 1) * 8 + 2 * c;
                const float b0 = bias[col], b1 = bias[col + 1];
                float2 o0 = make_float2(acc[mi][t][0] + b0, acc[mi][t][1] + b1);
                float2 o1 = make_float2(acc[mi][t][2] + b0, acc[mi][t][3] + b1);
                *(float2*)(C + (size_t)row * N + col)       = o0;
                *(float2*)(C + (size_t)(row + 8) * N + col) = o1;
            }
        }
    }
}

// ---------------- small 64x64 fp32 helpers (k2/combine only) -----------------
__device__ __forceinline__ void mm64_nt(float* C, int ldc,
                                        const float* A, int lda,
                                        const float* B, int ldb,
                                        float scale, int tid)
{
    const int i0 = (tid >> 4) * 4, j0 = (tid & 15) * 4;
    float c[4][4] = {};
    #pragma unroll 8
    for (int d = 0; d < 64; d++) {
        float a[4], bv[4];
        #pragma unroll
        for (int ii = 0; ii < 4; ii++) a[ii]  = A[(i0+ii)*lda + d];
        #pragma unroll
        for (int jj = 0; jj < 4; jj++) bv[jj] = B[(j0+jj)*ldb + d];
        #pragma unroll
        for (int ii = 0; ii < 4; ii++)
            #pragma unroll
            for (int jj = 0; jj < 4; jj++)
                c[ii][jj] += a[ii] * bv[jj];
    }
    #pragma unroll
    for (int ii = 0; ii < 4; ii++)
        #pragma unroll
        for (int jj = 0; jj < 4; jj++)
            C[(i0+ii)*ldc + j0+jj] = scale * c[ii][jj];
}

__device__ __forceinline__ void mm64_nn(float* C, int ldc,
                                        const float* A, int lda,
                                        const float* B, int ldb, int tid)
{
    const int i0 = (tid >> 4) * 4, j0 = (tid & 15) * 4;
    float c[4][4] = {};
    #pragma unroll 8
    for (int k = 0; k < 64; k++) {
        float a[4], bv[4];
        #pragma unroll
        for (int ii = 0; ii < 4; ii++) a[ii]  = A[(i0+ii)*lda + k];
        #pragma unroll
        for (int jj = 0; jj < 4; jj++) bv[jj] = B[k*ldb + j0+jj];
        #pragma unroll
        for (int ii = 0; ii < 4; ii++)
            #pragma unroll
            for (int jj = 0; jj < 4; jj++)
                c[ii][jj] += a[ii] * bv[jj];
    }
    #pragma unroll
    for (int ii = 0; ii < 4; ii++)
        #pragma unroll
        for (int jj = 0; jj < 4; jj++)
            C[(i0+ii)*ldc + j0+jj] = c[ii][jj];
}

// ---------------- kernel_2 softmax + Newton pseudo-inverse -------------------
__global__ void __launch_bounds__(256) k2_newton()
{
    extern __shared__ float sm2[];
    float* S  = sm2;
    float* Z  = S  + 4160;
    float* T1 = Z  + 4160;
    float* T2 = T1 + 4160;
    __shared__ float red[8];

    const int bh = blockIdx.x;
    const int b = bh >> 3, h = bh & 7;
    const int tid = threadIdx.x;

    for (int e = tid; e < 4096; e += 256) {
        int l = e >> 6, d = e & 63;
        size_t base = (size_t)(b * SEQ + l * LMSTRIDE) * QKV_N + h * HD + d;
        Z [l*65 + d] = __half2float(gYh[base]);
        T1[l*65 + d] = __half2float(gYh[base + CDIM]);
    }
    __syncthreads();

    mm64_nt(S, 65, Z, 65, T1, 65, SCALE, tid);
    __syncthreads();
    if (tid < 64) {
        float mx = -1e30f;
        for (int j = 0; j < 64; j++) mx = fmaxf(mx, S[tid*65 + j]);
        float s = 0.f;
        for (int j = 0; j < 64; j++) { float p = __expf(S[tid*65+j] - mx); S[tid*65+j] = p; s += p; }
        float inv = 1.f / s;
        for (int j = 0; j < 64; j++) S[tid*65 + j] *= inv;
    }
    __syncthreads();

    float part = 0.f;
    for (int e = tid; e < 4096; e += 256) {
        int i = e >> 6, j = e & 63;
        float v = S[i*65 + j];
        part += v * v;
    }
    #pragma unroll
    for (int o = 16; o; o >>= 1) part += __shfl_xor_sync(0xffffffffu, part, o);
    if ((tid & 31) == 0) red[tid >> 5] = part;
    __syncthreads();
    float fro2 = red[0]+red[1]+red[2]+red[3]+red[4]+red[5]+red[6]+red[7];
    fro2 = fmaxf(fro2, 1e-12f);
    float invf = 1.f / fro2;

    for (int e = tid; e < 4096; e += 256) {
        int i = e >> 6, j = e & 63;
        Z[j*65 + i] = S[i*65 + j] * invf;
    }
    __syncthreads();

    for (int it = 0; it < 6; it++) {
        mm64_nn(T1, 65, S, 65, Z, 65, tid);
        __syncthreads();
        mm64_nn(T2, 65, Z, 65, T1, 65, tid);
        __syncthreads();
        for (int e = tid; e < 4096; e += 256) {
            int i = e >> 6, j = e & 63;
            Z[i*65 + j] = 2.f * Z[i*65 + j] - T2[i*65 + j];
        }
        __syncthreads();
    }

    for (int e = tid; e < 4096; e += 256) {
        int i = e >> 6, j = e & 63;
        gW2inv[bh*4096 + i*64 + j] = Z[i*65 + j];
    }
}

// ---------------- kernel_3 flash (tensor-core): partials ---------------------
#define K3_SMEM (8192 + 2*16384)

__global__ void __launch_bounds__(128) k3_flash()
{
    extern __shared__ __align__(128) char sm3[];
    const uint32_t sQ  = smem_u32(sm3);
    const uint32_t sKV = sQ + 8192;

    const int bh = blockIdx.x;
    const int ch = blockIdx.y;
    const int b = bh >> 3, h = bh & 7;
    const int tid = threadIdx.x;
    const int lane = tid & 31;
    const int w = tid >> 5;
    const int g = lane >> 2, c = lane & 3;
    const int lrow = lane & 15, lhalf = lane >> 4;
    const int n0base = ch * KEYS_PER_CH;

    for (int i = tid; i < 512; i += 128) {
        int row = i >> 3, c4 = i & 7;
        CP_ASYNC16(sQ + row*128 + ((c4 ^ (row&7)) << 4),
                   gYh + ((size_t)(b*SEQ + row*LMSTRIDE))*QKV_N + h*HD + c4*8);
    }
    #pragma unroll
    for (int st = 0; st < 2; st++) {
        uint32_t base = sKV + st * 16384;
        for (int i = tid; i < 1024; i += 128) {
            int sel = i >> 9;
            int row = (i >> 3) & 63;
            int c4 = i & 7;
            CP_ASYNC16(base + sel*8192 + row*128 + ((c4 ^ (row&7)) << 4),
                       gYh + ((size_t)(b*SEQ + n0base + st*64 + row))*QKV_N
                           + (sel ? 2*CDIM : CDIM) + h*HD + c4*8);
        }
        CP_COMMIT();
    }

    float m0 = -1e30f, m1 = -1e30f, s0 = 0.f, s1 = 0.f;
    float oc[8][4];
    #pragma unroll
    for (int u = 0; u < 8; u++) { oc[u][0]=oc[u][1]=oc[u][2]=oc[u][3]=0.f; }

    for (int t = 0; t < 4; t++) {
        CP_WAIT1();
        __syncthreads();
        const uint32_t kb = sKV + (t & 1) * 16384;
        const uint32_t vb = kb + 8192;

        float sc[8][4];
        #pragma unroll
        for (int u = 0; u < 8; u++) { sc[u][0]=sc[u][1]=sc[u][2]=sc[u][3]=0.f; }
        #pragma unroll
        for (int ks = 0; ks < 4; ks++) {
            uint32_t af[4];
            const int qr = w*16 + lrow;
            ldsm_x4(af, sQ + qr*128 + (((ks*2+lhalf) ^ (qr&7)) << 4));
            #pragma unroll
            for (int nj = 0; nj < 4; nj++) {
                uint32_t bf[4];
                const int kr = nj*16 + lrow;
                ldsm_x4(bf, kb + kr*128 + (((ks*2+lhalf) ^ (kr&7)) << 4));
                uint32_t b2a[2] = { bf[0], bf[2] };
                mma_f16(sc[nj*2+0], af, b2a);
                uint32_t b2b[2] = { bf[1], bf[3] };
                mma_f16(sc[nj*2+1], af, b2b);
            }
        }
        float tm0 = -1e30f, tm1 = -1e30f;
        #pragma unroll
        for (int u = 0; u < 8; u++) {
            sc[u][0]*=SCALE; sc[u][1]*=SCALE; sc[u][2]*=SCALE; sc[u][3]*=SCALE;
            tm0 = fmaxf(tm0, fmaxf(sc[u][0], sc[u][1]));
            tm1 = fmaxf(tm1, fmaxf(sc[u][2], sc[u][3]));
        }
        tm0 = fmaxf(tm0, __shfl_xor_sync(0xffffffffu, tm0, 1));
        tm0 = fmaxf(tm0, __shfl_xor_sync(0xffffffffu, tm0, 2));
        tm1 = fmaxf(tm1, __shfl_xor_sync(0xffffffffu, tm1, 1));
        tm1 = fmaxf(tm1, __shfl_xor_sync(0xffffffffu, tm1, 2));
        const float mn0 = fmaxf(m0, tm0), mn1 = fmaxf(m1, tm1);
        const float cr0 = __expf(m0 - mn0), cr1 = __expf(m1 - mn1);
        float rs0 = 0.f, rs1 = 0.f;
        uint32_t pa[4][4];
        #pragma unroll
        for (int u = 0; u < 8; u++) {
            float p0 = __expf(sc[u][0]-mn0), p1 = __expf(sc[u][1]-mn0);
            float p2 = __expf(sc[u][2]-mn1), p3 = __expf(sc[u][3]-mn1);
            rs0 += p0 + p1; rs1 += p2 + p3;
            __half2 hA = __floats2half2_rn(p0, p1);
            __half2 hB = __floats2half2_rn(p2, p3);
            pa[u>>1][(u&1)*2+0] = *(uint32_t*)&hA;
            pa[u>>1][(u&1)*2+1] = *(uint32_t*)&hB;
        }
        rs0 += __shfl_xor_sync(0xffffffffu, rs0, 1);
        rs0 += __shfl_xor_sync(0xffffffffu, rs0, 2);
        rs1 += __shfl_xor_sync(0xffffffffu, rs1, 1);
        rs1 += __shfl_xor_sync(0xffffffffu, rs1, 2);
        s0 = s0*cr0 + rs0; s1 = s1*cr1 + rs1;
        m0 = mn0; m1 = mn1;
        #pragma unroll
        for (int u = 0; u < 8; u++) {
            oc[u][0]*=cr0; oc[u][1]*=cr0; oc[u][2]*=cr1; oc[u][3]*=cr1;
        }
        #pragma unroll
        for (int ks = 0; ks < 4; ks++) {
            #pragma unroll
            for (int nj = 0; nj < 4; nj++) {
                uint32_t bf[4];
                const int rk = ks*16 + (lane&7) + ((lane>>4)&1)*8;
                const int cn = nj*2 + ((lane>>3)&1);
                ldsm_x4_t(bf, vb + rk*128 + (((cn ^ (rk&7))) << 4));
                uint32_t b2a[2] = { bf[0], bf[2] };
                mma_f16(oc[nj*2+0], pa[ks], b2a);
                uint32_t b2b[2] = { bf[1], bf[3] };
                mma_f16(oc[nj*2+1], pa[ks], b2b);
            }
        }
        __syncthreads();
        if (t + 2 < 4) {
            uint32_t base = sKV + (t & 1) * 16384;
            int n0 = n0base + (t + 2) * 64;
            for (int i = tid; i < 1024; i += 128) {
                int sel = i >> 9;
                int row = (i >> 3) & 63;
                int c4 = i & 7;
                CP_ASYNC16(base + sel*8192 + row*128 + ((c4 ^ (row&7)) << 4),
                           gYh + ((size_t)(b*SEQ + n0 + row))*QKV_N
                               + (sel ? 2*CDIM : CDIM) + h*HD + c4*8);
            }
        }
        CP_COMMIT();
    }

    const size_t fbase = ((size_t)bh*NCH + ch)*4096;
    const int r0a = w*16 + g, r1a = r0a + 8;
    #pragma unroll
    for (int u = 0; u < 8; u++) {
        int col = u*8 + 2*c;
        *(float2*)&gFp[fbase + (size_t)r0a*64 + col] = make_float2(oc[u][0], oc[u][1]);
        *(float2*)&gFp[fbase + (size_t)r1a*64 + col] = make_float2(oc[u][2], oc[u][3]);
    }
    if (c == 0) {
        gMp[(bh*NCH+ch)*64 + r0a] = m0;
        gMp[(bh*NCH+ch)*64 + r1a] = m1;
        gSp[(bh*NCH+ch)*64 + r0a] = s0;
        gSp[(bh*NCH+ch)*64 + r1a] = s1;
    }
}

// ---------------- combine flash partials + T^T = (W2inv @ F)^T ---------------
__global__ void __launch_bounds__(256) k3_combine()
{
    __shared__ float wgt[NCH*64];
    __shared__ float sF[64*65];
    __shared__ float sW[64*64];
    const int bh = blockIdx.x;
    const int tid = threadIdx.x;

    if (tid < 64) {
        float M = -1e30f;
        for (int c = 0; c < NCH; c++) M = fmaxf(M, gMp[(bh*NCH + c)*64 + tid]);
        float denom = 0.f;
        for (int c = 0; c < NCH; c++)
            denom += __expf(gMp[(bh*NCH + c)*64 + tid] - M) * gSp[(bh*NCH + c)*64 + tid];
        float invd = 1.f / denom;
        for (int c = 0; c < NCH; c++)
            wgt[c*64 + tid] = __expf(gMp[(bh*NCH + c)*64 + tid] - M) * invd;
    }
    for (int e = tid; e < 4096; e += 256) sW[e] = gW2inv[bh*4096 + e];
    __syncthreads();

    for (int e = tid; e < 4096; e += 256) {
        int l = e >> 6, d = e & 63;
        float f = 0.f;
        for (int c = 0; c < NCH; c++)
            f += gFp[((size_t)bh * NCH + c) * 4096 + e] * wgt[c*64 + l];
        sF[l*65 + d] = f;
    }
    __syncthreads();

    const int i0 = (tid >> 4) * 4, j0 = (tid & 15) * 4;
    float cc[4][4] = {};
    #pragma unroll 8
    for (int k = 0; k < 64; k++) {
        float a[4], bv[4];
        #pragma unroll
        for (int ii = 0; ii < 4; ii++) a[ii] = sW[(i0+ii)*64 + k];
        #pragma unroll
        for (int jj = 0; jj < 4; jj++) bv[jj] = sF[k*65 + j0+jj];
        #pragma unroll
        for (int ii = 0; ii < 4; ii++)
            #pragma unroll
            for (int jj = 0; jj < 4; jj++)
                cc[ii][jj] += a[ii] * bv[jj];
    }
    #pragma unroll
    for (int ii = 0; ii < 4; ii++)
        #pragma unroll
        for (int jj = 0; jj < 4; jj++)
            gTth[bh*4096 + (j0+jj)*64 + (i0+ii)] = __float2half(cc[ii][jj]);
}

// ---------------- kernel_1 @ T (tensor-core) -> gATh -------------------------
#define K4_SMEM (3*8192)

__global__ void __launch_bounds__(128) k4_out()
{
    extern __shared__ __align__(128) char sm4[];
    const uint32_t sQ = smem_u32(sm4);
    const uint32_t sK = sQ + 8192;
    const uint32_t sT = sK + 8192;

    const int qt = blockIdx.x;
    const int bh = blockIdx.y;
    const int b = bh >> 3, h = bh & 7;
    const int n0 = qt * 64;
    const int tid = threadIdx.x;
    const int lane = tid & 31;
    const int w = tid >> 5;
    const int g = lane >> 2, c = lane & 3;
    const int lrow = lane & 15, lhalf = lane >> 4;

    for (int i = tid; i < 512; i += 128) {
        int row = i >> 3, c4 = i & 7;
        uint32_t swz = (uint32_t)((c4 ^ (row & 7)) << 4);
        CP_ASYNC16(sQ + row*128 + swz,
                   gYh + ((size_t)(b*SEQ + n0 + row))*QKV_N + h*HD + c4*8);
        CP_ASYNC16(sK + row*128 + swz,
                   gYh + ((size_t)(b*SEQ + row*LMSTRIDE))*QKV_N + CDIM + h*HD + c4*8);
        CP_ASYNC16(sT + row*128 + swz,
                   gTth + bh*4096 + row*64 + c4*8);
    }
    CP_COMMIT();
    CP_WAIT0();
    __syncthreads();

    float sc[8][4];
    #pragma unroll
    for (int u = 0; u < 8; u++) { sc[u][0]=sc[u][1]=sc[u][2]=sc[u][3]=0.f; }
    #pragma unroll
    for (int ks = 0; ks < 4; ks++) {
        uint32_t af[4];
        const int qr = w*16 + lrow;
        ldsm_x4(af, sQ + qr*128 + (((ks*2+lhalf) ^ (qr&7)) << 4));
        #pragma unroll
        for (int nj = 0; nj < 4; nj++) {
            uint32_t bf[4];
            const int kr = nj*16 + lrow;
            ldsm_x4(bf, sK + kr*128 + (((ks*2+lhalf) ^ (kr&7)) << 4));
            uint32_t b2a[2] = { bf[0], bf[2] };
            mma_f16(sc[nj*2+0], af, b2a);
            uint32_t b2b[2] = { bf[1], bf[3] };
            mma_f16(sc[nj*2+1], af, b2b);
        }
    }
    float tm0 = -1e30f, tm1 = -1e30f;
    #pragma unroll
    for (int u = 0; u < 8; u++) {
        sc[u][0]*=SCALE; sc[u][1]*=SCALE; sc[u][2]*=SCALE; sc[u][3]*=SCALE;
        tm0 = fmaxf(tm0, fmaxf(sc[u][0], sc[u][1]));
        tm1 = fmaxf(tm1, fmaxf(sc[u][2], sc[u][3]));
    }
    tm0 = fmaxf(tm0, __shfl_xor_sync(0xffffffffu, tm0, 1));
    tm0 = fmaxf(tm0, __shfl_xor_sync(0xffffffffu, tm0, 2));
    tm1 = fmaxf(tm1, __shfl_xor_sync(0xffffffffu, tm1, 1));
    tm1 = fmaxf(tm1, __shfl_xor_sync(0xffffffffu, tm1, 2));
    float rs0 = 0.f, rs1 = 0.f;
    uint32_t pa[4][4];
    #pragma unroll
    for (int u = 0; u < 8; u++) {
        float p0 = __expf(sc[u][0]-tm0), p1 = __expf(sc[u][1]-tm0);
        float p2 = __expf(sc[u][2]-tm1), p3 = __expf(sc[u][3]-tm1);
        rs0 += p0 + p1; rs1 += p2 + p3;
        __half2 hA = __floats2half2_rn(p0, p1);
        __half2 hB = __floats2half2_rn(p2, p3);
        pa[u>>1][(u&1)*2+0] = *(uint32_t*)&hA;
        pa[u>>1][(u&1)*2+1] = *(uint32_t*)&hB;
    }
    rs0 += __shfl_xor_sync(0xffffffffu, rs0, 1);
    rs0 += __shfl_xor_sync(0xffffffffu, rs0, 2);
    rs1 += __shfl_xor_sync(0xffffffffu, rs1, 1);
    rs1 += __shfl_xor_sync(0xffffffffu, rs1, 2);
    const float inv0 = 1.f / rs0, inv1 = 1.f / rs1;

    float oc[8][4];
    #pragma unroll
    for (int u = 0; u < 8; u++) { oc[u][0]=oc[u][1]=oc[u][2]=oc[u][3]=0.f; }
    #pragma unroll
    for (int ks = 0; ks < 4; ks++) {
        #pragma unroll
        for (int nj = 0; nj < 4; nj++) {
            uint32_t bf[4];
            const int tr = nj*16 + lrow;
            ldsm_x4(bf, sT + tr*128 + (((ks*2+lhalf) ^ (tr&7)) << 4));
            uint32_t b2a[2] = { bf[0], bf[2] };
            mma_f16(oc[nj*2+0], pa[ks], b2a);
            uint32_t b2b[2] = { bf[1], bf[3] };
            mma_f16(oc[nj*2+1], pa[ks], b2b);
        }
    }

    const int r0a = w*16 + g;
    #pragma unroll
    for (int u = 0; u < 8; u++) {
        int col = u*8 + 2*c;
        __half2 hA = __floats2half2_rn(oc[u][0]*inv0, oc[u][1]*inv0);
        __half2 hB = __floats2half2_rn(oc[u][2]*inv1, oc[u][3]*inv1);
        *(uint32_t*)&gATh[((size_t)(b*SEQ + n0 + r0a))*CDIM + h*HD + col]     = *(uint32_t*)&hA;
        *(uint32_t*)&gATh[((size_t)(b*SEQ + n0 + r0a + 8))*CDIM + h*HD + col] = *(uint32_t*)&hB;
    }
}

// ---------------- launcher ---------------------------------------------------
extern "C" void kernel_launch(void* const* d_in, const int* in_sizes, int n_in,
                              void* d_out, int out_size)
{
    const float* x     = (const float*)d_in[0];
    const float* Wqkv  = (const float*)d_in[1];
    const float* bqkv  = (const float*)d_in[2];
    const float* Wproj = (const float*)d_in[3];
    const float* bproj = (const float*)d_in[4];
    float* out = (float*)d_out;

    const int SMEM_K2 = 4 * 4160 * 4;
    cudaFuncSetAttribute(gemm_h,    cudaFuncAttributeMaxDynamicSharedMemorySize, SMEM_G3);
    cudaFuncSetAttribute(k2_newton, cudaFuncAttributeMaxDynamicSharedMemorySize, SMEM_K2);
    cudaFuncSetAttribute(k3_flash,  cudaFuncAttributeMaxDynamicSharedMemorySize, K3_SMEM);
    cudaFuncSetAttribute(k4_out,    cudaFuncAttributeMaxDynamicSharedMemorySize, K4_SMEM);

    __half *pXh, *pWqkvh, *pWph, *pYh, *pATh;
    cudaGetSymbolAddress((void**)&pXh,    gXh);
    cudaGetSymbolAddress((void**)&pWqkvh, gWqkvh);
    cudaGetSymbolAddress((void**)&pWph,   gWph);
    cudaGetSymbolAddress((void**)&pYh,    gYh);
    cudaGetSymbolAddress((void**)&pATh,   gATh);

    // 0. fp32 -> fp16 conversions
    {
        int nx = BN_TOK * CDIM;
        cvtf2h<<<(nx/8 + 255)/256, 256>>>(x, pXh, nx);
        int nw = QKV_N * CDIM;
        cvtf2h<<<(nw/8 + 255)/256, 256>>>(Wqkv, pWqkvh, nw);
        int np = CDIM * CDIM;
        cvtf2h<<<(np/8 + 255)/256, 256>>>(Wproj, pWph, np);
    }

    // 1. QKV projection -> fp16 gYh (128x128 block, 4 warps of 64x64)
    gemm_h<<<dim3(QKV_N/128, BN_TOK/128), 128, SMEM_G3>>>(pXh, pWqkvh, bqkv, pYh, BN_TOK, QKV_N, CDIM, 1);
    // 2. kernel_2 softmax + Newton inverse
    k2_newton<<<NBH, 256, SMEM_K2>>>();
    // 3. flash partials (tensor cores), combine + T^T fp16
    k3_flash<<<dim3(NBH, NCH), 128, K3_SMEM>>>();
    k3_combine<<<NBH, 256>>>();
    // 4. out = softmax(q k_lm^T) @ T (tensor cores) -> gATh fp16
    k4_out<<<dim3(SEQ/64, NBH), 128, K4_SMEM>>>();
    // 5. projection: out = gATh @ Wproj^T + bproj (fp32 out)
    gemm_h<<<dim3(CDIM/128, BN_TOK/128), 128, SMEM_G3>>>(pATh, pWph, bproj, out, BN_TOK, CDIM, CDIM, 0);
}

// round 9
// speedup vs baseline: 1.1390x; 1.0382x over previous
#include <cuda_runtime.h>
#include <cuda_fp16.h>
#include <cstdint>

// ---------------- problem constants ----------------
#define BDIM     4
#define SEQ      8192
#define CDIM     512
#define NH       8
#define HD       64
#define NLM      64
#define LMSTRIDE 128           // SEQ / NLM
#define BN_TOK   (BDIM*SEQ)    // 32768
#define QKV_N    (3*CDIM)      // 1536
#define NBH      (BDIM*NH)     // 32
#define NCH      16            // key chunks for kernel_3 flash
#define KEYS_PER_CH (SEQ/NCH)  // 512
#define TILES_PER_CH (KEYS_PER_CH/64) // 8
#define SCALE    0.125f        // hd^-0.5

// ---------------- device scratch (no runtime allocs allowed) ----------------
__device__ __half gXh[(size_t)BN_TOK * CDIM];    // x in fp16
__device__ __half gWqkvh[QKV_N * CDIM];          // Wqkv in fp16
__device__ __half gWph[CDIM * CDIM];             // Wproj in fp16
__device__ __half gYh[(size_t)BN_TOK * QKV_N];   // qkv activations fp16
__device__ __half gATh[(size_t)BN_TOK * CDIM];   // attention output fp16
__device__ float  gW2inv[NBH*64*64];
__device__ __half gTth[NBH*64*64];               // (W2inv @ F)^T fp16, [bh][hd][lm]
__device__ float  gFp[(size_t)NBH*NCH*64*64];    // flash partial accumulators
__device__ float  gMp[NBH*NCH*64];
__device__ float  gSp[NBH*NCH*64];

// ---------------- ptx helpers ------------------------------------------------
__device__ __forceinline__ uint32_t smem_u32(const void* p) {
    uint32_t a;
    asm("{ .reg .u64 t; cvta.to.shared.u64 t, %1; cvt.u32.u64 %0, t; }" : "=r"(a) : "l"(p));
    return a;
}
__device__ __forceinline__ void mma_f16(float* d, const uint32_t* a, const uint32_t* b) {
    asm volatile(
        "mma.sync.aligned.m16n8k16.row.col.f32.f16.f16.f32 "
        "{%0,%1,%2,%3}, {%4,%5,%6,%7}, {%8,%9}, {%0,%1,%2,%3};"
        : "+f"(d[0]), "+f"(d[1]), "+f"(d[2]), "+f"(d[3])
        : "r"(a[0]), "r"(a[1]), "r"(a[2]), "r"(a[3]),
          "r"(b[0]), "r"(b[1]));
}
__device__ __forceinline__ void ldsm_x4(uint32_t* r, uint32_t addr) {
    asm volatile("ldmatrix.sync.aligned.m8n8.x4.shared.b16 {%0,%1,%2,%3}, [%4];"
                 : "=r"(r[0]), "=r"(r[1]), "=r"(r[2]), "=r"(r[3]) : "r"(addr));
}
__device__ __forceinline__ void ldsm_x4_t(uint32_t* r, uint32_t addr) {
    asm volatile("ldmatrix.sync.aligned.m8n8.x4.trans.shared.b16 {%0,%1,%2,%3}, [%4];"
                 : "=r"(r[0]), "=r"(r[1]), "=r"(r[2]), "=r"(r[3]) : "r"(addr));
}
#define CP_ASYNC16(dst, src) \
    asm volatile("cp.async.cg.shared.global [%0], [%1], 16;" :: "r"(dst), "l"(src) : "memory")
#define CP_COMMIT() asm volatile("cp.async.commit_group;" ::: "memory")
#define CP_WAIT1()  asm volatile("cp.async.wait_group 1;" ::: "memory")
#define CP_WAIT0()  asm volatile("cp.async.wait_group 0;" ::: "memory")

// ---------------- fp32 -> fp16 conversion ------------------------------------
__global__ void __launch_bounds__(256) cvtf2h(const float* __restrict__ s,
                                              __half* __restrict__ d, int n)
{
    int i = (blockIdx.x * blockDim.x + threadIdx.x) * 8;
    if (i < n) {
        float4 a = *(const float4*)(s + i);
        float4 b = *(const float4*)(s + i + 4);
        __half2 h0 = __floats2half2_rn(a.x, a.y);
        __half2 h1 = __floats2half2_rn(a.z, a.w);
        __half2 h2 = __floats2half2_rn(b.x, b.y);
        __half2 h3 = __floats2half2_rn(b.z, b.w);
        uint4 o;
        o.x = *(uint32_t*)&h0; o.y = *(uint32_t*)&h1;
        o.z = *(uint32_t*)&h2; o.w = *(uint32_t*)&h3;
        *(uint4*)(d + i) = o;
    }
}

// ---------------- fp16 tensor-core GEMM: C = A[M,K]h @ B[N,K]h^T + bias -----
// round-6 config (best measured): block 128x128, 8 warps (warp 64x32),
// K chunk 64, 3-stage cp.async ring, ldmatrix.x4 fragment loads.
#define STG_BYTES 32768          // 16KB A + 16KB B per stage
#define SMEM_GEMMH (3 * STG_BYTES)

__device__ __forceinline__ void stage_copy(uint32_t sbase, const __half* A,
                                           const __half* B, int bm, int bn,
                                           int K, int k0, int tid)
{
    #pragma unroll
    for (int i = 0; i < 4; i++) {
        int lin = tid + i * 256;
        int row = lin >> 3;
        int c   = lin & 7;
        uint32_t dA = sbase + row * 128 + ((c ^ (row & 7)) << 4);
        CP_ASYNC16(dA, A + (size_t)(bm + row) * K + k0 + c * 8);
        uint32_t dB = sbase + 16384 + row * 128 + ((c ^ (row & 7)) << 4);
        CP_ASYNC16(dB, B + (size_t)(bn + row) * K + k0 + c * 8);
    }
}

__global__ void __launch_bounds__(256) gemm_h(const __half* __restrict__ A,
                                              const __half* __restrict__ B,
                                              const float* __restrict__ bias,
                                              void* __restrict__ Cv,
                                              int M, int N, int K, int half_out)
{
    extern __shared__ __align__(128) char smg[];
    const uint32_t sb = smem_u32(smg);

    const int bm = blockIdx.y * 128;
    const int bn = blockIdx.x * 128;
    const int tid  = threadIdx.x;
    const int lane = tid & 31;
    const int warp = tid >> 5;
    const int wm = (warp & 1) * 64;
    const int wn = (warp >> 1) * 32;
    const int g = lane >> 2;
    const int c = lane & 3;
    const int lrow = lane & 15;
    const int lhalf = lane >> 4;

    float acc[4][4][4];
    #pragma unroll
    for (int mi = 0; mi < 4; mi++)
        #pragma unroll
        for (int t = 0; t < 4; t++)
            #pragma unroll
            for (int r = 0; r < 4; r++) acc[mi][t][r] = 0.f;

    const int KT = K >> 6;

    stage_copy(sb, A, B, bm, bn, K, 0, tid);
    CP_COMMIT();
    stage_copy(sb + STG_BYTES, A, B, bm, bn, K, 64, tid);
    CP_COMMIT();

    for (int kt = 0; kt < KT; kt++) {
        CP_WAIT1();
        __syncthreads();

        if (kt + 2 < KT)
            stage_copy(sb + ((kt + 2) % 3) * STG_BYTES, A, B, bm, bn, K, (kt + 2) * 64, tid);
        CP_COMMIT();

        const uint32_t aBase = sb + (kt % 3) * STG_BYTES;
        const uint32_t bBase = aBase + 16384;

        #pragma unroll
        for (int ks = 0; ks < 4; ks++) {
            uint32_t af[4][4], bf[2][4];
            #pragma unroll
            for (int mi = 0; mi < 4; mi++) {
                const int row = wm + mi * 16 + lrow;
                const int ch  = (ks * 2 + lhalf) ^ (row & 7);
                ldsm_x4(af[mi], aBase + row * 128 + (ch << 4));
            }
            #pragma unroll
            for (int nj = 0; nj < 2; nj++) {
                const int row = wn + nj * 16 + lrow;
                const int ch  = (ks * 2 + lhalf) ^ (row & 7);
                ldsm_x4(bf[nj], bBase + row * 128 + (ch << 4));
            }
            #pragma unroll
            for (int mi = 0; mi < 4; mi++) {
                #pragma unroll
                for (int t = 0; t < 4; t++) {
                    const int nj = t >> 1, sub = t & 1;
                    uint32_t b2[2] = { bf[nj][sub], bf[nj][sub + 2] };
                    mma_f16(acc[mi][t], af[mi], b2);
                }
            }
        }
    }

    if (half_out) {
        __half* C = (__half*)Cv;
        #pragma unroll
        for (int mi = 0; mi < 4; mi++) {
            const int row = bm + wm + mi * 16 + g;
            #pragma unroll
            for (int t = 0; t < 4; t++) {
                const int col = bn + wn + (t >> 1) * 16 + (t & 1) * 8 + 2 * c;
                const float b0 = bias[col], b1 = bias[col + 1];
                __half2 o0 = __floats2half2_rn(acc[mi][t][0] + b0, acc[mi][t][1] + b1);
                __half2 o1 = __floats2half2_rn(acc[mi][t][2] + b0, acc[mi][t][3] + b1);
                *(uint32_t*)(C + (size_t)row * N + col)       = *(uint32_t*)&o0;
                *(uint32_t*)(C + (size_t)(row + 8) * N + col) = *(uint32_t*)&o1;
            }
        }
    } else {
        float* C = (float*)Cv;
        #pragma unroll
        for (int mi = 0; mi < 4; mi++) {
            const int row = bm + wm + mi * 16 + g;
            #pragma unroll
            for (int t = 0; t < 4; t++) {
                const int col = bn + wn + (t >> 1) * 16 + (t & 1) * 8 + 2 * c;
                const float b0 = bias[col], b1 = bias[col + 1];
                float2 o0 = make_float2(acc[mi][t][0] + b0, acc[mi][t][1] + b1);
                float2 o1 = make_float2(acc[mi][t][2] + b0, acc[mi][t][3] + b1);
                *(float2*)(C + (size_t)row * N + col)       = o0;
                *(float2*)(C + (size_t)(row + 8) * N + col) = o1;
            }
        }
    }
}

// ---------------- small 64x64 fp32 helpers (k2 only) -------------------------
__device__ __forceinline__ void mm64_nt(float* C, int ldc,
                                        const float* A, int lda,
                                        const float* B, int ldb,
                                        float scale, int tid)
{
    const int i0 = (tid >> 4) * 4, j0 = (tid & 15) * 4;
    float c[4][4] = {};
    #pragma unroll 8
    for (int d = 0; d < 64; d++) {
        float a[4], bv[4];
        #pragma unroll
        for (int ii = 0; ii < 4; ii++) a[ii]  = A[(i0+ii)*lda + d];
        #pragma unroll
        for (int jj = 0; jj < 4; jj++) bv[jj] = B[(j0+jj)*ldb + d];
        #pragma unroll
        for (int ii = 0; ii < 4; ii++)
            #pragma unroll
            for (int jj = 0; jj < 4; jj++)
                c[ii][jj] += a[ii] * bv[jj];
    }
    #pragma unroll
    for (int ii = 0; ii < 4; ii++)
        #pragma unroll
        for (int jj = 0; jj < 4; jj++)
            C[(i0+ii)*ldc + j0+jj] = scale * c[ii][jj];
}

__device__ __forceinline__ void mm64_nn(float* C, int ldc,
                                        const float* A, int lda,
                                        const float* B, int ldb, int tid)
{
    const int i0 = (tid >> 4) * 4, j0 = (tid & 15) * 4;
    float c[4][4] = {};
    #pragma unroll 8
    for (int k = 0; k < 64; k++) {
        float a[4], bv[4];
        #pragma unroll
        for (int ii = 0; ii < 4; ii++) a[ii]  = A[(i0+ii)*lda + k];
        #pragma unroll
        for (int jj = 0; jj < 4; jj++) bv[jj] = B[k*ldb + j0+jj];
        #pragma unroll
        for (int ii = 0; ii < 4; ii++)
            #pragma unroll
            for (int jj = 0; jj < 4; jj++)
                c[ii][jj] += a[ii] * bv[jj];
    }
    #pragma unroll
    for (int ii = 0; ii < 4; ii++)
        #pragma unroll
        for (int jj = 0; jj < 4; jj++)
            C[(i0+ii)*ldc + j0+jj] = c[ii][jj];
}

// ---------------- kernel_2 softmax + Newton pseudo-inverse -------------------
__global__ void __launch_bounds__(256) k2_newton()
{
    extern __shared__ float sm2[];
    float* S  = sm2;
    float* Z  = S  + 4160;
    float* T1 = Z  + 4160;
    float* T2 = T1 + 4160;
    __shared__ float red[8];

    const int bh = blockIdx.x;
    const int b = bh >> 3, h = bh & 7;
    const int tid = threadIdx.x;

    for (int e = tid; e < 4096; e += 256) {
        int l = e >> 6, d = e & 63;
        size_t base = (size_t)(b * SEQ + l * LMSTRIDE) * QKV_N + h * HD + d;
        Z [l*65 + d] = __half2float(gYh[base]);
        T1[l*65 + d] = __half2float(gYh[base + CDIM]);
    }
    __syncthreads();

    mm64_nt(S, 65, Z, 65, T1, 65, SCALE, tid);
    __syncthreads();
    if (tid < 64) {
        float mx = -1e30f;
        for (int j = 0; j < 64; j++) mx = fmaxf(mx, S[tid*65 + j]);
        float s = 0.f;
        for (int j = 0; j < 64; j++) { float p = __expf(S[tid*65+j] - mx); S[tid*65+j] = p; s += p; }
        float inv = 1.f / s;
        for (int j = 0; j < 64; j++) S[tid*65 + j] *= inv;
    }
    __syncthreads();

    float part = 0.f;
    for (int e = tid; e < 4096; e += 256) {
        int i = e >> 6, j = e & 63;
        float v = S[i*65 + j];
        part += v * v;
    }
    #pragma unroll
    for (int o = 16; o; o >>= 1) part += __shfl_xor_sync(0xffffffffu, part, o);
    if ((tid & 31) == 0) red[tid >> 5] = part;
    __syncthreads();
    float fro2 = red[0]+red[1]+red[2]+red[3]+red[4]+red[5]+red[6]+red[7];
    fro2 = fmaxf(fro2, 1e-12f);
    float invf = 1.f / fro2;

    for (int e = tid; e < 4096; e += 256) {
        int i = e >> 6, j = e & 63;
        Z[j*65 + i] = S[i*65 + j] * invf;
    }
    __syncthreads();

    for (int it = 0; it < 6; it++) {
        mm64_nn(T1, 65, S, 65, Z, 65, tid);
        __syncthreads();
        mm64_nn(T2, 65, Z, 65, T1, 65, tid);
        __syncthreads();
        for (int e = tid; e < 4096; e += 256) {
            int i = e >> 6, j = e & 63;
            Z[i*65 + j] = 2.f * Z[i*65 + j] - T2[i*65 + j];
        }
        __syncthreads();
    }

    for (int e = tid; e < 4096; e += 256) {
        int i = e >> 6, j = e & 63;
        gW2inv[bh*4096 + i*64 + j] = Z[i*65 + j];
    }
}

// ---------------- kernel_3 flash (tensor-core): partials ---------------------
// grid (NBH, NCH), 128 threads, TILES_PER_CH 64-key tiles per block
#define K3_SMEM (8192 + 2*16384)

__global__ void __launch_bounds__(128) k3_flash()
{
    extern __shared__ __align__(128) char sm3[];
    const uint32_t sQ  = smem_u32(sm3);
    const uint32_t sKV = sQ + 8192;

    const int bh = blockIdx.x;
    const int ch = blockIdx.y;
    const int b = bh >> 3, h = bh & 7;
    const int tid = threadIdx.x;
    const int lane = tid & 31;
    const int w = tid >> 5;
    const int g = lane >> 2, c = lane & 3;
    const int lrow = lane & 15, lhalf = lane >> 4;
    const int n0base = ch * KEYS_PER_CH;

    for (int i = tid; i < 512; i += 128) {
        int row = i >> 3, c4 = i & 7;
        CP_ASYNC16(sQ + row*128 + ((c4 ^ (row&7)) << 4),
                   gYh + ((size_t)(b*SEQ + row*LMSTRIDE))*QKV_N + h*HD + c4*8);
    }
    #pragma unroll
    for (int st = 0; st < 2; st++) {
        uint32_t base = sKV + st * 16384;
        for (int i = tid; i < 1024; i += 128) {
            int sel = i >> 9;
            int row = (i >> 3) & 63;
            int c4 = i & 7;
            CP_ASYNC16(base + sel*8192 + row*128 + ((c4 ^ (row&7)) << 4),
                       gYh + ((size_t)(b*SEQ + n0base + st*64 + row))*QKV_N
                           + (sel ? 2*CDIM : CDIM) + h*HD + c4*8);
        }
        CP_COMMIT();
    }

    float m0 = -1e30f, m1 = -1e30f, s0 = 0.f, s1 = 0.f;
    float oc[8][4];
    #pragma unroll
    for (int u = 0; u < 8; u++) { oc[u][0]=oc[u][1]=oc[u][2]=oc[u][3]=0.f; }

    for (int t = 0; t < TILES_PER_CH; t++) {
        CP_WAIT1();
        __syncthreads();
        const uint32_t kb = sKV + (t & 1) * 16384;
        const uint32_t vb = kb + 8192;

        float sc[8][4];
        #pragma unroll
        for (int u = 0; u < 8; u++) { sc[u][0]=sc[u][1]=sc[u][2]=sc[u][3]=0.f; }
        #pragma unroll
        for (int ks = 0; ks < 4; ks++) {
            uint32_t af[4];
            const int qr = w*16 + lrow;
            ldsm_x4(af, sQ + qr*128 + (((ks*2+lhalf) ^ (qr&7)) << 4));
            #pragma unroll
            for (int nj = 0; nj < 4; nj++) {
                uint32_t bf[4];
                const int kr = nj*16 + lrow;
                ldsm_x4(bf, kb + kr*128 + (((ks*2+lhalf) ^ (kr&7)) << 4));
                uint32_t b2a[2] = { bf[0], bf[2] };
                mma_f16(sc[nj*2+0], af, b2a);
                uint32_t b2b[2] = { bf[1], bf[3] };
                mma_f16(sc[nj*2+1], af, b2b);
            }
        }
        float tm0 = -1e30f, tm1 = -1e30f;
        #pragma unroll
        for (int u = 0; u < 8; u++) {
            sc[u][0]*=SCALE; sc[u][1]*=SCALE; sc[u][2]*=SCALE; sc[u][3]*=SCALE;
            tm0 = fmaxf(tm0, fmaxf(sc[u][0], sc[u][1]));
            tm1 = fmaxf(tm1, fmaxf(sc[u][2], sc[u][3]));
        }
        tm0 = fmaxf(tm0, __shfl_xor_sync(0xffffffffu, tm0, 1));
        tm0 = fmaxf(tm0, __shfl_xor_sync(0xffffffffu, tm0, 2));
        tm1 = fmaxf(tm1, __shfl_xor_sync(0xffffffffu, tm1, 1));
        tm1 = fmaxf(tm1, __shfl_xor_sync(0xffffffffu, tm1, 2));
        const float mn0 = fmaxf(m0, tm0), mn1 = fmaxf(m1, tm1);
        const float cr0 = __expf(m0 - mn0), cr1 = __expf(m1 - mn1);
        float rs0 = 0.f, rs1 = 0.f;
        uint32_t pa[4][4];
        #pragma unroll
        for (int u = 0; u < 8; u++) {
            float p0 = __expf(sc[u][0]-mn0), p1 = __expf(sc[u][1]-mn0);
            float p2 = __expf(sc[u][2]-mn1), p3 = __expf(sc[u][3]-mn1);
            rs0 += p0 + p1; rs1 += p2 + p3;
            __half2 hA = __floats2half2_rn(p0, p1);
            __half2 hB = __floats2half2_rn(p2, p3);
            pa[u>>1][(u&1)*2+0] = *(uint32_t*)&hA;
            pa[u>>1][(u&1)*2+1] = *(uint32_t*)&hB;
        }
        rs0 += __shfl_xor_sync(0xffffffffu, rs0, 1);
        rs0 += __shfl_xor_sync(0xffffffffu, rs0, 2);
        rs1 += __shfl_xor_sync(0xffffffffu, rs1, 1);
        rs1 += __shfl_xor_sync(0xffffffffu, rs1, 2);
        s0 = s0*cr0 + rs0; s1 = s1*cr1 + rs1;
        m0 = mn0; m1 = mn1;
        #pragma unroll
        for (int u = 0; u < 8; u++) {
            oc[u][0]*=cr0; oc[u][1]*=cr0; oc[u][2]*=cr1; oc[u][3]*=cr1;
        }
        #pragma unroll
        for (int ks = 0; ks < 4; ks++) {
            #pragma unroll
            for (int nj = 0; nj < 4; nj++) {
                uint32_t bf[4];
                const int rk = ks*16 + (lane&7) + ((lane>>4)&1)*8;
                const int cn = nj*2 + ((lane>>3)&1);
                ldsm_x4_t(bf, vb + rk*128 + (((cn ^ (rk&7))) << 4));
                uint32_t b2a[2] = { bf[0], bf[2] };
                mma_f16(oc[nj*2+0], pa[ks], b2a);
                uint32_t b2b[2] = { bf[1], bf[3] };
                mma_f16(oc[nj*2+1], pa[ks], b2b);
            }
        }
        __syncthreads();
        if (t + 2 < TILES_PER_CH) {
            uint32_t base = sKV + (t & 1) * 16384;
            int n0 = n0base + (t + 2) * 64;
            for (int i = tid; i < 1024; i += 128) {
                int sel = i >> 9;
                int row = (i >> 3) & 63;
                int c4 = i & 7;
                CP_ASYNC16(base + sel*8192 + row*128 + ((c4 ^ (row&7)) << 4),
                           gYh + ((size_t)(b*SEQ + n0 + row))*QKV_N
                               + (sel ? 2*CDIM : CDIM) + h*HD + c4*8);
            }
        }
        CP_COMMIT();
    }

    const size_t fbase = ((size_t)bh*NCH + ch)*4096;
    const int r0a = w*16 + g, r1a = r0a + 8;
    #pragma unroll
    for (int u = 0; u < 8; u++) {
        int col = u*8 + 2*c;
        *(float2*)&gFp[fbase + (size_t)r0a*64 + col] = make_float2(oc[u][0], oc[u][1]);
        *(float2*)&gFp[fbase + (size_t)r1a*64 + col] = make_float2(oc[u][2], oc[u][3]);
    }
    if (c == 0) {
        gMp[(bh*NCH+ch)*64 + r0a] = m0;
        gMp[(bh*NCH+ch)*64 + r1a] = m1;
        gSp[(bh*NCH+ch)*64 + r0a] = s0;
        gSp[(bh*NCH+ch)*64 + r1a] = s1;
    }
}

// ---------------- combine flash partials + T^T = (W2inv @ F)^T ---------------
// column-split: grid (NBH, 4), each block owns 16 d-columns of F and T.
__global__ void __launch_bounds__(256) k3_combine()
{
    __shared__ float wgt[NCH*64];
    __shared__ float sF[64*17];      // 64 rows x 16 cols (+1 pad)
    __shared__ float sW[64*64];
    const int bh = blockIdx.x;
    const int d0 = blockIdx.y * 16;
    const int tid = threadIdx.x;

    if (tid < 64) {
        float M = -1e30f;
        for (int c = 0; c < NCH; c++) M = fmaxf(M, gMp[(bh*NCH + c)*64 + tid]);
        float denom = 0.f;
        for (int c = 0; c < NCH; c++)
            denom += __expf(gMp[(bh*NCH + c)*64 + tid] - M) * gSp[(bh*NCH + c)*64 + tid];
        float invd = 1.f / denom;
        for (int c = 0; c < NCH; c++)
            wgt[c*64 + tid] = __expf(gMp[(bh*NCH + c)*64 + tid] - M) * invd;
    }
    for (int e = tid; e < 4096; e += 256) sW[e] = gW2inv[bh*4096 + e];
    __syncthreads();

    // F slice: 64 rows x 16 cols, weighted sum over NCH chunks
    for (int e = tid; e < 1024; e += 256) {
        int l = e >> 4, dd = e & 15;
        float f = 0.f;
        #pragma unroll 4
        for (int c = 0; c < NCH; c++)
            f += gFp[((size_t)bh * NCH + c) * 4096 + l*64 + d0 + dd] * wgt[c*64 + l];
        sF[l*17 + dd] = f;
    }
    __syncthreads();

    // T slice = W2inv @ F_slice; thread -> 4 rows x 1 col
    const int i0 = (tid >> 4) * 4, j = tid & 15;
    float cc[4] = {0.f, 0.f, 0.f, 0.f};
    #pragma unroll 8
    for (int k = 0; k < 64; k++) {
        float bv = sF[k*17 + j];
        cc[0] += sW[(i0+0)*64 + k] * bv;
        cc[1] += sW[(i0+1)*64 + k] * bv;
        cc[2] += sW[(i0+2)*64 + k] * bv;
        cc[3] += sW[(i0+3)*64 + k] * bv;
    }
    #pragma unroll
    for (int ii = 0; ii < 4; ii++)
        gTth[bh*4096 + (d0 + j)*64 + (i0 + ii)] = __float2half(cc[ii]);
}

// ---------------- kernel_1 @ T (tensor-core) -> gATh -------------------------
#define K4_SMEM (3*8192)

__global__ void __launch_bounds__(128) k4_out()
{
    extern __shared__ __align__(128) char sm4[];
    const uint32_t sQ = smem_u32(sm4);
    const uint32_t sK = sQ + 8192;
    const uint32_t sT = sK + 8192;

    const int qt = blockIdx.x;
    const int bh = blockIdx.y;
    const int b = bh >> 3, h = bh & 7;
    const int n0 = qt * 64;
    const int tid = threadIdx.x;
    const int lane = tid & 31;
    const int w = tid >> 5;
    const int g = lane >> 2, c = lane & 3;
    const int lrow = lane & 15, lhalf = lane >> 4;

    for (int i = tid; i < 512; i += 128) {
        int row = i >> 3, c4 = i & 7;
        uint32_t swz = (uint32_t)((c4 ^ (row & 7)) << 4);
        CP_ASYNC16(sQ + row*128 + swz,
                   gYh + ((size_t)(b*SEQ + n0 + row))*QKV_N + h*HD + c4*8);
        CP_ASYNC16(sK + row*128 + swz,
                   gYh + ((size_t)(b*SEQ + row*LMSTRIDE))*QKV_N + CDIM + h*HD + c4*8);
        CP_ASYNC16(sT + row*128 + swz,
                   gTth + bh*4096 + row*64 + c4*8);
    }
    CP_COMMIT();
    CP_WAIT0();
    __syncthreads();

    float sc[8][4];
    #pragma unroll
    for (int u = 0; u < 8; u++) { sc[u][0]=sc[u][1]=sc[u][2]=sc[u][3]=0.f; }
    #pragma unroll
    for (int ks = 0; ks < 4; ks++) {
        uint32_t af[4];
        const int qr = w*16 + lrow;
        ldsm_x4(af, sQ + qr*128 + (((ks*2+lhalf) ^ (qr&7)) << 4));
        #pragma unroll
        for (int nj = 0; nj < 4; nj++) {
            uint32_t bf[4];
            const int kr = nj*16 + lrow;
            ldsm_x4(bf, sK + kr*128 + (((ks*2+lhalf) ^ (kr&7)) << 4));
            uint32_t b2a[2] = { bf[0], bf[2] };
            mma_f16(sc[nj*2+0], af, b2a);
            uint32_t b2b[2] = { bf[1], bf[3] };
            mma_f16(sc[nj*2+1], af, b2b);
        }
    }
    float tm0 = -1e30f, tm1 = -1e30f;
    #pragma unroll
    for (int u = 0; u < 8; u++) {
        sc[u][0]*=SCALE; sc[u][1]*=SCALE; sc[u][2]*=SCALE; sc[u][3]*=SCALE;
        tm0 = fmaxf(tm0, fmaxf(sc[u][0], sc[u][1]));
        tm1 = fmaxf(tm1, fmaxf(sc[u][2], sc[u][3]));
    }
    tm0 = fmaxf(tm0, __shfl_xor_sync(0xffffffffu, tm0, 1));
    tm0 = fmaxf(tm0, __shfl_xor_sync(0xffffffffu, tm0, 2));
    tm1 = fmaxf(tm1, __shfl_xor_sync(0xffffffffu, tm1, 1));
    tm1 = fmaxf(tm1, __shfl_xor_sync(0xffffffffu, tm1, 2));
    float rs0 = 0.f, rs1 = 0.f;
    uint32_t pa[4][4];
    #pragma unroll
    for (int u = 0; u < 8; u++) {
        float p0 = __expf(sc[u][0]-tm0), p1 = __expf(sc[u][1]-tm0);
        float p2 = __expf(sc[u][2]-tm1), p3 = __expf(sc[u][3]-tm1);
        rs0 += p0 + p1; rs1 += p2 + p3;
        __half2 hA = __floats2half2_rn(p0, p1);
        __half2 hB = __floats2half2_rn(p2, p3);
        pa[u>>1][(u&1)*2+0] = *(uint32_t*)&hA;
        pa[u>>1][(u&1)*2+1] = *(uint32_t*)&hB;
    }
    rs0 += __shfl_xor_sync(0xffffffffu, rs0, 1);
    rs0 += __shfl_xor_sync(0xffffffffu, rs0, 2);
    rs1 += __shfl_xor_sync(0xffffffffu, rs1, 1);
    rs1 += __shfl_xor_sync(0xffffffffu, rs1, 2);
    const float inv0 = 1.f / rs0, inv1 = 1.f / rs1;

    float oc[8][4];
    #pragma unroll
    for (int u = 0; u < 8; u++) { oc[u][0]=oc[u][1]=oc[u][2]=oc[u][3]=0.f; }
    #pragma unroll
    for (int ks = 0; ks < 4; ks++) {
        #pragma unroll
        for (int nj = 0; nj < 4; nj++) {
            uint32_t bf[4];
            const int tr = nj*16 + lrow;
            ldsm_x4(bf, sT + tr*128 + (((ks*2+lhalf) ^ (tr&7)) << 4));
            uint32_t b2a[2] = { bf[0], bf[2] };
            mma_f16(oc[nj*2+0], pa[ks], b2a);
            uint32_t b2b[2] = { bf[1], bf[3] };
            mma_f16(oc[nj*2+1], pa[ks], b2b);
        }
    }

    const int r0a = w*16 + g;
    #pragma unroll
    for (int u = 0; u < 8; u++) {
        int col = u*8 + 2*c;
        __half2 hA = __floats2half2_rn(oc[u][0]*inv0, oc[u][1]*inv0);
        __half2 hB = __floats2half2_rn(oc[u][2]*inv1, oc[u][3]*inv1);
        *(uint32_t*)&gATh[((size_t)(b*SEQ + n0 + r0a))*CDIM + h*HD + col]     = *(uint32_t*)&hA;
        *(uint32_t*)&gATh[((size_t)(b*SEQ + n0 + r0a + 8))*CDIM + h*HD + col] = *(uint32_t*)&hB;
    }
}

// ---------------- launcher ---------------------------------------------------
extern "C" void kernel_launch(void* const* d_in, const int* in_sizes, int n_in,
                              void* d_out, int out_size)
{
    const float* x     = (const float*)d_in[0];
    const float* Wqkv  = (const float*)d_in[1];
    const float* bqkv  = (const float*)d_in[2];
    const float* Wproj = (const float*)d_in[3];
    const float* bproj = (const float*)d_in[4];
    float* out = (float*)d_out;

    const int SMEM_K2 = 4 * 4160 * 4;
    cudaFuncSetAttribute(gemm_h,    cudaFuncAttributeMaxDynamicSharedMemorySize, SMEM_GEMMH);
    cudaFuncSetAttribute(k2_newton, cudaFuncAttributeMaxDynamicSharedMemorySize, SMEM_K2);
    cudaFuncSetAttribute(k3_flash,  cudaFuncAttributeMaxDynamicSharedMemorySize, K3_SMEM);
    cudaFuncSetAttribute(k4_out,    cudaFuncAttributeMaxDynamicSharedMemorySize, K4_SMEM);

    __half *pXh, *pWqkvh, *pWph, *pYh, *pATh;
    cudaGetSymbolAddress((void**)&pXh,    gXh);
    cudaGetSymbolAddress((void**)&pWqkvh, gWqkvh);
    cudaGetSymbolAddress((void**)&pWph,   gWph);
    cudaGetSymbolAddress((void**)&pYh,    gYh);
    cudaGetSymbolAddress((void**)&pATh,   gATh);

    // 0. fp32 -> fp16 conversions
    {
        int nx = BN_TOK * CDIM;
        cvtf2h<<<(nx/8 + 255)/256, 256>>>(x, pXh, nx);
        int nw = QKV_N * CDIM;
        cvtf2h<<<(nw/8 + 255)/256, 256>>>(Wqkv, pWqkvh, nw);
        int np = CDIM * CDIM;
        cvtf2h<<<(np/8 + 255)/256, 256>>>(Wproj, pWph, np);
    }

    // 1. QKV projection -> fp16 gYh
    gemm_h<<<dim3(QKV_N/128, BN_TOK/128), 256, SMEM_GEMMH>>>(pXh, pWqkvh, bqkv, pYh, BN_TOK, QKV_N, CDIM, 1);
    // 2. kernel_2 softmax + Newton inverse
    k2_newton<<<NBH, 256, SMEM_K2>>>();
    // 3. flash partials (tensor cores), combine (column-split) + T^T fp16
    k3_flash<<<dim3(NBH, NCH), 128, K3_SMEM>>>();
    k3_combine<<<dim3(NBH, 4), 256>>>();
    // 4. out = softmax(q k_lm^T) @ T (tensor cores) -> gATh fp16
    k4_out<<<dim3(SEQ/64, NBH), 128, K4_SMEM>>>();
    // 5. projection: out = gATh @ Wproj^T + bproj (fp32 out)
    gemm_h<<<dim3(CDIM/128, BN_TOK/128), 256, SMEM_GEMMH>>>(pATh, pWph, bproj, out, BN_TOK, CDIM, CDIM, 0);
}

// round 10
// speedup vs baseline: 1.1502x; 1.0099x over previous
#include <cuda_runtime.h>
#include <cuda_fp16.h>
#include <cstdint>

// ---------------- problem constants ----------------
#define BDIM     4
#define SEQ      8192
#define CDIM     512
#define NH       8
#define HD       64
#define NLM      64
#define LMSTRIDE 128           // SEQ / NLM
#define BN_TOK   (BDIM*SEQ)    // 32768
#define QKV_N    (3*CDIM)      // 1536
#define NBH      (BDIM*NH)     // 32
#define NCH      16            // key chunks for kernel_3 flash
#define KEYS_PER_CH (SEQ/NCH)  // 512
#define TILES_PER_CH (KEYS_PER_CH/64) // 8
#define SCALE    0.125f        // hd^-0.5

// ---------------- device scratch (no runtime allocs allowed) ----------------
__device__ __half gXh[(size_t)BN_TOK * CDIM];    // x in fp16
__device__ __half gWqkvh[QKV_N * CDIM];          // Wqkv in fp16
__device__ __half gWph[CDIM * CDIM];             // Wproj in fp16
__device__ __half gYh[(size_t)BN_TOK * QKV_N];   // qkv activations fp16
__device__ __half gATh[(size_t)BN_TOK * CDIM];   // attention output fp16
__device__ float  gW2inv[NBH*64*64];
__device__ __half gTth[NBH*64*64];               // (W2inv @ F)^T fp16, [bh][hd][lm]
__device__ float  gFp[(size_t)NBH*NCH*64*64];    // flash partial accumulators
__device__ float  gMp[NBH*NCH*64];
__device__ float  gSp[NBH*NCH*64];

// ---------------- ptx helpers ------------------------------------------------
__device__ __forceinline__ uint32_t smem_u32(const void* p) {
    uint32_t a;
    asm("{ .reg .u64 t; cvta.to.shared.u64 t, %1; cvt.u32.u64 %0, t; }" : "=r"(a) : "l"(p));
    return a;
}
__device__ __forceinline__ void mma_f16(float* d, const uint32_t* a, const uint32_t* b) {
    asm volatile(
        "mma.sync.aligned.m16n8k16.row.col.f32.f16.f16.f32 "
        "{%0,%1,%2,%3}, {%4,%5,%6,%7}, {%8,%9}, {%0,%1,%2,%3};"
        : "+f"(d[0]), "+f"(d[1]), "+f"(d[2]), "+f"(d[3])
        : "r"(a[0]), "r"(a[1]), "r"(a[2]), "r"(a[3]),
          "r"(b[0]), "r"(b[1]));
}
__device__ __forceinline__ void ldsm_x4(uint32_t* r, uint32_t addr) {
    asm volatile("ldmatrix.sync.aligned.m8n8.x4.shared.b16 {%0,%1,%2,%3}, [%4];"
                 : "=r"(r[0]), "=r"(r[1]), "=r"(r[2]), "=r"(r[3]) : "r"(addr));
}
__device__ __forceinline__ void ldsm_x4_t(uint32_t* r, uint32_t addr) {
    asm volatile("ldmatrix.sync.aligned.m8n8.x4.trans.shared.b16 {%0,%1,%2,%3}, [%4];"
                 : "=r"(r[0]), "=r"(r[1]), "=r"(r[2]), "=r"(r[3]) : "r"(addr));
}
#define CP_ASYNC16(dst, src) \
    asm volatile("cp.async.cg.shared.global [%0], [%1], 16;" :: "r"(dst), "l"(src) : "memory")
#define CP_COMMIT() asm volatile("cp.async.commit_group;" ::: "memory")
#define CP_WAIT1()  asm volatile("cp.async.wait_group 1;" ::: "memory")
#define CP_WAIT0()  asm volatile("cp.async.wait_group 0;" ::: "memory")

// ---------------- fp32 -> fp16 conversion ------------------------------------
__global__ void __launch_bounds__(256) cvtf2h(const float* __restrict__ s,
                                              __half* __restrict__ d, int n)
{
    int i = (blockIdx.x * blockDim.x + threadIdx.x) * 8;
    if (i < n) {
        float4 a = *(const float4*)(s + i);
        float4 b = *(const float4*)(s + i + 4);
        __half2 h0 = __floats2half2_rn(a.x, a.y);
        __half2 h1 = __floats2half2_rn(a.z, a.w);
        __half2 h2 = __floats2half2_rn(b.x, b.y);
        __half2 h3 = __floats2half2_rn(b.z, b.w);
        uint4 o;
        o.x = *(uint32_t*)&h0; o.y = *(uint32_t*)&h1;
        o.z = *(uint32_t*)&h2; o.w = *(uint32_t*)&h3;
        *(uint4*)(d + i) = o;
    }
}

// ---------------- fp16 tensor-core GEMM (round-6 best config) ----------------
#define STG_BYTES 32768          // 16KB A + 16KB B per stage
#define SMEM_GEMMH (3 * STG_BYTES)

__device__ __forceinline__ void stage_copy(uint32_t sbase, const __half* A,
                                           const __half* B, int bm, int bn,
                                           int K, int k0, int tid)
{
    #pragma unroll
    for (int i = 0; i < 4; i++) {
        int lin = tid + i * 256;
        int row = lin >> 3;
        int c   = lin & 7;
        uint32_t dA = sbase + row * 128 + ((c ^ (row & 7)) << 4);
        CP_ASYNC16(dA, A + (size_t)(bm + row) * K + k0 + c * 8);
        uint32_t dB = sbase + 16384 + row * 128 + ((c ^ (row & 7)) << 4);
        CP_ASYNC16(dB, B + (size_t)(bn + row) * K + k0 + c * 8);
    }
}

__global__ void __launch_bounds__(256) gemm_h(const __half* __restrict__ A,
                                              const __half* __restrict__ B,
                                              const float* __restrict__ bias,
                                              void* __restrict__ Cv,
                                              int M, int N, int K, int half_out)
{
    extern __shared__ __align__(128) char smg[];
    const uint32_t sb = smem_u32(smg);

    const int bm = blockIdx.y * 128;
    const int bn = blockIdx.x * 128;
    const int tid  = threadIdx.x;
    const int lane = tid & 31;
    const int warp = tid >> 5;
    const int wm = (warp & 1) * 64;
    const int wn = (warp >> 1) * 32;
    const int g = lane >> 2;
    const int c = lane & 3;
    const int lrow = lane & 15;
    const int lhalf = lane >> 4;

    float acc[4][4][4];
    #pragma unroll
    for (int mi = 0; mi < 4; mi++)
        #pragma unroll
        for (int t = 0; t < 4; t++)
            #pragma unroll
            for (int r = 0; r < 4; r++) acc[mi][t][r] = 0.f;

    const int KT = K >> 6;

    stage_copy(sb, A, B, bm, bn, K, 0, tid);
    CP_COMMIT();
    stage_copy(sb + STG_BYTES, A, B, bm, bn, K, 64, tid);
    CP_COMMIT();

    for (int kt = 0; kt < KT; kt++) {
        CP_WAIT1();
        __syncthreads();

        if (kt + 2 < KT)
            stage_copy(sb + ((kt + 2) % 3) * STG_BYTES, A, B, bm, bn, K, (kt + 2) * 64, tid);
        CP_COMMIT();

        const uint32_t aBase = sb + (kt % 3) * STG_BYTES;
        const uint32_t bBase = aBase + 16384;

        #pragma unroll
        for (int ks = 0; ks < 4; ks++) {
            uint32_t af[4][4], bf[2][4];
            #pragma unroll
            for (int mi = 0; mi < 4; mi++) {
                const int row = wm + mi * 16 + lrow;
                const int ch  = (ks * 2 + lhalf) ^ (row & 7);
                ldsm_x4(af[mi], aBase + row * 128 + (ch << 4));
            }
            #pragma unroll
            for (int nj = 0; nj < 2; nj++) {
                const int row = wn + nj * 16 + lrow;
                const int ch  = (ks * 2 + lhalf) ^ (row & 7);
                ldsm_x4(bf[nj], bBase + row * 128 + (ch << 4));
            }
            #pragma unroll
            for (int mi = 0; mi < 4; mi++) {
                #pragma unroll
                for (int t = 0; t < 4; t++) {
                    const int nj = t >> 1, sub = t & 1;
                    uint32_t b2[2] = { bf[nj][sub], bf[nj][sub + 2] };
                    mma_f16(acc[mi][t], af[mi], b2);
                }
            }
        }
    }

    if (half_out) {
        __half* C = (__half*)Cv;
        #pragma unroll
        for (int mi = 0; mi < 4; mi++) {
            const int row = bm + wm + mi * 16 + g;
            #pragma unroll
            for (int t = 0; t < 4; t++) {
                const int col = bn + wn + (t >> 1) * 16 + (t & 1) * 8 + 2 * c;
                const float b0 = bias[col], b1 = bias[col + 1];
                __half2 o0 = __floats2half2_rn(acc[mi][t][0] + b0, acc[mi][t][1] + b1);
                __half2 o1 = __floats2half2_rn(acc[mi][t][2] + b0, acc[mi][t][3] + b1);
                *(uint32_t*)(C + (size_t)row * N + col)       = *(uint32_t*)&o0;
                *(uint32_t*)(C + (size_t)(row + 8) * N + col) = *(uint32_t*)&o1;
            }
        }
    } else {
        float* C = (float*)Cv;
        #pragma unroll
        for (int mi = 0; mi < 4; mi++) {
            const int row = bm + wm + mi * 16 + g;
            #pragma unroll
            for (int t = 0; t < 4; t++) {
                const int col = bn + wn + (t >> 1) * 16 + (t & 1) * 8 + 2 * c;
                const float b0 = bias[col], b1 = bias[col + 1];
                float2 o0 = make_float2(acc[mi][t][0] + b0, acc[mi][t][1] + b1);
                float2 o1 = make_float2(acc[mi][t][2] + b0, acc[mi][t][3] + b1);
                *(float2*)(C + (size_t)row * N + col)       = o0;
                *(float2*)(C + (size_t)(row + 8) * N + col) = o1;
            }
        }
    }
}

// ---------------- 64x64 fp32 helpers for 128 threads (4x8 tiles) -------------
__device__ __forceinline__ void mm64_nt8(float* C, int ldc,
                                         const float* A, int lda,
                                         const float* B, int ldb,
                                         float scale, int tid)
{
    const int i0 = (tid >> 3) * 4, j0 = (tid & 7) * 8;
    float c[4][8] = {};
    #pragma unroll 4
    for (int d = 0; d < 64; d++) {
        float a[4], bv[8];
        #pragma unroll
        for (int ii = 0; ii < 4; ii++) a[ii]  = A[(i0+ii)*lda + d];
        #pragma unroll
        for (int jj = 0; jj < 8; jj++) bv[jj] = B[(j0+jj)*ldb + d];
        #pragma unroll
        for (int ii = 0; ii < 4; ii++)
            #pragma unroll
            for (int jj = 0; jj < 8; jj++)
                c[ii][jj] += a[ii] * bv[jj];
    }
    #pragma unroll
    for (int ii = 0; ii < 4; ii++)
        #pragma unroll
        for (int jj = 0; jj < 8; jj++)
            C[(i0+ii)*ldc + j0+jj] = scale * c[ii][jj];
}

__device__ __forceinline__ void mm64_nn8(float* C, int ldc,
                                         const float* A, int lda,
                                         const float* B, int ldb, int tid)
{
    const int i0 = (tid >> 3) * 4, j0 = (tid & 7) * 8;
    float c[4][8] = {};
    #pragma unroll 4
    for (int k = 0; k < 64; k++) {
        float a[4], bv[8];
        #pragma unroll
        for (int ii = 0; ii < 4; ii++) a[ii]  = A[(i0+ii)*lda + k];
        #pragma unroll
        for (int jj = 0; jj < 8; jj++) bv[jj] = B[k*ldb + j0+jj];
        #pragma unroll
        for (int ii = 0; ii < 4; ii++)
            #pragma unroll
            for (int jj = 0; jj < 8; jj++)
                c[ii][jj] += a[ii] * bv[jj];
    }
    #pragma unroll
    for (int ii = 0; ii < 4; ii++)
        #pragma unroll
        for (int jj = 0; jj < 8; jj++)
            C[(i0+ii)*ldc + j0+jj] = c[ii][jj];
}

// ---------------- newton branch (128 threads) ---------------------------------
__device__ void k2_newton_body(char* smraw, int bh, int tid)
{
    float* S  = (float*)smraw;
    float* Z  = S  + 4160;
    float* T1 = Z  + 4160;
    float* T2 = T1 + 4160;
    __shared__ float red[4];

    const int b = bh >> 3, h = bh & 7;

    for (int e = tid; e < 4096; e += 128) {
        int l = e >> 6, d = e & 63;
        size_t base = (size_t)(b * SEQ + l * LMSTRIDE) * QKV_N + h * HD + d;
        Z [l*65 + d] = __half2float(gYh[base]);
        T1[l*65 + d] = __half2float(gYh[base + CDIM]);
    }
    __syncthreads();

    mm64_nt8(S, 65, Z, 65, T1, 65, SCALE, tid);
    __syncthreads();
    if (tid < 64) {
        float mx = -1e30f;
        for (int j = 0; j < 64; j++) mx = fmaxf(mx, S[tid*65 + j]);
        float s = 0.f;
        for (int j = 0; j < 64; j++) { float p = __expf(S[tid*65+j] - mx); S[tid*65+j] = p; s += p; }
        float inv = 1.f / s;
        for (int j = 0; j < 64; j++) S[tid*65 + j] *= inv;
    }
    __syncthreads();

    float part = 0.f;
    for (int e = tid; e < 4096; e += 128) {
        int i = e >> 6, j = e & 63;
        float v = S[i*65 + j];
        part += v * v;
    }
    #pragma unroll
    for (int o = 16; o; o >>= 1) part += __shfl_xor_sync(0xffffffffu, part, o);
    if ((tid & 31) == 0) red[tid >> 5] = part;
    __syncthreads();
    float fro2 = fmaxf(red[0]+red[1]+red[2]+red[3], 1e-12f);
    float invf = 1.f / fro2;

    for (int e = tid; e < 4096; e += 128) {
        int i = e >> 6, j = e & 63;
        Z[j*65 + i] = S[i*65 + j] * invf;
    }
    __syncthreads();

    for (int it = 0; it < 6; it++) {
        mm64_nn8(T1, 65, S, 65, Z, 65, tid);
        __syncthreads();
        mm64_nn8(T2, 65, Z, 65, T1, 65, tid);
        __syncthreads();
        for (int e = tid; e < 4096; e += 128) {
            int i = e >> 6, j = e & 63;
            Z[i*65 + j] = 2.f * Z[i*65 + j] - T2[i*65 + j];
        }
        __syncthreads();
    }

    for (int e = tid; e < 4096; e += 128) {
        int i = e >> 6, j = e & 63;
        gW2inv[bh*4096 + i*64 + j] = Z[i*65 + j];
    }
}

// ---------------- unified flash + newton kernel -------------------------------
// blocks [0, NBH*NCH): flash partials; blocks [NBH*NCH, NBH*NCH+NBH): newton.
// dynamic smem = 66560 bytes (newton requirement; flash uses first 40960).
#define K3K2_SMEM 66560
#define FLASH_BLOCKS (NBH*NCH)

__global__ void __launch_bounds__(128) k3k2()
{
    extern __shared__ __align__(128) char smu[];
    const int blk = blockIdx.x;
    const int tid = threadIdx.x;

    if (blk >= FLASH_BLOCKS) {
        k2_newton_body(smu, blk - FLASH_BLOCKS, tid);
        return;
    }

    const uint32_t sQ  = smem_u32(smu);
    const uint32_t sKV = sQ + 8192;

    const int bh = blk & (NBH - 1);
    const int ch = blk >> 5;
    const int b = bh >> 3, h = bh & 7;
    const int lane = tid & 31;
    const int w = tid >> 5;
    const int g = lane >> 2, c = lane & 3;
    const int lrow = lane & 15, lhalf = lane >> 4;
    const int n0base = ch * KEYS_PER_CH;

    for (int i = tid; i < 512; i += 128) {
        int row = i >> 3, c4 = i & 7;
        CP_ASYNC16(sQ + row*128 + ((c4 ^ (row&7)) << 4),
                   gYh + ((size_t)(b*SEQ + row*LMSTRIDE))*QKV_N + h*HD + c4*8);
    }
    #pragma unroll
    for (int st = 0; st < 2; st++) {
        uint32_t base = sKV + st * 16384;
        for (int i = tid; i < 1024; i += 128) {
            int sel = i >> 9;
            int row = (i >> 3) & 63;
            int c4 = i & 7;
            CP_ASYNC16(base + sel*8192 + row*128 + ((c4 ^ (row&7)) << 4),
                       gYh + ((size_t)(b*SEQ + n0base + st*64 + row))*QKV_N
                           + (sel ? 2*CDIM : CDIM) + h*HD + c4*8);
        }
        CP_COMMIT();
    }

    float m0 = -1e30f, m1 = -1e30f, s0 = 0.f, s1 = 0.f;
    float oc[8][4];
    #pragma unroll
    for (int u = 0; u < 8; u++) { oc[u][0]=oc[u][1]=oc[u][2]=oc[u][3]=0.f; }

    for (int t = 0; t < TILES_PER_CH; t++) {
        CP_WAIT1();
        __syncthreads();
        const uint32_t kb = sKV + (t & 1) * 16384;
        const uint32_t vb = kb + 8192;

        float sc[8][4];
        #pragma unroll
        for (int u = 0; u < 8; u++) { sc[u][0]=sc[u][1]=sc[u][2]=sc[u][3]=0.f; }
        #pragma unroll
        for (int ks = 0; ks < 4; ks++) {
            uint32_t af[4];
            const int qr = w*16 + lrow;
            ldsm_x4(af, sQ + qr*128 + (((ks*2+lhalf) ^ (qr&7)) << 4));
            #pragma unroll
            for (int nj = 0; nj < 4; nj++) {
                uint32_t bf[4];
                const int kr = nj*16 + lrow;
                ldsm_x4(bf, kb + kr*128 + (((ks*2+lhalf) ^ (kr&7)) << 4));
                uint32_t b2a[2] = { bf[0], bf[2] };
                mma_f16(sc[nj*2+0], af, b2a);
                uint32_t b2b[2] = { bf[1], bf[3] };
                mma_f16(sc[nj*2+1], af, b2b);
            }
        }
        float tm0 = -1e30f, tm1 = -1e30f;
        #pragma unroll
        for (int u = 0; u < 8; u++) {
            sc[u][0]*=SCALE; sc[u][1]*=SCALE; sc[u][2]*=SCALE; sc[u][3]*=SCALE;
            tm0 = fmaxf(tm0, fmaxf(sc[u][0], sc[u][1]));
            tm1 = fmaxf(tm1, fmaxf(sc[u][2], sc[u][3]));
        }
        tm0 = fmaxf(tm0, __shfl_xor_sync(0xffffffffu, tm0, 1));
        tm0 = fmaxf(tm0, __shfl_xor_sync(0xffffffffu, tm0, 2));
        tm1 = fmaxf(tm1, __shfl_xor_sync(0xffffffffu, tm1, 1));
        tm1 = fmaxf(tm1, __shfl_xor_sync(0xffffffffu, tm1, 2));
        const float mn0 = fmaxf(m0, tm0), mn1 = fmaxf(m1, tm1);
        const float cr0 = __expf(m0 - mn0), cr1 = __expf(m1 - mn1);
        float rs0 = 0.f, rs1 = 0.f;
        uint32_t pa[4][4];
        #pragma unroll
        for (int u = 0; u < 8; u++) {
            float p0 = __expf(sc[u][0]-mn0), p1 = __expf(sc[u][1]-mn0);
            float p2 = __expf(sc[u][2]-mn1), p3 = __expf(sc[u][3]-mn1);
            rs0 += p0 + p1; rs1 += p2 + p3;
            __half2 hA = __floats2half2_rn(p0, p1);
            __half2 hB = __floats2half2_rn(p2, p3);
            pa[u>>1][(u&1)*2+0] = *(uint32_t*)&hA;
            pa[u>>1][(u&1)*2+1] = *(uint32_t*)&hB;
        }
        rs0 += __shfl_xor_sync(0xffffffffu, rs0, 1);
        rs0 += __shfl_xor_sync(0xffffffffu, rs0, 2);
        rs1 += __shfl_xor_sync(0xffffffffu, rs1, 1);
        rs1 += __shfl_xor_sync(0xffffffffu, rs1, 2);
        s0 = s0*cr0 + rs0; s1 = s1*cr1 + rs1;
        m0 = mn0; m1 = mn1;
        #pragma unroll
        for (int u = 0; u < 8; u++) {
            oc[u][0]*=cr0; oc[u][1]*=cr0; oc[u][2]*=cr1; oc[u][3]*=cr1;
        }
        #pragma unroll
        for (int ks = 0; ks < 4; ks++) {
            #pragma unroll
            for (int nj = 0; nj < 4; nj++) {
                uint32_t bf[4];
                const int rk = ks*16 + (lane&7) + ((lane>>4)&1)*8;
                const int cn = nj*2 + ((lane>>3)&1);
                ldsm_x4_t(bf, vb + rk*128 + (((cn ^ (rk&7))) << 4));
                uint32_t b2a[2] = { bf[0], bf[2] };
                mma_f16(oc[nj*2+0], pa[ks], b2a);
                uint32_t b2b[2] = { bf[1], bf[3] };
                mma_f16(oc[nj*2+1], pa[ks], b2b);
            }
        }
        __syncthreads();
        if (t + 2 < TILES_PER_CH) {
            uint32_t base = sKV + (t & 1) * 16384;
            int n0 = n0base + (t + 2) * 64;
            for (int i = tid; i < 1024; i += 128) {
                int sel = i >> 9;
                int row = (i >> 3) & 63;
                int c4 = i & 7;
                CP_ASYNC16(base + sel*8192 + row*128 + ((c4 ^ (row&7)) << 4),
                           gYh + ((size_t)(b*SEQ + n0 + row))*QKV_N
                               + (sel ? 2*CDIM : CDIM) + h*HD + c4*8);
            }
        }
        CP_COMMIT();
    }

    const size_t fbase = ((size_t)bh*NCH + ch)*4096;
    const int r0a = w*16 + g, r1a = r0a + 8;
    #pragma unroll
    for (int u = 0; u < 8; u++) {
        int col = u*8 + 2*c;
        *(float2*)&gFp[fbase + (size_t)r0a*64 + col] = make_float2(oc[u][0], oc[u][1]);
        *(float2*)&gFp[fbase + (size_t)r1a*64 + col] = make_float2(oc[u][2], oc[u][3]);
    }
    if (c == 0) {
        gMp[(bh*NCH+ch)*64 + r0a] = m0;
        gMp[(bh*NCH+ch)*64 + r1a] = m1;
        gSp[(bh*NCH+ch)*64 + r0a] = s0;
        gSp[(bh*NCH+ch)*64 + r1a] = s1;
    }
}

// ---------------- combine flash partials + T^T = (W2inv @ F)^T ---------------
__global__ void __launch_bounds__(256) k3_combine()
{
    __shared__ float wgt[NCH*64];
    __shared__ float sF[64*17];
    __shared__ float sW[64*64];
    const int bh = blockIdx.x;
    const int d0 = blockIdx.y * 16;
    const int tid = threadIdx.x;

    if (tid < 64) {
        float M = -1e30f;
        for (int c = 0; c < NCH; c++) M = fmaxf(M, gMp[(bh*NCH + c)*64 + tid]);
        float denom = 0.f;
        for (int c = 0; c < NCH; c++)
            denom += __expf(gMp[(bh*NCH + c)*64 + tid] - M) * gSp[(bh*NCH + c)*64 + tid];
        float invd = 1.f / denom;
        for (int c = 0; c < NCH; c++)
            wgt[c*64 + tid] = __expf(gMp[(bh*NCH + c)*64 + tid] - M) * invd;
    }
    for (int e = tid; e < 4096; e += 256) sW[e] = gW2inv[bh*4096 + e];
    __syncthreads();

    for (int e = tid; e < 1024; e += 256) {
        int l = e >> 4, dd = e & 15;
        float f = 0.f;
        #pragma unroll 4
        for (int c = 0; c < NCH; c++)
            f += gFp[((size_t)bh * NCH + c) * 4096 + l*64 + d0 + dd] * wgt[c*64 + l];
        sF[l*17 + dd] = f;
    }
    __syncthreads();

    const int i0 = (tid >> 4) * 4, j = tid & 15;
    float cc[4] = {0.f, 0.f, 0.f, 0.f};
    #pragma unroll 8
    for (int k = 0; k < 64; k++) {
        float bv = sF[k*17 + j];
        cc[0] += sW[(i0+0)*64 + k] * bv;
        cc[1] += sW[(i0+1)*64 + k] * bv;
        cc[2] += sW[(i0+2)*64 + k] * bv;
        cc[3] += sW[(i0+3)*64 + k] * bv;
    }
    #pragma unroll
    for (int ii = 0; ii < 4; ii++)
        gTth[bh*4096 + (d0 + j)*64 + (i0 + ii)] = __float2half(cc[ii]);
}

// ---------------- kernel_1 @ T (tensor-core) -> gATh, 128 q-rows/block -------
#define K4_SMEM (16384 + 2*8192)

__global__ void __launch_bounds__(256) k4_out()
{
    extern __shared__ __align__(128) char sm4[];
    const uint32_t sQ = smem_u32(sm4);       // 128 rows
    const uint32_t sK = sQ + 16384;          // 64 landmark rows
    const uint32_t sT = sK + 8192;           // 64 hd rows (T^T)

    const int qt = blockIdx.x;
    const int bh = blockIdx.y;
    const int b = bh >> 3, h = bh & 7;
    const int n0 = qt * 128;
    const int tid = threadIdx.x;
    const int lane = tid & 31;
    const int w = tid >> 5;
    const int g = lane >> 2, c = lane & 3;
    const int lrow = lane & 15, lhalf = lane >> 4;

    for (int i = tid; i < 1024; i += 256) {
        int row = i >> 3, c4 = i & 7;
        uint32_t swz = (uint32_t)((c4 ^ (row & 7)) << 4);
        CP_ASYNC16(sQ + row*128 + swz,
                   gYh + ((size_t)(b*SEQ + n0 + row))*QKV_N + h*HD + c4*8);
    }
    for (int i = tid; i < 512; i += 256) {
        int row = i >> 3, c4 = i & 7;
        uint32_t swz = (uint32_t)((c4 ^ (row & 7)) << 4);
        CP_ASYNC16(sK + row*128 + swz,
                   gYh + ((size_t)(b*SEQ + row*LMSTRIDE))*QKV_N + CDIM + h*HD + c4*8);
        CP_ASYNC16(sT + row*128 + swz,
                   gTth + bh*4096 + row*64 + c4*8);
    }
    CP_COMMIT();
    CP_WAIT0();
    __syncthreads();

    // S = Q @ K_lm^T ; warp w handles q rows [w*16, w*16+16)
    float sc[8][4];
    #pragma unroll
    for (int u = 0; u < 8; u++) { sc[u][0]=sc[u][1]=sc[u][2]=sc[u][3]=0.f; }
    #pragma unroll
    for (int ks = 0; ks < 4; ks++) {
        uint32_t af[4];
        const int qr = w*16 + lrow;
        ldsm_x4(af, sQ + qr*128 + (((ks*2+lhalf) ^ (qr&7)) << 4));
        #pragma unroll
        for (int nj = 0; nj < 4; nj++) {
            uint32_t bf[4];
            const int kr = nj*16 + lrow;
            ldsm_x4(bf, sK + kr*128 + (((ks*2+lhalf) ^ (kr&7)) << 4));
            uint32_t b2a[2] = { bf[0], bf[2] };
            mma_f16(sc[nj*2+0], af, b2a);
            uint32_t b2b[2] = { bf[1], bf[3] };
            mma_f16(sc[nj*2+1], af, b2b);
        }
    }
    float tm0 = -1e30f, tm1 = -1e30f;
    #pragma unroll
    for (int u = 0; u < 8; u++) {
        sc[u][0]*=SCALE; sc[u][1]*=SCALE; sc[u][2]*=SCALE; sc[u][3]*=SCALE;
        tm0 = fmaxf(tm0, fmaxf(sc[u][0], sc[u][1]));
        tm1 = fmaxf(tm1, fmaxf(sc[u][2], sc[u][3]));
    }
    tm0 = fmaxf(tm0, __shfl_xor_sync(0xffffffffu, tm0, 1));
    tm0 = fmaxf(tm0, __shfl_xor_sync(0xffffffffu, tm0, 2));
    tm1 = fmaxf(tm1, __shfl_xor_sync(0xffffffffu, tm1, 1));
    tm1 = fmaxf(tm1, __shfl_xor_sync(0xffffffffu, tm1, 2));
    float rs0 = 0.f, rs1 = 0.f;
    uint32_t pa[4][4];
    #pragma unroll
    for (int u = 0; u < 8; u++) {
        float p0 = __expf(sc[u][0]-tm0), p1 = __expf(sc[u][1]-tm0);
        float p2 = __expf(sc[u][2]-tm1), p3 = __expf(sc[u][3]-tm1);
        rs0 += p0 + p1; rs1 += p2 + p3;
        __half2 hA = __floats2half2_rn(p0, p1);
        __half2 hB = __floats2half2_rn(p2, p3);
        pa[u>>1][(u&1)*2+0] = *(uint32_t*)&hA;
        pa[u>>1][(u&1)*2+1] = *(uint32_t*)&hB;
    }
    rs0 += __shfl_xor_sync(0xffffffffu, rs0, 1);
    rs0 += __shfl_xor_sync(0xffffffffu, rs0, 2);
    rs1 += __shfl_xor_sync(0xffffffffu, rs1, 1);
    rs1 += __shfl_xor_sync(0xffffffffu, rs1, 2);
    const float inv0 = 1.f / rs0, inv1 = 1.f / rs1;

    float oc[8][4];
    #pragma unroll
    for (int u = 0; u < 8; u++) { oc[u][0]=oc[u][1]=oc[u][2]=oc[u][3]=0.f; }
    #pragma unroll
    for (int ks = 0; ks < 4; ks++) {
        #pragma unroll
        for (int nj = 0; nj < 4; nj++) {
            uint32_t bf[4];
            const int tr = nj*16 + lrow;
            ldsm_x4(bf, sT + tr*128 + (((ks*2+lhalf) ^ (tr&7)) << 4));
            uint32_t b2a[2] = { bf[0], bf[2] };
            mma_f16(oc[nj*2+0], pa[ks], b2a);
            uint32_t b2b[2] = { bf[1], bf[3] };
            mma_f16(oc[nj*2+1], pa[ks], b2b);
        }
    }

    const int r0a = w*16 + g;
    #pragma unroll
    for (int u = 0; u < 8; u++) {
        int col = u*8 + 2*c;
        __half2 hA = __floats2half2_rn(oc[u][0]*inv0, oc[u][1]*inv0);
        __half2 hB = __floats2half2_rn(oc[u][2]*inv1, oc[u][3]*inv1);
        *(uint32_t*)&gATh[((size_t)(b*SEQ + n0 + r0a))*CDIM + h*HD + col]     = *(uint32_t*)&hA;
        *(uint32_t*)&gATh[((size_t)(b*SEQ + n0 + r0a + 8))*CDIM + h*HD + col] = *(uint32_t*)&hB;
    }
}

// ---------------- launcher ---------------------------------------------------
extern "C" void kernel_launch(void* const* d_in, const int* in_sizes, int n_in,
                              void* d_out, int out_size)
{
    const float* x     = (const float*)d_in[0];
    const float* Wqkv  = (const float*)d_in[1];
    const float* bqkv  = (const float*)d_in[2];
    const float* Wproj = (const float*)d_in[3];
    const float* bproj = (const float*)d_in[4];
    float* out = (float*)d_out;

    cudaFuncSetAttribute(gemm_h, cudaFuncAttributeMaxDynamicSharedMemorySize, SMEM_GEMMH);
    cudaFuncSetAttribute(k3k2,   cudaFuncAttributeMaxDynamicSharedMemorySize, K3K2_SMEM);
    cudaFuncSetAttribute(k4_out, cudaFuncAttributeMaxDynamicSharedMemorySize, K4_SMEM);

    __half *pXh, *pWqkvh, *pWph, *pYh, *pATh;
    cudaGetSymbolAddress((void**)&pXh,    gXh);
    cudaGetSymbolAddress((void**)&pWqkvh, gWqkvh);
    cudaGetSymbolAddress((void**)&pWph,   gWph);
    cudaGetSymbolAddress((void**)&pYh,    gYh);
    cudaGetSymbolAddress((void**)&pATh,   gATh);

    // 0. fp32 -> fp16 conversions
    {
        int nx = BN_TOK * CDIM;
        cvtf2h<<<(nx/8 + 255)/256, 256>>>(x, pXh, nx);
        int nw = QKV_N * CDIM;
        cvtf2h<<<(nw/8 + 255)/256, 256>>>(Wqkv, pWqkvh, nw);
        int np = CDIM * CDIM;
        cvtf2h<<<(np/8 + 255)/256, 256>>>(Wproj, pWph, np);
    }

    // 1. QKV projection -> fp16 gYh
    gemm_h<<<dim3(QKV_N/128, BN_TOK/128), 256, SMEM_GEMMH>>>(pXh, pWqkvh, bqkv, pYh, BN_TOK, QKV_N, CDIM, 1);
    // 2+3. flash partials AND newton inverse concurrently (heterogeneous grid)
    k3k2<<<FLASH_BLOCKS + NBH, 128, K3K2_SMEM>>>();
    k3_combine<<<dim3(NBH, 4), 256>>>();
    // 4. out = softmax(q k_lm^T) @ T -> gATh fp16 (128 q-rows per block)
    k4_out<<<dim3(SEQ/128, NBH), 256, K4_SMEM>>>();
    // 5. projection: out = gATh @ Wproj^T + bproj (fp32 out)
    gemm_h<<<dim3(CDIM/128, BN_TOK/128), 256, SMEM_GEMMH>>>(pATh, pWph, bproj, out, BN_TOK, CDIM, CDIM, 0);
}

// round 11
// speedup vs baseline: 1.1722x; 1.0192x over previous
#include <cuda_runtime.h>
#include <cuda_fp16.h>
#include <cstdint>

// ---------------- problem constants ----------------
#define BDIM     4
#define SEQ      8192
#define CDIM     512
#define NH       8
#define HD       64
#define NLM      64
#define LMSTRIDE 128           // SEQ / NLM
#define BN_TOK   (BDIM*SEQ)    // 32768
#define QKV_N    (3*CDIM)      // 1536
#define NBH      (BDIM*NH)     // 32
#define NCH      16            // key chunks for kernel_3 flash
#define KEYS_PER_CH (SEQ/NCH)  // 512
#define TILES_PER_CH (KEYS_PER_CH/64) // 8
#define SCALE    0.125f        // hd^-0.5

// ---------------- device scratch (no runtime allocs allowed) ----------------
__device__ __half gXh[(size_t)BN_TOK * CDIM];    // x in fp16
__device__ __half gWqkvh[QKV_N * CDIM];          // Wqkv in fp16
__device__ __half gWph[CDIM * CDIM];             // Wproj in fp16
__device__ __half gYh[(size_t)BN_TOK * QKV_N];   // qkv activations fp16
__device__ __half gATh[(size_t)BN_TOK * CDIM];   // attention output fp16
__device__ float  gW2inv[NBH*64*64];
__device__ __half gTth[NBH*64*64];               // (W2inv @ F)^T fp16, [bh][hd][lm]
__device__ float  gFp[(size_t)NBH*NCH*64*64];    // flash partial accumulators
__device__ float  gMp[NBH*NCH*64];
__device__ float  gSp[NBH*NCH*64];

// ---------------- ptx helpers ------------------------------------------------
__device__ __forceinline__ uint32_t smem_u32(const void* p) {
    uint32_t a;
    asm("{ .reg .u64 t; cvta.to.shared.u64 t, %1; cvt.u32.u64 %0, t; }" : "=r"(a) : "l"(p));
    return a;
}
__device__ __forceinline__ void mma_f16(float* d, const uint32_t* a, const uint32_t* b) {
    asm volatile(
        "mma.sync.aligned.m16n8k16.row.col.f32.f16.f16.f32 "
        "{%0,%1,%2,%3}, {%4,%5,%6,%7}, {%8,%9}, {%0,%1,%2,%3};"
        : "+f"(d[0]), "+f"(d[1]), "+f"(d[2]), "+f"(d[3])
        : "r"(a[0]), "r"(a[1]), "r"(a[2]), "r"(a[3]),
          "r"(b[0]), "r"(b[1]));
}
__device__ __forceinline__ void ldsm_x4(uint32_t* r, uint32_t addr) {
    asm volatile("ldmatrix.sync.aligned.m8n8.x4.shared.b16 {%0,%1,%2,%3}, [%4];"
                 : "=r"(r[0]), "=r"(r[1]), "=r"(r[2]), "=r"(r[3]) : "r"(addr));
}
__device__ __forceinline__ void ldsm_x4_t(uint32_t* r, uint32_t addr) {
    asm volatile("ldmatrix.sync.aligned.m8n8.x4.trans.shared.b16 {%0,%1,%2,%3}, [%4];"
                 : "=r"(r[0]), "=r"(r[1]), "=r"(r[2]), "=r"(r[3]) : "r"(addr));
}
#define CP_ASYNC16(dst, src) \
    asm volatile("cp.async.cg.shared.global [%0], [%1], 16;" :: "r"(dst), "l"(src) : "memory")
#define CP_COMMIT() asm volatile("cp.async.commit_group;" ::: "memory")
#define CP_WAIT1()  asm volatile("cp.async.wait_group 1;" ::: "memory")
#define CP_WAIT0()  asm volatile("cp.async.wait_group 0;" ::: "memory")

// ---------------- fp32 -> fp16 conversion ------------------------------------
__global__ void __launch_bounds__(256) cvtf2h(const float* __restrict__ s,
                                              __half* __restrict__ d, int n)
{
    int i = (blockIdx.x * blockDim.x + threadIdx.x) * 8;
    if (i < n) {
        float4 a = *(const float4*)(s + i);
        float4 b = *(const float4*)(s + i + 4);
        __half2 h0 = __floats2half2_rn(a.x, a.y);
        __half2 h1 = __floats2half2_rn(a.z, a.w);
        __half2 h2 = __floats2half2_rn(b.x, b.y);
        __half2 h3 = __floats2half2_rn(b.z, b.w);
        uint4 o;
        o.x = *(uint32_t*)&h0; o.y = *(uint32_t*)&h1;
        o.z = *(uint32_t*)&h2; o.w = *(uint32_t*)&h3;
        *(uint4*)(d + i) = o;
    }
}

// ---------------- fp16 tensor-core GEMM (round-6 best config) ----------------
#define STG_BYTES 32768          // 16KB A + 16KB B per stage
#define SMEM_GEMMH (3 * STG_BYTES)

__device__ __forceinline__ void stage_copy(uint32_t sbase, const __half* A,
                                           const __half* B, int bm, int bn,
                                           int K, int k0, int tid)
{
    #pragma unroll
    for (int i = 0; i < 4; i++) {
        int lin = tid + i * 256;
        int row = lin >> 3;
        int c   = lin & 7;
        uint32_t dA = sbase + row * 128 + ((c ^ (row & 7)) << 4);
        CP_ASYNC16(dA, A + (size_t)(bm + row) * K + k0 + c * 8);
        uint32_t dB = sbase + 16384 + row * 128 + ((c ^ (row & 7)) << 4);
        CP_ASYNC16(dB, B + (size_t)(bn + row) * K + k0 + c * 8);
    }
}

__global__ void __launch_bounds__(256) gemm_h(const __half* __restrict__ A,
                                              const __half* __restrict__ B,
                                              const float* __restrict__ bias,
                                              void* __restrict__ Cv,
                                              int M, int N, int K, int half_out)
{
    extern __shared__ __align__(128) char smg[];
    const uint32_t sb = smem_u32(smg);

    const int bm = blockIdx.y * 128;
    const int bn = blockIdx.x * 128;
    const int tid  = threadIdx.x;
    const int lane = tid & 31;
    const int warp = tid >> 5;
    const int wm = (warp & 1) * 64;
    const int wn = (warp >> 1) * 32;
    const int g = lane >> 2;
    const int c = lane & 3;
    const int lrow = lane & 15;
    const int lhalf = lane >> 4;

    float acc[4][4][4];
    #pragma unroll
    for (int mi = 0; mi < 4; mi++)
        #pragma unroll
        for (int t = 0; t < 4; t++)
            #pragma unroll
            for (int r = 0; r < 4; r++) acc[mi][t][r] = 0.f;

    const int KT = K >> 6;

    stage_copy(sb, A, B, bm, bn, K, 0, tid);
    CP_COMMIT();
    stage_copy(sb + STG_BYTES, A, B, bm, bn, K, 64, tid);
    CP_COMMIT();

    for (int kt = 0; kt < KT; kt++) {
        CP_WAIT1();
        __syncthreads();

        if (kt + 2 < KT)
            stage_copy(sb + ((kt + 2) % 3) * STG_BYTES, A, B, bm, bn, K, (kt + 2) * 64, tid);
        CP_COMMIT();

        const uint32_t aBase = sb + (kt % 3) * STG_BYTES;
        const uint32_t bBase = aBase + 16384;

        #pragma unroll
        for (int ks = 0; ks < 4; ks++) {
            uint32_t af[4][4], bf[2][4];
            #pragma unroll
            for (int mi = 0; mi < 4; mi++) {
                const int row = wm + mi * 16 + lrow;
                const int ch  = (ks * 2 + lhalf) ^ (row & 7);
                ldsm_x4(af[mi], aBase + row * 128 + (ch << 4));
            }
            #pragma unroll
            for (int nj = 0; nj < 2; nj++) {
                const int row = wn + nj * 16 + lrow;
                const int ch  = (ks * 2 + lhalf) ^ (row & 7);
                ldsm_x4(bf[nj], bBase + row * 128 + (ch << 4));
            }
            #pragma unroll
            for (int mi = 0; mi < 4; mi++) {
                #pragma unroll
                for (int t = 0; t < 4; t++) {
                    const int nj = t >> 1, sub = t & 1;
                    uint32_t b2[2] = { bf[nj][sub], bf[nj][sub + 2] };
                    mma_f16(acc[mi][t], af[mi], b2);
                }
            }
        }
    }

    if (half_out) {
        __half* C = (__half*)Cv;
        #pragma unroll
        for (int mi = 0; mi < 4; mi++) {
            const int row = bm + wm + mi * 16 + g;
            #pragma unroll
            for (int t = 0; t < 4; t++) {
                const int col = bn + wn + (t >> 1) * 16 + (t & 1) * 8 + 2 * c;
                const float b0 = bias[col], b1 = bias[col + 1];
                __half2 o0 = __floats2half2_rn(acc[mi][t][0] + b0, acc[mi][t][1] + b1);
                __half2 o1 = __floats2half2_rn(acc[mi][t][2] + b0, acc[mi][t][3] + b1);
                *(uint32_t*)(C + (size_t)row * N + col)       = *(uint32_t*)&o0;
                *(uint32_t*)(C + (size_t)(row + 8) * N + col) = *(uint32_t*)&o1;
            }
        }
    } else {
        float* C = (float*)Cv;
        #pragma unroll
        for (int mi = 0; mi < 4; mi++) {
            const int row = bm + wm + mi * 16 + g;
            #pragma unroll
            for (int t = 0; t < 4; t++) {
                const int col = bn + wn + (t >> 1) * 16 + (t & 1) * 8 + 2 * c;
                const float b0 = bias[col], b1 = bias[col + 1];
                float2 o0 = make_float2(acc[mi][t][0] + b0, acc[mi][t][1] + b1);
                float2 o1 = make_float2(acc[mi][t][2] + b0, acc[mi][t][3] + b1);
                *(float2*)(C + (size_t)row * N + col)       = o0;
                *(float2*)(C + (size_t)(row + 8) * N + col) = o1;
            }
        }
    }
}

// ---------------- 64x64 fp32 helpers for 128 threads (4x8 tiles) -------------
__device__ __forceinline__ void mm64_nt8(float* C, int ldc,
                                         const float* A, int lda,
                                         const float* B, int ldb,
                                         float scale, int tid)
{
    const int i0 = (tid >> 3) * 4, j0 = (tid & 7) * 8;
    float c[4][8] = {};
    #pragma unroll 4
    for (int d = 0; d < 64; d++) {
        float a[4], bv[8];
        #pragma unroll
        for (int ii = 0; ii < 4; ii++) a[ii]  = A[(i0+ii)*lda + d];
        #pragma unroll
        for (int jj = 0; jj < 8; jj++) bv[jj] = B[(j0+jj)*ldb + d];
        #pragma unroll
        for (int ii = 0; ii < 4; ii++)
            #pragma unroll
            for (int jj = 0; jj < 8; jj++)
                c[ii][jj] += a[ii] * bv[jj];
    }
    #pragma unroll
    for (int ii = 0; ii < 4; ii++)
        #pragma unroll
        for (int jj = 0; jj < 8; jj++)
            C[(i0+ii)*ldc + j0+jj] = scale * c[ii][jj];
}

__device__ __forceinline__ void mm64_nn8(float* C, int ldc,
                                         const float* A, int lda,
                                         const float* B, int ldb, int tid)
{
    const int i0 = (tid >> 3) * 4, j0 = (tid & 7) * 8;
    float c[4][8] = {};
    #pragma unroll 4
    for (int k = 0; k < 64; k++) {
        float a[4], bv[8];
        #pragma unroll
        for (int ii = 0; ii < 4; ii++) a[ii]  = A[(i0+ii)*lda + k];
        #pragma unroll
        for (int jj = 0; jj < 8; jj++) bv[jj] = B[k*ldb + j0+jj];
        #pragma unroll
        for (int ii = 0; ii < 4; ii++)
            #pragma unroll
            for (int jj = 0; jj < 8; jj++)
                c[ii][jj] += a[ii] * bv[jj];
    }
    #pragma unroll
    for (int ii = 0; ii < 4; ii++)
        #pragma unroll
        for (int jj = 0; jj < 8; jj++)
            C[(i0+ii)*ldc + j0+jj] = c[ii][jj];
}

// ---------------- newton branch (128 threads, 3 smem matrices) ----------------
// Z-update is done with register accumulation + barrier (in-place on Z),
// eliminating the 4th 64x65 buffer -> 49,920 B total.
__device__ void k2_newton_body(char* smraw, int bh, int tid)
{
    float* S  = (float*)smraw;
    float* Z  = S  + 4160;
    float* T1 = Z  + 4160;
    __shared__ float red[4];

    const int b = bh >> 3, h = bh & 7;

    for (int e = tid; e < 4096; e += 128) {
        int l = e >> 6, d = e & 63;
        size_t base = (size_t)(b * SEQ + l * LMSTRIDE) * QKV_N + h * HD + d;
        Z [l*65 + d] = __half2float(gYh[base]);
        T1[l*65 + d] = __half2float(gYh[base + CDIM]);
    }
    __syncthreads();

    mm64_nt8(S, 65, Z, 65, T1, 65, SCALE, tid);   // S = scale * Qlm Klm^T
    __syncthreads();
    if (tid < 64) {
        float mx = -1e30f;
        for (int j = 0; j < 64; j++) mx = fmaxf(mx, S[tid*65 + j]);
        float s = 0.f;
        for (int j = 0; j < 64; j++) { float p = __expf(S[tid*65+j] - mx); S[tid*65+j] = p; s += p; }
        float inv = 1.f / s;
        for (int j = 0; j < 64; j++) S[tid*65 + j] *= inv;
    }
    __syncthreads();

    float part = 0.f;
    for (int e = tid; e < 4096; e += 128) {
        int i = e >> 6, j = e & 63;
        float v = S[i*65 + j];
        part += v * v;
    }
    #pragma unroll
    for (int o = 16; o; o >>= 1) part += __shfl_xor_sync(0xffffffffu, part, o);
    if ((tid & 31) == 0) red[tid >> 5] = part;
    __syncthreads();
    float fro2 = fmaxf(red[0]+red[1]+red[2]+red[3], 1e-12f);
    float invf = 1.f / fro2;

    // Z = S^T / fro^2  (old Z fully consumed by mm64_nt8 above)
    for (int e = tid; e < 4096; e += 128) {
        int i = e >> 6, j = e & 63;
        Z[j*65 + i] = S[i*65 + j] * invf;
    }
    __syncthreads();

    const int i0 = (tid >> 3) * 4, j0 = (tid & 7) * 8;
    for (int it = 0; it < 6; it++) {
        mm64_nn8(T1, 65, S, 65, Z, 65, tid);   // T1 = S @ Z
        __syncthreads();
        // cc = 2Z - Z @ T1 (all smem reads into regs), then in-place write
        float cc[4][8];
        #pragma unroll
        for (int ii = 0; ii < 4; ii++)
            #pragma unroll
            for (int jj = 0; jj < 8; jj++)
                cc[ii][jj] = 2.f * Z[(i0+ii)*65 + j0+jj];
        #pragma unroll 4
        for (int k = 0; k < 64; k++) {
            float a[4], bv[8];
            #pragma unroll
            for (int ii = 0; ii < 4; ii++) a[ii]  = Z[(i0+ii)*65 + k];
            #pragma unroll
            for (int jj = 0; jj < 8; jj++) bv[jj] = T1[k*65 + j0+jj];
            #pragma unroll
            for (int ii = 0; ii < 4; ii++)
                #pragma unroll
                for (int jj = 0; jj < 8; jj++)
                    cc[ii][jj] -= a[ii] * bv[jj];
        }
        __syncthreads();   // all reads of Z complete before overwrite
        #pragma unroll
        for (int ii = 0; ii < 4; ii++)
            #pragma unroll
            for (int jj = 0; jj < 8; jj++)
                Z[(i0+ii)*65 + j0+jj] = cc[ii][jj];
        __syncthreads();
    }

    for (int e = tid; e < 4096; e += 128) {
        int i = e >> 6, j = e & 63;
        gW2inv[bh*4096 + i*64 + j] = Z[i*65 + j];
    }
}

// ---------------- unified flash + newton kernel -------------------------------
// blocks [0, NBH): newton; blocks [NBH, NBH + NBH*NCH): flash partials.
// dynamic smem = 49,920 bytes -> 4 CTAs/SM.
#define K3K2_SMEM 49920
#define FLASH_BLOCKS (NBH*NCH)

__global__ void __launch_bounds__(128) k3k2()
{
    extern __shared__ __align__(128) char smu[];
    const int blk = blockIdx.x;
    const int tid = threadIdx.x;

    if (blk < NBH) {
        k2_newton_body(smu, blk, tid);
        return;
    }

    const uint32_t sQ  = smem_u32(smu);
    const uint32_t sKV = sQ + 8192;

    const int fblk = blk - NBH;
    const int bh = fblk & (NBH - 1);
    const int ch = fblk >> 5;
    const int b = bh >> 3, h = bh & 7;
    const int lane = tid & 31;
    const int w = tid >> 5;
    const int g = lane >> 2, c = lane & 3;
    const int lrow = lane & 15, lhalf = lane >> 4;
    const int n0base = ch * KEYS_PER_CH;

    for (int i = tid; i < 512; i += 128) {
        int row = i >> 3, c4 = i & 7;
        CP_ASYNC16(sQ + row*128 + ((c4 ^ (row&7)) << 4),
                   gYh + ((size_t)(b*SEQ + row*LMSTRIDE))*QKV_N + h*HD + c4*8);
    }
    #pragma unroll
    for (int st = 0; st < 2; st++) {
        uint32_t base = sKV + st * 16384;
        for (int i = tid; i < 1024; i += 128) {
            int sel = i >> 9;
            int row = (i >> 3) & 63;
            int c4 = i & 7;
            CP_ASYNC16(base + sel*8192 + row*128 + ((c4 ^ (row&7)) << 4),
                       gYh + ((size_t)(b*SEQ + n0base + st*64 + row))*QKV_N
                           + (sel ? 2*CDIM : CDIM) + h*HD + c4*8);
        }
        CP_COMMIT();
    }

    float m0 = -1e30f, m1 = -1e30f, s0 = 0.f, s1 = 0.f;
    float oc[8][4];
    #pragma unroll
    for (int u = 0; u < 8; u++) { oc[u][0]=oc[u][1]=oc[u][2]=oc[u][3]=0.f; }

    for (int t = 0; t < TILES_PER_CH; t++) {
        CP_WAIT1();
        __syncthreads();
        const uint32_t kb = sKV + (t & 1) * 16384;
        const uint32_t vb = kb + 8192;

        float sc[8][4];
        #pragma unroll
        for (int u = 0; u < 8; u++) { sc[u][0]=sc[u][1]=sc[u][2]=sc[u][3]=0.f; }
        #pragma unroll
        for (int ks = 0; ks < 4; ks++) {
            uint32_t af[4];
            const int qr = w*16 + lrow;
            ldsm_x4(af, sQ + qr*128 + (((ks*2+lhalf) ^ (qr&7)) << 4));
            #pragma unroll
            for (int nj = 0; nj < 4; nj++) {
                uint32_t bf[4];
                const int kr = nj*16 + lrow;
                ldsm_x4(bf, kb + kr*128 + (((ks*2+lhalf) ^ (kr&7)) << 4));
                uint32_t b2a[2] = { bf[0], bf[2] };
                mma_f16(sc[nj*2+0], af, b2a);
                uint32_t b2b[2] = { bf[1], bf[3] };
                mma_f16(sc[nj*2+1], af, b2b);
            }
        }
        float tm0 = -1e30f, tm1 = -1e30f;
        #pragma unroll
        for (int u = 0; u < 8; u++) {
            sc[u][0]*=SCALE; sc[u][1]*=SCALE; sc[u][2]*=SCALE; sc[u][3]*=SCALE;
            tm0 = fmaxf(tm0, fmaxf(sc[u][0], sc[u][1]));
            tm1 = fmaxf(tm1, fmaxf(sc[u][2], sc[u][3]));
        }
        tm0 = fmaxf(tm0, __shfl_xor_sync(0xffffffffu, tm0, 1));
        tm0 = fmaxf(tm0, __shfl_xor_sync(0xffffffffu, tm0, 2));
        tm1 = fmaxf(tm1, __shfl_xor_sync(0xffffffffu, tm1, 1));
        tm1 = fmaxf(tm1, __shfl_xor_sync(0xffffffffu, tm1, 2));
        const float mn0 = fmaxf(m0, tm0), mn1 = fmaxf(m1, tm1);
        const float cr0 = __expf(m0 - mn0), cr1 = __expf(m1 - mn1);
        float rs0 = 0.f, rs1 = 0.f;
        uint32_t pa[4][4];
        #pragma unroll
        for (int u = 0; u < 8; u++) {
            float p0 = __expf(sc[u][0]-mn0), p1 = __expf(sc[u][1]-mn0);
            float p2 = __expf(sc[u][2]-mn1), p3 = __expf(sc[u][3]-mn1);
            rs0 += p0 + p1; rs1 += p2 + p3;
            __half2 hA = __floats2half2_rn(p0, p1);
            __half2 hB = __floats2half2_rn(p2, p3);
            pa[u>>1][(u&1)*2+0] = *(uint32_t*)&hA;
            pa[u>>1][(u&1)*2+1] = *(uint32_t*)&hB;
        }
        rs0 += __shfl_xor_sync(0xffffffffu, rs0, 1);
        rs0 += __shfl_xor_sync(0xffffffffu, rs0, 2);
        rs1 += __shfl_xor_sync(0xffffffffu, rs1, 1);
        rs1 += __shfl_xor_sync(0xffffffffu, rs1, 2);
        s0 = s0*cr0 + rs0; s1 = s1*cr1 + rs1;
        m0 = mn0; m1 = mn1;
        #pragma unroll
        for (int u = 0; u < 8; u++) {
            oc[u][0]*=cr0; oc[u][1]*=cr0; oc[u][2]*=cr1; oc[u][3]*=cr1;
        }
        #pragma unroll
        for (int ks = 0; ks < 4; ks++) {
            #pragma unroll
            for (int nj = 0; nj < 4; nj++) {
                uint32_t bf[4];
                const int rk = ks*16 + (lane&7) + ((lane>>4)&1)*8;
                const int cn = nj*2 + ((lane>>3)&1);
                ldsm_x4_t(bf, vb + rk*128 + (((cn ^ (rk&7))) << 4));
                uint32_t b2a[2] = { bf[0], bf[2] };
                mma_f16(oc[nj*2+0], pa[ks], b2a);
                uint32_t b2b[2] = { bf[1], bf[3] };
                mma_f16(oc[nj*2+1], pa[ks], b2b);
            }
        }
        __syncthreads();
        if (t + 2 < TILES_PER_CH) {
            uint32_t base = sKV + (t & 1) * 16384;
            int n0 = n0base + (t + 2) * 64;
            for (int i = tid; i < 1024; i += 128) {
                int sel = i >> 9;
                int row = (i >> 3) & 63;
                int c4 = i & 7;
                CP_ASYNC16(base + sel*8192 + row*128 + ((c4 ^ (row&7)) << 4),
                           gYh + ((size_t)(b*SEQ + n0 + row))*QKV_N
                               + (sel ? 2*CDIM : CDIM) + h*HD + c4*8);
            }
        }
        CP_COMMIT();
    }

    const size_t fbase = ((size_t)bh*NCH + ch)*4096;
    const int r0a = w*16 + g, r1a = r0a + 8;
    #pragma unroll
    for (int u = 0; u < 8; u++) {
        int col = u*8 + 2*c;
        *(float2*)&gFp[fbase + (size_t)r0a*64 + col] = make_float2(oc[u][0], oc[u][1]);
        *(float2*)&gFp[fbase + (size_t)r1a*64 + col] = make_float2(oc[u][2], oc[u][3]);
    }
    if (c == 0) {
        gMp[(bh*NCH+ch)*64 + r0a] = m0;
        gMp[(bh*NCH+ch)*64 + r1a] = m1;
        gSp[(bh*NCH+ch)*64 + r0a] = s0;
        gSp[(bh*NCH+ch)*64 + r1a] = s1;
    }
}

// ---------------- combine flash partials + T^T = (W2inv @ F)^T ---------------
__global__ void __launch_bounds__(256) k3_combine()
{
    __shared__ float wgt[NCH*64];
    __shared__ float sF[64*17];
    __shared__ float sW[64*64];
    const int bh = blockIdx.x;
    const int d0 = blockIdx.y * 16;
    const int tid = threadIdx.x;

    if (tid < 64) {
        float M = -1e30f;
        for (int c = 0; c < NCH; c++) M = fmaxf(M, gMp[(bh*NCH + c)*64 + tid]);
        float denom = 0.f;
        for (int c = 0; c < NCH; c++)
            denom += __expf(gMp[(bh*NCH + c)*64 + tid] - M) * gSp[(bh*NCH + c)*64 + tid];
        float invd = 1.f / denom;
        for (int c = 0; c < NCH; c++)
            wgt[c*64 + tid] = __expf(gMp[(bh*NCH + c)*64 + tid] - M) * invd;
    }
    for (int e = tid; e < 4096; e += 256) sW[e] = gW2inv[bh*4096 + e];
    __syncthreads();

    for (int e = tid; e < 1024; e += 256) {
        int l = e >> 4, dd = e & 15;
        float f = 0.f;
        #pragma unroll 4
        for (int c = 0; c < NCH; c++)
            f += gFp[((size_t)bh * NCH + c) * 4096 + l*64 + d0 + dd] * wgt[c*64 + l];
        sF[l*17 + dd] = f;
    }
    __syncthreads();

    const int i0 = (tid >> 4) * 4, j = tid & 15;
    float cc[4] = {0.f, 0.f, 0.f, 0.f};
    #pragma unroll 8
    for (int k = 0; k < 64; k++) {
        float bv = sF[k*17 + j];
        cc[0] += sW[(i0+0)*64 + k] * bv;
        cc[1] += sW[(i0+1)*64 + k] * bv;
        cc[2] += sW[(i0+2)*64 + k] * bv;
        cc[3] += sW[(i0+3)*64 + k] * bv;
    }
    #pragma unroll
    for (int ii = 0; ii < 4; ii++)
        gTth[bh*4096 + (d0 + j)*64 + (i0 + ii)] = __float2half(cc[ii]);
}

// ---------------- kernel_1 @ T (tensor-core) -> gATh, 128 q-rows/block -------
#define K4_SMEM (16384 + 2*8192)

__global__ void __launch_bounds__(256) k4_out()
{
    extern __shared__ __align__(128) char sm4[];
    const uint32_t sQ = smem_u32(sm4);       // 128 rows
    const uint32_t sK = sQ + 16384;          // 64 landmark rows
    const uint32_t sT = sK + 8192;           // 64 hd rows (T^T)

    const int qt = blockIdx.x;
    const int bh = blockIdx.y;
    const int b = bh >> 3, h = bh & 7;
    const int n0 = qt * 128;
    const int tid = threadIdx.x;
    const int lane = tid & 31;
    const int w = tid >> 5;
    const int g = lane >> 2, c = lane & 3;
    const int lrow = lane & 15, lhalf = lane >> 4;

    for (int i = tid; i < 1024; i += 256) {
        int row = i >> 3, c4 = i & 7;
        uint32_t swz = (uint32_t)((c4 ^ (row & 7)) << 4);
        CP_ASYNC16(sQ + row*128 + swz,
                   gYh + ((size_t)(b*SEQ + n0 + row))*QKV_N + h*HD + c4*8);
    }
    for (int i = tid; i < 512; i += 256) {
        int row = i >> 3, c4 = i & 7;
        uint32_t swz = (uint32_t)((c4 ^ (row & 7)) << 4);
        CP_ASYNC16(sK + row*128 + swz,
                   gYh + ((size_t)(b*SEQ + row*LMSTRIDE))*QKV_N + CDIM + h*HD + c4*8);
        CP_ASYNC16(sT + row*128 + swz,
                   gTth + bh*4096 + row*64 + c4*8);
    }
    CP_COMMIT();
    CP_WAIT0();
    __syncthreads();

    float sc[8][4];
    #pragma unroll
    for (int u = 0; u < 8; u++) { sc[u][0]=sc[u][1]=sc[u][2]=sc[u][3]=0.f; }
    #pragma unroll
    for (int ks = 0; ks < 4; ks++) {
        uint32_t af[4];
        const int qr = w*16 + lrow;
        ldsm_x4(af, sQ + qr*128 + (((ks*2+lhalf) ^ (qr&7)) << 4));
        #pragma unroll
        for (int nj = 0; nj < 4; nj++) {
            uint32_t bf[4];
            const int kr = nj*16 + lrow;
            ldsm_x4(bf, sK + kr*128 + (((ks*2+lhalf) ^ (kr&7)) << 4));
            uint32_t b2a[2] = { bf[0], bf[2] };
            mma_f16(sc[nj*2+0], af, b2a);
            uint32_t b2b[2] = { bf[1], bf[3] };
            mma_f16(sc[nj*2+1], af, b2b);
        }
    }
    float tm0 = -1e30f, tm1 = -1e30f;
    #pragma unroll
    for (int u = 0; u < 8; u++) {
        sc[u][0]*=SCALE; sc[u][1]*=SCALE; sc[u][2]*=SCALE; sc[u][3]*=SCALE;
        tm0 = fmaxf(tm0, fmaxf(sc[u][0], sc[u][1]));
        tm1 = fmaxf(tm1, fmaxf(sc[u][2], sc[u][3]));
    }
    tm0 = fmaxf(tm0, __shfl_xor_sync(0xffffffffu, tm0, 1));
    tm0 = fmaxf(tm0, __shfl_xor_sync(0xffffffffu, tm0, 2));
    tm1 = fmaxf(tm1, __shfl_xor_sync(0xffffffffu, tm1, 1));
    tm1 = fmaxf(tm1, __shfl_xor_sync(0xffffffffu, tm1, 2));
    float rs0 = 0.f, rs1 = 0.f;
    uint32_t pa[4][4];
    #pragma unroll
    for (int u = 0; u < 8; u++) {
        float p0 = __expf(sc[u][0]-tm0), p1 = __expf(sc[u][1]-tm0);
        float p2 = __expf(sc[u][2]-tm1), p3 = __expf(sc[u][3]-tm1);
        rs0 += p0 + p1; rs1 += p2 + p3;
        __half2 hA = __floats2half2_rn(p0, p1);
        __half2 hB = __floats2half2_rn(p2, p3);
        pa[u>>1][(u&1)*2+0] = *(uint32_t*)&hA;
        pa[u>>1][(u&1)*2+1] = *(uint32_t*)&hB;
    }
    rs0 += __shfl_xor_sync(0xffffffffu, rs0, 1);
    rs0 += __shfl_xor_sync(0xffffffffu, rs0, 2);
    rs1 += __shfl_xor_sync(0xffffffffu, rs1, 1);
    rs1 += __shfl_xor_sync(0xffffffffu, rs1, 2);
    const float inv0 = 1.f / rs0, inv1 = 1.f / rs1;

    float oc[8][4];
    #pragma unroll
    for (int u = 0; u < 8; u++) { oc[u][0]=oc[u][1]=oc[u][2]=oc[u][3]=0.f; }
    #pragma unroll
    for (int ks = 0; ks < 4; ks++) {
        #pragma unroll
        for (int nj = 0; nj < 4; nj++) {
            uint32_t bf[4];
            const int tr = nj*16 + lrow;
            ldsm_x4(bf, sT + tr*128 + (((ks*2+lhalf) ^ (tr&7)) << 4));
            uint32_t b2a[2] = { bf[0], bf[2] };
            mma_f16(oc[nj*2+0], pa[ks], b2a);
            uint32_t b2b[2] = { bf[1], bf[3] };
            mma_f16(oc[nj*2+1], pa[ks], b2b);
        }
    }

    const int r0a = w*16 + g;
    #pragma unroll
    for (int u = 0; u < 8; u++) {
        int col = u*8 + 2*c;
        __half2 hA = __floats2half2_rn(oc[u][0]*inv0, oc[u][1]*inv0);
        __half2 hB = __floats2half2_rn(oc[u][2]*inv1, oc[u][3]*inv1);
        *(uint32_t*)&gATh[((size_t)(b*SEQ + n0 + r0a))*CDIM + h*HD + col]     = *(uint32_t*)&hA;
        *(uint32_t*)&gATh[((size_t)(b*SEQ + n0 + r0a + 8))*CDIM + h*HD + col] = *(uint32_t*)&hB;
    }
}

// ---------------- launcher ---------------------------------------------------
extern "C" void kernel_launch(void* const* d_in, const int* in_sizes, int n_in,
                              void* d_out, int out_size)
{
    const float* x     = (const float*)d_in[0];
    const float* Wqkv  = (const float*)d_in[1];
    const float* bqkv  = (const float*)d_in[2];
    const float* Wproj = (const float*)d_in[3];
    const float* bproj = (const float*)d_in[4];
    float* out = (float*)d_out;

    cudaFuncSetAttribute(gemm_h, cudaFuncAttributeMaxDynamicSharedMemorySize, SMEM_GEMMH);
    cudaFuncSetAttribute(k3k2,   cudaFuncAttributeMaxDynamicSharedMemorySize, K3K2_SMEM);
    cudaFuncSetAttribute(k4_out, cudaFuncAttributeMaxDynamicSharedMemorySize, K4_SMEM);

    __half *pXh, *pWqkvh, *pWph, *pYh, *pATh;
    cudaGetSymbolAddress((void**)&pXh,    gXh);
    cudaGetSymbolAddress((void**)&pWqkvh, gWqkvh);
    cudaGetSymbolAddress((void**)&pWph,   gWph);
    cudaGetSymbolAddress((void**)&pYh,    gYh);
    cudaGetSymbolAddress((void**)&pATh,   gATh);

    // 0. fp32 -> fp16 conversions
    {
        int nx = BN_TOK * CDIM;
        cvtf2h<<<(nx/8 + 255)/256, 256>>>(x, pXh, nx);
        int nw = QKV_N * CDIM;
        cvtf2h<<<(nw/8 + 255)/256, 256>>>(Wqkv, pWqkvh, nw);
        int np = CDIM * CDIM;
        cvtf2h<<<(np/8 + 255)/256, 256>>>(Wproj, pWph, np);
    }

    // 1. QKV projection -> fp16 gYh
    gemm_h<<<dim3(QKV_N/128, BN_TOK/128), 256, SMEM_GEMMH>>>(pXh, pWqkvh, bqkv, pYh, BN_TOK, QKV_N, CDIM, 1);
    // 2+3. newton inverse AND flash partials concurrently (heterogeneous grid)
    k3k2<<<NBH + FLASH_BLOCKS, 128, K3K2_SMEM>>>();
    k3_combine<<<dim3(NBH, 4), 256>>>();
    // 4. out = softmax(q k_lm^T) @ T -> gATh fp16 (128 q-rows per block)
    k4_out<<<dim3(SEQ/128, NBH), 256, K4_SMEM>>>();
    // 5. projection: out = gATh @ Wproj^T + bproj (fp32 out)
    gemm_h<<<dim3(CDIM/128, BN_TOK/128), 256, SMEM_GEMMH>>>(pATh, pWph, bproj, out, BN_TOK, CDIM, CDIM, 0);
}

// round 12
// speedup vs baseline: 1.1746x; 1.0020x over previous
#include <cuda_runtime.h>
#include <cuda_fp16.h>
#include <cstdint>

// ---------------- problem constants ----------------
#define BDIM     4
#define SEQ      8192
#define CDIM     512
#define NH       8
#define HD       64
#define NLM      64
#define LMSTRIDE 128           // SEQ / NLM
#define BN_TOK   (BDIM*SEQ)    // 32768
#define QKV_N    (3*CDIM)      // 1536
#define NBH      (BDIM*NH)     // 32
#define NCH      16            // key chunks for kernel_3 flash
#define KEYS_PER_CH (SEQ/NCH)  // 512
#define TILES_PER_CH (KEYS_PER_CH/64) // 8
#define SCALE    0.125f        // hd^-0.5

// ---------------- device scratch (no runtime allocs allowed) ----------------
__device__ __half gXh[(size_t)BN_TOK * CDIM];    // x in fp16
__device__ __half gWqkvh[QKV_N * CDIM];          // Wqkv in fp16
__device__ __half gWph[CDIM * CDIM];             // Wproj in fp16
__device__ __half gYh[(size_t)BN_TOK * QKV_N];   // qkv activations fp16
__device__ __half gATh[(size_t)BN_TOK * CDIM];   // attention output fp16
__device__ float  gW2inv[NBH*64*64];
__device__ __half gTth[NBH*64*64];               // (W2inv @ F)^T fp16, [bh][hd][lm]
__device__ float  gFp[(size_t)NBH*NCH*64*64];    // flash partial accumulators
__device__ float  gMp[NBH*NCH*64];
__device__ float  gSp[NBH*NCH*64];

// ---------------- ptx helpers ------------------------------------------------
__device__ __forceinline__ uint32_t smem_u32(const void* p) {
    uint32_t a;
    asm("{ .reg .u64 t; cvta.to.shared.u64 t, %1; cvt.u32.u64 %0, t; }" : "=r"(a) : "l"(p));
    return a;
}
__device__ __forceinline__ void mma_f16(float* d, const uint32_t* a, const uint32_t* b) {
    asm volatile(
        "mma.sync.aligned.m16n8k16.row.col.f32.f16.f16.f32 "
        "{%0,%1,%2,%3}, {%4,%5,%6,%7}, {%8,%9}, {%0,%1,%2,%3};"
        : "+f"(d[0]), "+f"(d[1]), "+f"(d[2]), "+f"(d[3])
        : "r"(a[0]), "r"(a[1]), "r"(a[2]), "r"(a[3]),
          "r"(b[0]), "r"(b[1]));
}
__device__ __forceinline__ void ldsm_x4(uint32_t* r, uint32_t addr) {
    asm volatile("ldmatrix.sync.aligned.m8n8.x4.shared.b16 {%0,%1,%2,%3}, [%4];"
                 : "=r"(r[0]), "=r"(r[1]), "=r"(r[2]), "=r"(r[3]) : "r"(addr));
}
__device__ __forceinline__ void ldsm_x4_t(uint32_t* r, uint32_t addr) {
    asm volatile("ldmatrix.sync.aligned.m8n8.x4.trans.shared.b16 {%0,%1,%2,%3}, [%4];"
                 : "=r"(r[0]), "=r"(r[1]), "=r"(r[2]), "=r"(r[3]) : "r"(addr));
}
#define CP_ASYNC16(dst, src) \
    asm volatile("cp.async.cg.shared.global [%0], [%1], 16;" :: "r"(dst), "l"(src) : "memory")
#define CP_COMMIT() asm volatile("cp.async.commit_group;" ::: "memory")
#define CP_WAIT1()  asm volatile("cp.async.wait_group 1;" ::: "memory")
#define CP_WAIT0()  asm volatile("cp.async.wait_group 0;" ::: "memory")

// ---------------- fused fp32 -> fp16 conversion (x | Wqkv | Wproj) -----------
__global__ void __launch_bounds__(256) cvt_all(const float* __restrict__ x,
                                               const float* __restrict__ wqkv,
                                               const float* __restrict__ wproj)
{
    const int nx = BN_TOK * CDIM;
    const int nw = QKV_N * CDIM;
    const int np = CDIM * CDIM;
    int i = (blockIdx.x * blockDim.x + threadIdx.x) * 8;
    const float* s;
    __half* d;
    if (i < nx)               { s = x + i;              d = gXh + i; }
    else if (i < nx + nw)     { s = wqkv + (i - nx);    d = gWqkvh + (i - nx); }
    else if (i < nx + nw + np){ s = wproj + (i - nx - nw); d = gWph + (i - nx - nw); }
    else return;
    float4 a = *(const float4*)(s);
    float4 b = *(const float4*)(s + 4);
    __half2 h0 = __floats2half2_rn(a.x, a.y);
    __half2 h1 = __floats2half2_rn(a.z, a.w);
    __half2 h2 = __floats2half2_rn(b.x, b.y);
    __half2 h3 = __floats2half2_rn(b.z, b.w);
    uint4 o;
    o.x = *(uint32_t*)&h0; o.y = *(uint32_t*)&h1;
    o.z = *(uint32_t*)&h2; o.w = *(uint32_t*)&h3;
    *(uint4*)d = o;
}

// ---------------- fp16 tensor-core GEMM (round-6 best config) ----------------
#define STG_BYTES 32768          // 16KB A + 16KB B per stage
#define SMEM_GEMMH (3 * STG_BYTES)

__device__ __forceinline__ void stage_copy(uint32_t sbase, const __half* A,
                                           const __half* B, int bm, int bn,
                                           int K, int k0, int tid)
{
    #pragma unroll
    for (int i = 0; i < 4; i++) {
        int lin = tid + i * 256;
        int row = lin >> 3;
        int c   = lin & 7;
        uint32_t dA = sbase + row * 128 + ((c ^ (row & 7)) << 4);
        CP_ASYNC16(dA, A + (size_t)(bm + row) * K + k0 + c * 8);
        uint32_t dB = sbase + 16384 + row * 128 + ((c ^ (row & 7)) << 4);
        CP_ASYNC16(dB, B + (size_t)(bn + row) * K + k0 + c * 8);
    }
}

__global__ void __launch_bounds__(256) gemm_h(const __half* __restrict__ A,
                                              const __half* __restrict__ B,
                                              const float* __restrict__ bias,
                                              void* __restrict__ Cv,
                                              int M, int N, int K, int half_out)
{
    extern __shared__ __align__(128) char smg[];
    const uint32_t sb = smem_u32(smg);

    const int bm = blockIdx.y * 128;
    const int bn = blockIdx.x * 128;
    const int tid  = threadIdx.x;
    const int lane = tid & 31;
    const int warp = tid >> 5;
    const int wm = (warp & 1) * 64;
    const int wn = (warp >> 1) * 32;
    const int g = lane >> 2;
    const int c = lane & 3;
    const int lrow = lane & 15;
    const int lhalf = lane >> 4;

    float acc[4][4][4];
    #pragma unroll
    for (int mi = 0; mi < 4; mi++)
        #pragma unroll
        for (int t = 0; t < 4; t++)
            #pragma unroll
            for (int r = 0; r < 4; r++) acc[mi][t][r] = 0.f;

    const int KT = K >> 6;

    stage_copy(sb, A, B, bm, bn, K, 0, tid);
    CP_COMMIT();
    stage_copy(sb + STG_BYTES, A, B, bm, bn, K, 64, tid);
    CP_COMMIT();

    for (int kt = 0; kt < KT; kt++) {
        CP_WAIT1();
        __syncthreads();

        if (kt + 2 < KT)
            stage_copy(sb + ((kt + 2) % 3) * STG_BYTES, A, B, bm, bn, K, (kt + 2) * 64, tid);
        CP_COMMIT();

        const uint32_t aBase = sb + (kt % 3) * STG_BYTES;
        const uint32_t bBase = aBase + 16384;

        #pragma unroll
        for (int ks = 0; ks < 4; ks++) {
            uint32_t af[4][4], bf[2][4];
            #pragma unroll
            for (int mi = 0; mi < 4; mi++) {
                const int row = wm + mi * 16 + lrow;
                const int ch  = (ks * 2 + lhalf) ^ (row & 7);
                ldsm_x4(af[mi], aBase + row * 128 + (ch << 4));
            }
            #pragma unroll
            for (int nj = 0; nj < 2; nj++) {
                const int row = wn + nj * 16 + lrow;
                const int ch  = (ks * 2 + lhalf) ^ (row & 7);
                ldsm_x4(bf[nj], bBase + row * 128 + (ch << 4));
            }
            #pragma unroll
            for (int mi = 0; mi < 4; mi++) {
                #pragma unroll
                for (int t = 0; t < 4; t++) {
                    const int nj = t >> 1, sub = t & 1;
                    uint32_t b2[2] = { bf[nj][sub], bf[nj][sub + 2] };
                    mma_f16(acc[mi][t], af[mi], b2);
                }
            }
        }
    }

    if (half_out) {
        __half* C = (__half*)Cv;
        #pragma unroll
        for (int mi = 0; mi < 4; mi++) {
            const int row = bm + wm + mi * 16 + g;
            #pragma unroll
            for (int t = 0; t < 4; t++) {
                const int col = bn + wn + (t >> 1) * 16 + (t & 1) * 8 + 2 * c;
                const float b0 = bias[col], b1 = bias[col + 1];
                __half2 o0 = __floats2half2_rn(acc[mi][t][0] + b0, acc[mi][t][1] + b1);
                __half2 o1 = __floats2half2_rn(acc[mi][t][2] + b0, acc[mi][t][3] + b1);
                *(uint32_t*)(C + (size_t)row * N + col)       = *(uint32_t*)&o0;
                *(uint32_t*)(C + (size_t)(row + 8) * N + col) = *(uint32_t*)&o1;
            }
        }
    } else {
        float* C = (float*)Cv;
        #pragma unroll
        for (int mi = 0; mi < 4; mi++) {
            const int row = bm + wm + mi * 16 + g;
            #pragma unroll
            for (int t = 0; t < 4; t++) {
                const int col = bn + wn + (t >> 1) * 16 + (t & 1) * 8 + 2 * c;
                const float b0 = bias[col], b1 = bias[col + 1];
                float2 o0 = make_float2(acc[mi][t][0] + b0, acc[mi][t][1] + b1);
                float2 o1 = make_float2(acc[mi][t][2] + b0, acc[mi][t][3] + b1);
                *(float2*)(C + (size_t)row * N + col)       = o0;
                *(float2*)(C + (size_t)(row + 8) * N + col) = o1;
            }
        }
    }
}

// ---------------- 64x64 fp32 helpers for 128 threads (4x8 tiles) -------------
__device__ __forceinline__ void mm64_nt8(float* C, int ldc,
                                         const float* A, int lda,
                                         const float* B, int ldb,
                                         float scale, int tid)
{
    const int i0 = (tid >> 3) * 4, j0 = (tid & 7) * 8;
    float c[4][8] = {};
    #pragma unroll 4
    for (int d = 0; d < 64; d++) {
        float a[4], bv[8];
        #pragma unroll
        for (int ii = 0; ii < 4; ii++) a[ii]  = A[(i0+ii)*lda + d];
        #pragma unroll
        for (int jj = 0; jj < 8; jj++) bv[jj] = B[(j0+jj)*ldb + d];
        #pragma unroll
        for (int ii = 0; ii < 4; ii++)
            #pragma unroll
            for (int jj = 0; jj < 8; jj++)
                c[ii][jj] += a[ii] * bv[jj];
    }
    #pragma unroll
    for (int ii = 0; ii < 4; ii++)
        #pragma unroll
        for (int jj = 0; jj < 8; jj++)
            C[(i0+ii)*ldc + j0+jj] = scale * c[ii][jj];
}

__device__ __forceinline__ void mm64_nn8(float* C, int ldc,
                                         const float* A, int lda,
                                         const float* B, int ldb, int tid)
{
    const int i0 = (tid >> 3) * 4, j0 = (tid & 7) * 8;
    float c[4][8] = {};
    #pragma unroll 4
    for (int k = 0; k < 64; k++) {
        float a[4], bv[8];
        #pragma unroll
        for (int ii = 0; ii < 4; ii++) a[ii]  = A[(i0+ii)*lda + k];
        #pragma unroll
        for (int jj = 0; jj < 8; jj++) bv[jj] = B[k*ldb + j0+jj];
        #pragma unroll
        for (int ii = 0; ii < 4; ii++)
            #pragma unroll
            for (int jj = 0; jj < 8; jj++)
                c[ii][jj] += a[ii] * bv[jj];
    }
    #pragma unroll
    for (int ii = 0; ii < 4; ii++)
        #pragma unroll
        for (int jj = 0; jj < 8; jj++)
            C[(i0+ii)*ldc + j0+jj] = c[ii][jj];
}

// ---------------- newton branch (128 threads, 3 smem matrices) ----------------
__device__ void k2_newton_body(char* smraw, int bh, int tid)
{
    float* S  = (float*)smraw;
    float* Z  = S  + 4160;
    float* T1 = Z  + 4160;
    __shared__ float red[4];

    const int b = bh >> 3, h = bh & 7;

    for (int e = tid; e < 4096; e += 128) {
        int l = e >> 6, d = e & 63;
        size_t base = (size_t)(b * SEQ + l * LMSTRIDE) * QKV_N + h * HD + d;
        Z [l*65 + d] = __half2float(gYh[base]);
        T1[l*65 + d] = __half2float(gYh[base + CDIM]);
    }
    __syncthreads();

    mm64_nt8(S, 65, Z, 65, T1, 65, SCALE, tid);
    __syncthreads();
    if (tid < 64) {
        float mx = -1e30f;
        for (int j = 0; j < 64; j++) mx = fmaxf(mx, S[tid*65 + j]);
        float s = 0.f;
        for (int j = 0; j < 64; j++) { float p = __expf(S[tid*65+j] - mx); S[tid*65+j] = p; s += p; }
        float inv = 1.f / s;
        for (int j = 0; j < 64; j++) S[tid*65 + j] *= inv;
    }
    __syncthreads();

    float part = 0.f;
    for (int e = tid; e < 4096; e += 128) {
        int i = e >> 6, j = e & 63;
        float v = S[i*65 + j];
        part += v * v;
    }
    #pragma unroll
    for (int o = 16; o; o >>= 1) part += __shfl_xor_sync(0xffffffffu, part, o);
    if ((tid & 31) == 0) red[tid >> 5] = part;
    __syncthreads();
    float fro2 = fmaxf(red[0]+red[1]+red[2]+red[3], 1e-12f);
    float invf = 1.f / fro2;

    for (int e = tid; e < 4096; e += 128) {
        int i = e >> 6, j = e & 63;
        Z[j*65 + i] = S[i*65 + j] * invf;
    }
    __syncthreads();

    const int i0 = (tid >> 3) * 4, j0 = (tid & 7) * 8;
    for (int it = 0; it < 6; it++) {
        mm64_nn8(T1, 65, S, 65, Z, 65, tid);
        __syncthreads();
        float cc[4][8];
        #pragma unroll
        for (int ii = 0; ii < 4; ii++)
            #pragma unroll
            for (int jj = 0; jj < 8; jj++)
                cc[ii][jj] = 2.f * Z[(i0+ii)*65 + j0+jj];
        #pragma unroll 4
        for (int k = 0; k < 64; k++) {
            float a[4], bv[8];
            #pragma unroll
            for (int ii = 0; ii < 4; ii++) a[ii]  = Z[(i0+ii)*65 + k];
            #pragma unroll
            for (int jj = 0; jj < 8; jj++) bv[jj] = T1[k*65 + j0+jj];
            #pragma unroll
            for (int ii = 0; ii < 4; ii++)
                #pragma unroll
                for (int jj = 0; jj < 8; jj++)
                    cc[ii][jj] -= a[ii] * bv[jj];
        }
        __syncthreads();
        #pragma unroll
        for (int ii = 0; ii < 4; ii++)
            #pragma unroll
            for (int jj = 0; jj < 8; jj++)
                Z[(i0+ii)*65 + j0+jj] = cc[ii][jj];
        __syncthreads();
    }

    for (int e = tid; e < 4096; e += 128) {
        int i = e >> 6, j = e & 63;
        gW2inv[bh*4096 + i*64 + j] = Z[i*65 + j];
    }
}

// ---------------- unified flash + newton kernel -------------------------------
#define K3K2_SMEM 49920
#define FLASH_BLOCKS (NBH*NCH)

__global__ void __launch_bounds__(128) k3k2()
{
    extern __shared__ __align__(128) char smu[];
    const int blk = blockIdx.x;
    const int tid = threadIdx.x;

    if (blk < NBH) {
        k2_newton_body(smu, blk, tid);
        return;
    }

    const uint32_t sQ  = smem_u32(smu);
    const uint32_t sKV = sQ + 8192;

    const int fblk = blk - NBH;
    const int bh = fblk & (NBH - 1);
    const int ch = fblk >> 5;
    const int b = bh >> 3, h = bh & 7;
    const int lane = tid & 31;
    const int w = tid >> 5;
    const int g = lane >> 2, c = lane & 3;
    const int lrow = lane & 15, lhalf = lane >> 4;
    const int n0base = ch * KEYS_PER_CH;

    for (int i = tid; i < 512; i += 128) {
        int row = i >> 3, c4 = i & 7;
        CP_ASYNC16(sQ + row*128 + ((c4 ^ (row&7)) << 4),
                   gYh + ((size_t)(b*SEQ + row*LMSTRIDE))*QKV_N + h*HD + c4*8);
    }
    #pragma unroll
    for (int st = 0; st < 2; st++) {
        uint32_t base = sKV + st * 16384;
        for (int i = tid; i < 1024; i += 128) {
            int sel = i >> 9;
            int row = (i >> 3) & 63;
            int c4 = i & 7;
            CP_ASYNC16(base + sel*8192 + row*128 + ((c4 ^ (row&7)) << 4),
                       gYh + ((size_t)(b*SEQ + n0base + st*64 + row))*QKV_N
                           + (sel ? 2*CDIM : CDIM) + h*HD + c4*8);
        }
        CP_COMMIT();
    }

    float m0 = -1e30f, m1 = -1e30f, s0 = 0.f, s1 = 0.f;
    float oc[8][4];
    #pragma unroll
    for (int u = 0; u < 8; u++) { oc[u][0]=oc[u][1]=oc[u][2]=oc[u][3]=0.f; }

    for (int t = 0; t < TILES_PER_CH; t++) {
        CP_WAIT1();
        __syncthreads();
        const uint32_t kb = sKV + (t & 1) * 16384;
        const uint32_t vb = kb + 8192;

        float sc[8][4];
        #pragma unroll
        for (int u = 0; u < 8; u++) { sc[u][0]=sc[u][1]=sc[u][2]=sc[u][3]=0.f; }
        #pragma unroll
        for (int ks = 0; ks < 4; ks++) {
            uint32_t af[4];
            const int qr = w*16 + lrow;
            ldsm_x4(af, sQ + qr*128 + (((ks*2+lhalf) ^ (qr&7)) << 4));
            #pragma unroll
            for (int nj = 0; nj < 4; nj++) {
                uint32_t bf[4];
                const int kr = nj*16 + lrow;
                ldsm_x4(bf, kb + kr*128 + (((ks*2+lhalf) ^ (kr&7)) << 4));
                uint32_t b2a[2] = { bf[0], bf[2] };
                mma_f16(sc[nj*2+0], af, b2a);
                uint32_t b2b[2] = { bf[1], bf[3] };
                mma_f16(sc[nj*2+1], af, b2b);
            }
        }
        float tm0 = -1e30f, tm1 = -1e30f;
        #pragma unroll
        for (int u = 0; u < 8; u++) {
            sc[u][0]*=SCALE; sc[u][1]*=SCALE; sc[u][2]*=SCALE; sc[u][3]*=SCALE;
            tm0 = fmaxf(tm0, fmaxf(sc[u][0], sc[u][1]));
            tm1 = fmaxf(tm1, fmaxf(sc[u][2], sc[u][3]));
        }
        tm0 = fmaxf(tm0, __shfl_xor_sync(0xffffffffu, tm0, 1));
        tm0 = fmaxf(tm0, __shfl_xor_sync(0xffffffffu, tm0, 2));
        tm1 = fmaxf(tm1, __shfl_xor_sync(0xffffffffu, tm1, 1));
        tm1 = fmaxf(tm1, __shfl_xor_sync(0xffffffffu, tm1, 2));
        const float mn0 = fmaxf(m0, tm0), mn1 = fmaxf(m1, tm1);
        const float cr0 = __expf(m0 - mn0), cr1 = __expf(m1 - mn1);
        float rs0 = 0.f, rs1 = 0.f;
        uint32_t pa[4][4];
        #pragma unroll
        for (int u = 0; u < 8; u++) {
            float p0 = __expf(sc[u][0]-mn0), p1 = __expf(sc[u][1]-mn0);
            float p2 = __expf(sc[u][2]-mn1), p3 = __expf(sc[u][3]-mn1);
            rs0 += p0 + p1; rs1 += p2 + p3;
            __half2 hA = __floats2half2_rn(p0, p1);
            __half2 hB = __floats2half2_rn(p2, p3);
            pa[u>>1][(u&1)*2+0] = *(uint32_t*)&hA;
            pa[u>>1][(u&1)*2+1] = *(uint32_t*)&hB;
        }
        rs0 += __shfl_xor_sync(0xffffffffu, rs0, 1);
        rs0 += __shfl_xor_sync(0xffffffffu, rs0, 2);
        rs1 += __shfl_xor_sync(0xffffffffu, rs1, 1);
        rs1 += __shfl_xor_sync(0xffffffffu, rs1, 2);
        s0 = s0*cr0 + rs0; s1 = s1*cr1 + rs1;
        m0 = mn0; m1 = mn1;
        #pragma unroll
        for (int u = 0; u < 8; u++) {
            oc[u][0]*=cr0; oc[u][1]*=cr0; oc[u][2]*=cr1; oc[u][3]*=cr1;
        }
        #pragma unroll
        for (int ks = 0; ks < 4; ks++) {
            #pragma unroll
            for (int nj = 0; nj < 4; nj++) {
                uint32_t bf[4];
                const int rk = ks*16 + (lane&7) + ((lane>>4)&1)*8;
                const int cn = nj*2 + ((lane>>3)&1);
                ldsm_x4_t(bf, vb + rk*128 + (((cn ^ (rk&7))) << 4));
                uint32_t b2a[2] = { bf[0], bf[2] };
                mma_f16(oc[nj*2+0], pa[ks], b2a);
                uint32_t b2b[2] = { bf[1], bf[3] };
                mma_f16(oc[nj*2+1], pa[ks], b2b);
            }
        }
        __syncthreads();
        if (t + 2 < TILES_PER_CH) {
            uint32_t base = sKV + (t & 1) * 16384;
            int n0 = n0base + (t + 2) * 64;
            for (int i = tid; i < 1024; i += 128) {
                int sel = i >> 9;
                int row = (i >> 3) & 63;
                int c4 = i & 7;
                CP_ASYNC16(base + sel*8192 + row*128 + ((c4 ^ (row&7)) << 4),
                           gYh + ((size_t)(b*SEQ + n0 + row))*QKV_N
                               + (sel ? 2*CDIM : CDIM) + h*HD + c4*8);
            }
        }
        CP_COMMIT();
    }

    const size_t fbase = ((size_t)bh*NCH + ch)*4096;
    const int r0a = w*16 + g, r1a = r0a + 8;
    #pragma unroll
    for (int u = 0; u < 8; u++) {
        int col = u*8 + 2*c;
        *(float2*)&gFp[fbase + (size_t)r0a*64 + col] = make_float2(oc[u][0], oc[u][1]);
        *(float2*)&gFp[fbase + (size_t)r1a*64 + col] = make_float2(oc[u][2], oc[u][3]);
    }
    if (c == 0) {
        gMp[(bh*NCH+ch)*64 + r0a] = m0;
        gMp[(bh*NCH+ch)*64 + r1a] = m1;
        gSp[(bh*NCH+ch)*64 + r0a] = s0;
        gSp[(bh*NCH+ch)*64 + r1a] = s1;
    }
}

// ---------------- combine flash partials + T^T = (W2inv @ F)^T ---------------
__global__ void __launch_bounds__(256) k3_combine()
{
    __shared__ float wgt[NCH*64];
    __shared__ float sF[64*17];
    __shared__ float sW[64*64];
    const int bh = blockIdx.x;
    const int d0 = blockIdx.y * 16;
    const int tid = threadIdx.x;

    if (tid < 64) {
        float M = -1e30f;
        for (int c = 0; c < NCH; c++) M = fmaxf(M, gMp[(bh*NCH + c)*64 + tid]);
        float denom = 0.f;
        for (int c = 0; c < NCH; c++)
            denom += __expf(gMp[(bh*NCH + c)*64 + tid] - M) * gSp[(bh*NCH + c)*64 + tid];
        float invd = 1.f / denom;
        for (int c = 0; c < NCH; c++)
            wgt[c*64 + tid] = __expf(gMp[(bh*NCH + c)*64 + tid] - M) * invd;
    }
    for (int e = tid; e < 4096; e += 256) sW[e] = gW2inv[bh*4096 + e];
    __syncthreads();

    for (int e = tid; e < 1024; e += 256) {
        int l = e >> 4, dd = e & 15;
        float f = 0.f;
        #pragma unroll 4
        for (int c = 0; c < NCH; c++)
            f += gFp[((size_t)bh * NCH + c) * 4096 + l*64 + d0 + dd] * wgt[c*64 + l];
        sF[l*17 + dd] = f;
    }
    __syncthreads();

    const int i0 = (tid >> 4) * 4, j = tid & 15;
    float cc[4] = {0.f, 0.f, 0.f, 0.f};
    #pragma unroll 8
    for (int k = 0; k < 64; k++) {
        float bv = sF[k*17 + j];
        cc[0] += sW[(i0+0)*64 + k] * bv;
        cc[1] += sW[(i0+1)*64 + k] * bv;
        cc[2] += sW[(i0+2)*64 + k] * bv;
        cc[3] += sW[(i0+3)*64 + k] * bv;
    }
    #pragma unroll
    for (int ii = 0; ii < 4; ii++)
        gTth[bh*4096 + (d0 + j)*64 + (i0 + ii)] = __float2half(cc[ii]);
}

// ---------------- kernel_1 @ T -> gATh : K/T resident, 4 q-tiles per block ---
#define K4_TILES 4
#define K4_SMEM (8192 + 8192 + 2*16384)   // K + T + double-buffered Q

__global__ void __launch_bounds__(256) k4_out()
{
    extern __shared__ __align__(128) char sm4[];
    const uint32_t sK  = smem_u32(sm4);
    const uint32_t sT  = sK + 8192;
    const uint32_t sQb = sT + 8192;

    const int bh = blockIdx.y;
    const int b = bh >> 3, h = bh & 7;
    const int qt0 = blockIdx.x * K4_TILES;
    const int tid = threadIdx.x;
    const int lane = tid & 31;
    const int w = tid >> 5;
    const int g = lane >> 2, c = lane & 3;
    const int lrow = lane & 15, lhalf = lane >> 4;

    // K_lm + T (once per block)
    for (int i = tid; i < 512; i += 256) {
        int row = i >> 3, c4 = i & 7;
        uint32_t swz = (uint32_t)((c4 ^ (row & 7)) << 4);
        CP_ASYNC16(sK + row*128 + swz,
                   gYh + ((size_t)(b*SEQ + row*LMSTRIDE))*QKV_N + CDIM + h*HD + c4*8);
        CP_ASYNC16(sT + row*128 + swz,
                   gTth + bh*4096 + row*64 + c4*8);
    }
    // Q tile 0
    for (int i = tid; i < 1024; i += 256) {
        int row = i >> 3, c4 = i & 7;
        uint32_t swz = (uint32_t)((c4 ^ (row & 7)) << 4);
        CP_ASYNC16(sQb + row*128 + swz,
                   gYh + ((size_t)(b*SEQ + qt0*128 + row))*QKV_N + h*HD + c4*8);
    }
    CP_COMMIT();

    for (int t = 0; t < K4_TILES; t++) {
        CP_WAIT0();
        __syncthreads();
        const uint32_t sQ = sQb + (t & 1) * 16384;
        const int n0 = (qt0 + t) * 128;

        // prefetch next Q tile into the other buffer
        if (t + 1 < K4_TILES) {
            const uint32_t nQ = sQb + ((t + 1) & 1) * 16384;
            const int nn0 = (qt0 + t + 1) * 128;
            for (int i = tid; i < 1024; i += 256) {
                int row = i >> 3, c4 = i & 7;
                uint32_t swz = (uint32_t)((c4 ^ (row & 7)) << 4);
                CP_ASYNC16(nQ + row*128 + swz,
                           gYh + ((size_t)(b*SEQ + nn0 + row))*QKV_N + h*HD + c4*8);
            }
        }
        CP_COMMIT();

        // S = Q @ K_lm^T ; warp w -> q rows [w*16, w*16+16)
        float sc[8][4];
        #pragma unroll
        for (int u = 0; u < 8; u++) { sc[u][0]=sc[u][1]=sc[u][2]=sc[u][3]=0.f; }
        #pragma unroll
        for (int ks = 0; ks < 4; ks++) {
            uint32_t af[4];
            const int qr = w*16 + lrow;
            ldsm_x4(af, sQ + qr*128 + (((ks*2+lhalf) ^ (qr&7)) << 4));
            #pragma unroll
            for (int nj = 0; nj < 4; nj++) {
                uint32_t bf[4];
                const int kr = nj*16 + lrow;
                ldsm_x4(bf, sK + kr*128 + (((ks*2+lhalf) ^ (kr&7)) << 4));
                uint32_t b2a[2] = { bf[0], bf[2] };
                mma_f16(sc[nj*2+0], af, b2a);
                uint32_t b2b[2] = { bf[1], bf[3] };
                mma_f16(sc[nj*2+1], af, b2b);
            }
        }
        float tm0 = -1e30f, tm1 = -1e30f;
        #pragma unroll
        for (int u = 0; u < 8; u++) {
            sc[u][0]*=SCALE; sc[u][1]*=SCALE; sc[u][2]*=SCALE; sc[u][3]*=SCALE;
            tm0 = fmaxf(tm0, fmaxf(sc[u][0], sc[u][1]));
            tm1 = fmaxf(tm1, fmaxf(sc[u][2], sc[u][3]));
        }
        tm0 = fmaxf(tm0, __shfl_xor_sync(0xffffffffu, tm0, 1));
        tm0 = fmaxf(tm0, __shfl_xor_sync(0xffffffffu, tm0, 2));
        tm1 = fmaxf(tm1, __shfl_xor_sync(0xffffffffu, tm1, 1));
        tm1 = fmaxf(tm1, __shfl_xor_sync(0xffffffffu, tm1, 2));
        float rs0 = 0.f, rs1 = 0.f;
        uint32_t pa[4][4];
        #pragma unroll
        for (int u = 0; u < 8; u++) {
            float p0 = __expf(sc[u][0]-tm0), p1 = __expf(sc[u][1]-tm0);
            float p2 = __expf(sc[u][2]-tm1), p3 = __expf(sc[u][3]-tm1);
            rs0 += p0 + p1; rs1 += p2 + p3;
            __half2 hA = __floats2half2_rn(p0, p1);
            __half2 hB = __floats2half2_rn(p2, p3);
            pa[u>>1][(u&1)*2+0] = *(uint32_t*)&hA;
            pa[u>>1][(u&1)*2+1] = *(uint32_t*)&hB;
        }
        rs0 += __shfl_xor_sync(0xffffffffu, rs0, 1);
        rs0 += __shfl_xor_sync(0xffffffffu, rs0, 2);
        rs1 += __shfl_xor_sync(0xffffffffu, rs1, 1);
        rs1 += __shfl_xor_sync(0xffffffffu, rs1, 2);
        const float inv0 = 1.f / rs0, inv1 = 1.f / rs1;

        float oc[8][4];
        #pragma unroll
        for (int u = 0; u < 8; u++) { oc[u][0]=oc[u][1]=oc[u][2]=oc[u][3]=0.f; }
        #pragma unroll
        for (int ks = 0; ks < 4; ks++) {
            #pragma unroll
            for (int nj = 0; nj < 4; nj++) {
                uint32_t bf[4];
                const int tr = nj*16 + lrow;
                ldsm_x4(bf, sT + tr*128 + (((ks*2+lhalf) ^ (tr&7)) << 4));
                uint32_t b2a[2] = { bf[0], bf[2] };
                mma_f16(oc[nj*2+0], pa[ks], b2a);
                uint32_t b2b[2] = { bf[1], bf[3] };
                mma_f16(oc[nj*2+1], pa[ks], b2b);
            }
        }

        const int r0a = w*16 + g;
        #pragma unroll
        for (int u = 0; u < 8; u++) {
            int col = u*8 + 2*c;
            __half2 hA = __floats2half2_rn(oc[u][0]*inv0, oc[u][1]*inv0);
            __half2 hB = __floats2half2_rn(oc[u][2]*inv1, oc[u][3]*inv1);
            *(uint32_t*)&gATh[((size_t)(b*SEQ + n0 + r0a))*CDIM + h*HD + col]     = *(uint32_t*)&hA;
            *(uint32_t*)&gATh[((size_t)(b*SEQ + n0 + r0a + 8))*CDIM + h*HD + col] = *(uint32_t*)&hB;
        }
        __syncthreads();   // all reads of sQ done before next prefetch overwrite cycle
    }
}

// ---------------- launcher ---------------------------------------------------
extern "C" void kernel_launch(void* const* d_in, const int* in_sizes, int n_in,
                              void* d_out, int out_size)
{
    const float* x     = (const float*)d_in[0];
    const float* Wqkv  = (const float*)d_in[1];
    const float* bqkv  = (const float*)d_in[2];
    const float* Wproj = (const float*)d_in[3];
    const float* bproj = (const float*)d_in[4];
    float* out = (float*)d_out;

    cudaFuncSetAttribute(gemm_h, cudaFuncAttributeMaxDynamicSharedMemorySize, SMEM_GEMMH);
    cudaFuncSetAttribute(k3k2,   cudaFuncAttributeMaxDynamicSharedMemorySize, K3K2_SMEM);
    cudaFuncSetAttribute(k4_out, cudaFuncAttributeMaxDynamicSharedMemorySize, K4_SMEM);

    __half *pXh, *pWqkvh, *pWph, *pYh, *pATh;
    cudaGetSymbolAddress((void**)&pXh,    gXh);
    cudaGetSymbolAddress((void**)&pWqkvh, gWqkvh);
    cudaGetSymbolAddress((void**)&pWph,   gWph);
    cudaGetSymbolAddress((void**)&pYh,    gYh);
    cudaGetSymbolAddress((void**)&pATh,   gATh);

    // 0. fused fp32 -> fp16 conversion (x | Wqkv | Wproj)
    {
        int ntot = BN_TOK * CDIM + QKV_N * CDIM + CDIM * CDIM;
        cvt_all<<<(ntot/8 + 255)/256, 256>>>(x, Wqkv, Wproj);
    }

    // 1. QKV projection -> fp16 gYh
    gemm_h<<<dim3(QKV_N/128, BN_TOK/128), 256, SMEM_GEMMH>>>(pXh, pWqkvh, bqkv, pYh, BN_TOK, QKV_N, CDIM, 1);
    // 2+3. newton inverse AND flash partials concurrently (heterogeneous grid)
    k3k2<<<NBH + FLASH_BLOCKS, 128, K3K2_SMEM>>>();
    k3_combine<<<dim3(NBH, 4), 256>>>();
    // 4. out = softmax(q k_lm^T) @ T -> gATh fp16 (4 q-tiles/block, K/T resident)
    k4_out<<<dim3(SEQ/128/K4_TILES, NBH), 256, K4_SMEM>>>();
    // 5. projection: out = gATh @ Wproj^T + bproj (fp32 out)
    gemm_h<<<dim3(CDIM/128, BN_TOK/128), 256, SMEM_GEMMH>>>(pATh, pWph, bproj, out, BN_TOK, CDIM, CDIM, 0);
}

// round 13
// speedup vs baseline: 1.1799x; 1.0045x over previous
#include <cuda_runtime.h>
#include <cuda_fp16.h>
#include <cstdint>

// ---------------- problem constants ----------------
#define BDIM     4
#define SEQ      8192
#define CDIM     512
#define NH       8
#define HD       64
#define NLM      64
#define LMSTRIDE 128           // SEQ / NLM
#define BN_TOK   (BDIM*SEQ)    // 32768
#define QKV_N    (3*CDIM)      // 1536
#define NBH      (BDIM*NH)     // 32
#define NCH      16            // key chunks for kernel_3 flash
#define KEYS_PER_CH (SEQ/NCH)  // 512
#define TILES_PER_CH (KEYS_PER_CH/64) // 8
#define SCALE    0.125f        // hd^-0.5

// ---------------- device scratch (no runtime allocs allowed) ----------------
__device__ __half gXh[(size_t)BN_TOK * CDIM];    // x in fp16
__device__ __half gWqkvh[QKV_N * CDIM];          // Wqkv in fp16
__device__ __half gWph[CDIM * CDIM];             // Wproj in fp16
__device__ __half gYh[(size_t)BN_TOK * QKV_N];   // qkv activations fp16
__device__ __half gATh[(size_t)BN_TOK * CDIM];   // attention output fp16
__device__ float  gW2inv[NBH*64*64];
__device__ __half gTth[NBH*64*64];               // (W2inv @ F)^T fp16, [bh][hd][lm]
__device__ float  gFp[(size_t)NBH*NCH*64*64];    // flash partial accumulators
__device__ float  gMp[NBH*NCH*64];
__device__ float  gSp[NBH*NCH*64];

// ---------------- ptx helpers ------------------------------------------------
__device__ __forceinline__ uint32_t smem_u32(const void* p) {
    uint32_t a;
    asm("{ .reg .u64 t; cvta.to.shared.u64 t, %1; cvt.u32.u64 %0, t; }" : "=r"(a) : "l"(p));
    return a;
}
__device__ __forceinline__ void mma_f16(float* d, const uint32_t* a, const uint32_t* b) {
    asm volatile(
        "mma.sync.aligned.m16n8k16.row.col.f32.f16.f16.f32 "
        "{%0,%1,%2,%3}, {%4,%5,%6,%7}, {%8,%9}, {%0,%1,%2,%3};"
        : "+f"(d[0]), "+f"(d[1]), "+f"(d[2]), "+f"(d[3])
        : "r"(a[0]), "r"(a[1]), "r"(a[2]), "r"(a[3]),
          "r"(b[0]), "r"(b[1]));
}
__device__ __forceinline__ void ldsm_x4(uint32_t* r, uint32_t addr) {
    asm volatile("ldmatrix.sync.aligned.m8n8.x4.shared.b16 {%0,%1,%2,%3}, [%4];"
                 : "=r"(r[0]), "=r"(r[1]), "=r"(r[2]), "=r"(r[3]) : "r"(addr));
}
__device__ __forceinline__ void ldsm_x4_t(uint32_t* r, uint32_t addr) {
    asm volatile("ldmatrix.sync.aligned.m8n8.x4.trans.shared.b16 {%0,%1,%2,%3}, [%4];"
                 : "=r"(r[0]), "=r"(r[1]), "=r"(r[2]), "=r"(r[3]) : "r"(addr));
}
#define CP_ASYNC16(dst, src) \
    asm volatile("cp.async.cg.shared.global [%0], [%1], 16;" :: "r"(dst), "l"(src) : "memory")
#define CP_COMMIT() asm volatile("cp.async.commit_group;" ::: "memory")
#define CP_WAIT1()  asm volatile("cp.async.wait_group 1;" ::: "memory")
#define CP_WAIT0()  asm volatile("cp.async.wait_group 0;" ::: "memory")

// ---------------- fused fp32 -> fp16 conversion (x | Wqkv | Wproj) -----------
__global__ void __launch_bounds__(256) cvt_all(const float* __restrict__ x,
                                               const float* __restrict__ wqkv,
                                               const float* __restrict__ wproj)
{
    const int nx = BN_TOK * CDIM;
    const int nw = QKV_N * CDIM;
    const int np = CDIM * CDIM;
    int i = (blockIdx.x * blockDim.x + threadIdx.x) * 8;
    const float* s;
    __half* d;
    if (i < nx)               { s = x + i;              d = gXh + i; }
    else if (i < nx + nw)     { s = wqkv + (i - nx);    d = gWqkvh + (i - nx); }
    else if (i < nx + nw + np){ s = wproj + (i - nx - nw); d = gWph + (i - nx - nw); }
    else return;
    float4 a = *(const float4*)(s);
    float4 b = *(const float4*)(s + 4);
    __half2 h0 = __floats2half2_rn(a.x, a.y);
    __half2 h1 = __floats2half2_rn(a.z, a.w);
    __half2 h2 = __floats2half2_rn(b.x, b.y);
    __half2 h3 = __floats2half2_rn(b.z, b.w);
    uint4 o;
    o.x = *(uint32_t*)&h0; o.y = *(uint32_t*)&h1;
    o.z = *(uint32_t*)&h2; o.w = *(uint32_t*)&h3;
    *(uint4*)d = o;
}

// ---------------- fp16 tensor-core GEMM (round-6 best config) ----------------
#define STG_BYTES 32768          // 16KB A + 16KB B per stage
#define SMEM_GEMMH (3 * STG_BYTES)

__device__ __forceinline__ void stage_copy(uint32_t sbase, const __half* A,
                                           const __half* B, int bm, int bn,
                                           int K, int k0, int tid)
{
    #pragma unroll
    for (int i = 0; i < 4; i++) {
        int lin = tid + i * 256;
        int row = lin >> 3;
        int c   = lin & 7;
        uint32_t dA = sbase + row * 128 + ((c ^ (row & 7)) << 4);
        CP_ASYNC16(dA, A + (size_t)(bm + row) * K + k0 + c * 8);
        uint32_t dB = sbase + 16384 + row * 128 + ((c ^ (row & 7)) << 4);
        CP_ASYNC16(dB, B + (size_t)(bn + row) * K + k0 + c * 8);
    }
}

__global__ void __launch_bounds__(256) gemm_h(const __half* __restrict__ A,
                                              const __half* __restrict__ B,
                                              const float* __restrict__ bias,
                                              void* __restrict__ Cv,
                                              int M, int N, int K, int half_out)
{
    extern __shared__ __align__(128) char smg[];
    const uint32_t sb = smem_u32(smg);

    const int bm = blockIdx.y * 128;
    const int bn = blockIdx.x * 128;
    const int tid  = threadIdx.x;
    const int lane = tid & 31;
    const int warp = tid >> 5;
    const int wm = (warp & 1) * 64;
    const int wn = (warp >> 1) * 32;
    const int g = lane >> 2;
    const int c = lane & 3;
    const int lrow = lane & 15;
    const int lhalf = lane >> 4;

    float acc[4][4][4];
    #pragma unroll
    for (int mi = 0; mi < 4; mi++)
        #pragma unroll
        for (int t = 0; t < 4; t++)
            #pragma unroll
            for (int r = 0; r < 4; r++) acc[mi][t][r] = 0.f;

    const int KT = K >> 6;

    stage_copy(sb, A, B, bm, bn, K, 0, tid);
    CP_COMMIT();
    stage_copy(sb + STG_BYTES, A, B, bm, bn, K, 64, tid);
    CP_COMMIT();

    for (int kt = 0; kt < KT; kt++) {
        CP_WAIT1();
        __syncthreads();

        if (kt + 2 < KT)
            stage_copy(sb + ((kt + 2) % 3) * STG_BYTES, A, B, bm, bn, K, (kt + 2) * 64, tid);
        CP_COMMIT();

        const uint32_t aBase = sb + (kt % 3) * STG_BYTES;
        const uint32_t bBase = aBase + 16384;

        #pragma unroll
        for (int ks = 0; ks < 4; ks++) {
            uint32_t af[4][4], bf[2][4];
            #pragma unroll
            for (int mi = 0; mi < 4; mi++) {
                const int row = wm + mi * 16 + lrow;
                const int ch  = (ks * 2 + lhalf) ^ (row & 7);
                ldsm_x4(af[mi], aBase + row * 128 + (ch << 4));
            }
            #pragma unroll
            for (int nj = 0; nj < 2; nj++) {
                const int row = wn + nj * 16 + lrow;
                const int ch  = (ks * 2 + lhalf) ^ (row & 7);
                ldsm_x4(bf[nj], bBase + row * 128 + (ch << 4));
            }
            #pragma unroll
            for (int mi = 0; mi < 4; mi++) {
                #pragma unroll
                for (int t = 0; t < 4; t++) {
                    const int nj = t >> 1, sub = t & 1;
                    uint32_t b2[2] = { bf[nj][sub], bf[nj][sub + 2] };
                    mma_f16(acc[mi][t], af[mi], b2);
                }
            }
        }
    }

    if (half_out) {
        __half* C = (__half*)Cv;
        #pragma unroll
        for (int mi = 0; mi < 4; mi++) {
            const int row = bm + wm + mi * 16 + g;
            #pragma unroll
            for (int t = 0; t < 4; t++) {
                const int col = bn + wn + (t >> 1) * 16 + (t & 1) * 8 + 2 * c;
                const float b0 = bias[col], b1 = bias[col + 1];
                __half2 o0 = __floats2half2_rn(acc[mi][t][0] + b0, acc[mi][t][1] + b1);
                __half2 o1 = __floats2half2_rn(acc[mi][t][2] + b0, acc[mi][t][3] + b1);
                *(uint32_t*)(C + (size_t)row * N + col)       = *(uint32_t*)&o0;
                *(uint32_t*)(C + (size_t)(row + 8) * N + col) = *(uint32_t*)&o1;
            }
        }
    } else {
        float* C = (float*)Cv;
        #pragma unroll
        for (int mi = 0; mi < 4; mi++) {
            const int row = bm + wm + mi * 16 + g;
            #pragma unroll
            for (int t = 0; t < 4; t++) {
                const int col = bn + wn + (t >> 1) * 16 + (t & 1) * 8 + 2 * c;
                const float b0 = bias[col], b1 = bias[col + 1];
                float2 o0 = make_float2(acc[mi][t][0] + b0, acc[mi][t][1] + b1);
                float2 o1 = make_float2(acc[mi][t][2] + b0, acc[mi][t][3] + b1);
                *(float2*)(C + (size_t)row * N + col)       = o0;
                *(float2*)(C + (size_t)(row + 8) * N + col) = o1;
            }
        }
    }
}

// ---------------- 64x64 fp32 helpers for 128 threads (4x8 tiles) -------------
__device__ __forceinline__ void mm64_nt8(float* C, int ldc,
                                         const float* A, int lda,
                                         const float* B, int ldb,
                                         float scale, int tid)
{
    const int i0 = (tid >> 3) * 4, j0 = (tid & 7) * 8;
    float c[4][8] = {};
    #pragma unroll 4
    for (int d = 0; d < 64; d++) {
        float a[4], bv[8];
        #pragma unroll
        for (int ii = 0; ii < 4; ii++) a[ii]  = A[(i0+ii)*lda + d];
        #pragma unroll
        for (int jj = 0; jj < 8; jj++) bv[jj] = B[(j0+jj)*ldb + d];
        #pragma unroll
        for (int ii = 0; ii < 4; ii++)
            #pragma unroll
            for (int jj = 0; jj < 8; jj++)
                c[ii][jj] += a[ii] * bv[jj];
    }
    #pragma unroll
    for (int ii = 0; ii < 4; ii++)
        #pragma unroll
        for (int jj = 0; jj < 8; jj++)
            C[(i0+ii)*ldc + j0+jj] = scale * c[ii][jj];
}

__device__ __forceinline__ void mm64_nn8(float* C, int ldc,
                                         const float* A, int lda,
                                         const float* B, int ldb, int tid)
{
    const int i0 = (tid >> 3) * 4, j0 = (tid & 7) * 8;
    float c[4][8] = {};
    #pragma unroll 4
    for (int k = 0; k < 64; k++) {
        float a[4], bv[8];
        #pragma unroll
        for (int ii = 0; ii < 4; ii++) a[ii]  = A[(i0+ii)*lda + k];
        #pragma unroll
        for (int jj = 0; jj < 8; jj++) bv[jj] = B[k*ldb + j0+jj];
        #pragma unroll
        for (int ii = 0; ii < 4; ii++)
            #pragma unroll
            for (int jj = 0; jj < 8; jj++)
                c[ii][jj] += a[ii] * bv[jj];
    }
    #pragma unroll
    for (int ii = 0; ii < 4; ii++)
        #pragma unroll
        for (int jj = 0; jj < 8; jj++)
            C[(i0+ii)*ldc + j0+jj] = c[ii][jj];
}

// ---------------- newton branch (128 threads, 3 smem matrices) ----------------
__device__ void k2_newton_body(char* smraw, int bh, int tid)
{
    float* S  = (float*)smraw;
    float* Z  = S  + 4160;
    float* T1 = Z  + 4160;
    __shared__ float red[4];

    const int b = bh >> 3, h = bh & 7;

    for (int e = tid; e < 4096; e += 128) {
        int l = e >> 6, d = e & 63;
        size_t base = (size_t)(b * SEQ + l * LMSTRIDE) * QKV_N + h * HD + d;
        Z [l*65 + d] = __half2float(gYh[base]);
        T1[l*65 + d] = __half2float(gYh[base + CDIM]);
    }
    __syncthreads();

    mm64_nt8(S, 65, Z, 65, T1, 65, SCALE, tid);
    __syncthreads();
    if (tid < 64) {
        float mx = -1e30f;
        for (int j = 0; j < 64; j++) mx = fmaxf(mx, S[tid*65 + j]);
        float s = 0.f;
        for (int j = 0; j < 64; j++) { float p = __expf(S[tid*65+j] - mx); S[tid*65+j] = p; s += p; }
        float inv = 1.f / s;
        for (int j = 0; j < 64; j++) S[tid*65 + j] *= inv;
    }
    __syncthreads();

    float part = 0.f;
    for (int e = tid; e < 4096; e += 128) {
        int i = e >> 6, j = e & 63;
        float v = S[i*65 + j];
        part += v * v;
    }
    #pragma unroll
    for (int o = 16; o; o >>= 1) part += __shfl_xor_sync(0xffffffffu, part, o);
    if ((tid & 31) == 0) red[tid >> 5] = part;
    __syncthreads();
    float fro2 = fmaxf(red[0]+red[1]+red[2]+red[3], 1e-12f);
    float invf = 1.f / fro2;

    for (int e = tid; e < 4096; e += 128) {
        int i = e >> 6, j = e & 63;
        Z[j*65 + i] = S[i*65 + j] * invf;
    }
    __syncthreads();

    const int i0 = (tid >> 3) * 4, j0 = (tid & 7) * 8;
    for (int it = 0; it < 6; it++) {
        mm64_nn8(T1, 65, S, 65, Z, 65, tid);
        __syncthreads();
        float cc[4][8];
        #pragma unroll
        for (int ii = 0; ii < 4; ii++)
            #pragma unroll
            for (int jj = 0; jj < 8; jj++)
                cc[ii][jj] = 2.f * Z[(i0+ii)*65 + j0+jj];
        #pragma unroll 4
        for (int k = 0; k < 64; k++) {
            float a[4], bv[8];
            #pragma unroll
            for (int ii = 0; ii < 4; ii++) a[ii]  = Z[(i0+ii)*65 + k];
            #pragma unroll
            for (int jj = 0; jj < 8; jj++) bv[jj] = T1[k*65 + j0+jj];
            #pragma unroll
            for (int ii = 0; ii < 4; ii++)
                #pragma unroll
                for (int jj = 0; jj < 8; jj++)
                    cc[ii][jj] -= a[ii] * bv[jj];
        }
        __syncthreads();
        #pragma unroll
        for (int ii = 0; ii < 4; ii++)
            #pragma unroll
            for (int jj = 0; jj < 8; jj++)
                Z[(i0+ii)*65 + j0+jj] = cc[ii][jj];
        __syncthreads();
    }

    for (int e = tid; e < 4096; e += 128) {
        int i = e >> 6, j = e & 63;
        gW2inv[bh*4096 + i*64 + j] = Z[i*65 + j];
    }
}

// ---------------- unified flash + newton kernel -------------------------------
#define K3K2_SMEM 49920
#define FLASH_BLOCKS (NBH*NCH)

__global__ void __launch_bounds__(128) k3k2()
{
    extern __shared__ __align__(128) char smu[];
    const int blk = blockIdx.x;
    const int tid = threadIdx.x;

    if (blk < NBH) {
        k2_newton_body(smu, blk, tid);
        return;
    }

    const uint32_t sQ  = smem_u32(smu);
    const uint32_t sKV = sQ + 8192;

    const int fblk = blk - NBH;
    const int bh = fblk & (NBH - 1);
    const int ch = fblk >> 5;
    const int b = bh >> 3, h = bh & 7;
    const int lane = tid & 31;
    const int w = tid >> 5;
    const int g = lane >> 2, c = lane & 3;
    const int lrow = lane & 15, lhalf = lane >> 4;
    const int n0base = ch * KEYS_PER_CH;

    for (int i = tid; i < 512; i += 128) {
        int row = i >> 3, c4 = i & 7;
        CP_ASYNC16(sQ + row*128 + ((c4 ^ (row&7)) << 4),
                   gYh + ((size_t)(b*SEQ + row*LMSTRIDE))*QKV_N + h*HD + c4*8);
    }
    #pragma unroll
    for (int st = 0; st < 2; st++) {
        uint32_t base = sKV + st * 16384;
        for (int i = tid; i < 1024; i += 128) {
            int sel = i >> 9;
            int row = (i >> 3) & 63;
            int c4 = i & 7;
            CP_ASYNC16(base + sel*8192 + row*128 + ((c4 ^ (row&7)) << 4),
                       gYh + ((size_t)(b*SEQ + n0base + st*64 + row))*QKV_N
                           + (sel ? 2*CDIM : CDIM) + h*HD + c4*8);
        }
        CP_COMMIT();
    }

    float m0 = -1e30f, m1 = -1e30f, s0 = 0.f, s1 = 0.f;
    float oc[8][4];
    #pragma unroll
    for (int u = 0; u < 8; u++) { oc[u][0]=oc[u][1]=oc[u][2]=oc[u][3]=0.f; }

    for (int t = 0; t < TILES_PER_CH; t++) {
        CP_WAIT1();
        __syncthreads();
        const uint32_t kb = sKV + (t & 1) * 16384;
        const uint32_t vb = kb + 8192;

        float sc[8][4];
        #pragma unroll
        for (int u = 0; u < 8; u++) { sc[u][0]=sc[u][1]=sc[u][2]=sc[u][3]=0.f; }
        #pragma unroll
        for (int ks = 0; ks < 4; ks++) {
            uint32_t af[4];
            const int qr = w*16 + lrow;
            ldsm_x4(af, sQ + qr*128 + (((ks*2+lhalf) ^ (qr&7)) << 4));
            #pragma unroll
            for (int nj = 0; nj < 4; nj++) {
                uint32_t bf[4];
                const int kr = nj*16 + lrow;
                ldsm_x4(bf, kb + kr*128 + (((ks*2+lhalf) ^ (kr&7)) << 4));
                uint32_t b2a[2] = { bf[0], bf[2] };
                mma_f16(sc[nj*2+0], af, b2a);
                uint32_t b2b[2] = { bf[1], bf[3] };
                mma_f16(sc[nj*2+1], af, b2b);
            }
        }
        float tm0 = -1e30f, tm1 = -1e30f;
        #pragma unroll
        for (int u = 0; u < 8; u++) {
            sc[u][0]*=SCALE; sc[u][1]*=SCALE; sc[u][2]*=SCALE; sc[u][3]*=SCALE;
            tm0 = fmaxf(tm0, fmaxf(sc[u][0], sc[u][1]));
            tm1 = fmaxf(tm1, fmaxf(sc[u][2], sc[u][3]));
        }
        tm0 = fmaxf(tm0, __shfl_xor_sync(0xffffffffu, tm0, 1));
        tm0 = fmaxf(tm0, __shfl_xor_sync(0xffffffffu, tm0, 2));
        tm1 = fmaxf(tm1, __shfl_xor_sync(0xffffffffu, tm1, 1));
        tm1 = fmaxf(tm1, __shfl_xor_sync(0xffffffffu, tm1, 2));
        const float mn0 = fmaxf(m0, tm0), mn1 = fmaxf(m1, tm1);
        const float cr0 = __expf(m0 - mn0), cr1 = __expf(m1 - mn1);
        float rs0 = 0.f, rs1 = 0.f;
        uint32_t pa[4][4];
        #pragma unroll
        for (int u = 0; u < 8; u++) {
            float p0 = __expf(sc[u][0]-mn0), p1 = __expf(sc[u][1]-mn0);
            float p2 = __expf(sc[u][2]-mn1), p3 = __expf(sc[u][3]-mn1);
            rs0 += p0 + p1; rs1 += p2 + p3;
            __half2 hA = __floats2half2_rn(p0, p1);
            __half2 hB = __floats2half2_rn(p2, p3);
            pa[u>>1][(u&1)*2+0] = *(uint32_t*)&hA;
            pa[u>>1][(u&1)*2+1] = *(uint32_t*)&hB;
        }
        rs0 += __shfl_xor_sync(0xffffffffu, rs0, 1);
        rs0 += __shfl_xor_sync(0xffffffffu, rs0, 2);
        rs1 += __shfl_xor_sync(0xffffffffu, rs1, 1);
        rs1 += __shfl_xor_sync(0xffffffffu, rs1, 2);
        s0 = s0*cr0 + rs0; s1 = s1*cr1 + rs1;
        m0 = mn0; m1 = mn1;
        #pragma unroll
        for (int u = 0; u < 8; u++) {
            oc[u][0]*=cr0; oc[u][1]*=cr0; oc[u][2]*=cr1; oc[u][3]*=cr1;
        }
        #pragma unroll
        for (int ks = 0; ks < 4; ks++) {
            #pragma unroll
            for (int nj = 0; nj < 4; nj++) {
                uint32_t bf[4];
                const int rk = ks*16 + (lane&7) + ((lane>>4)&1)*8;
                const int cn = nj*2 + ((lane>>3)&1);
                ldsm_x4_t(bf, vb + rk*128 + (((cn ^ (rk&7))) << 4));
                uint32_t b2a[2] = { bf[0], bf[2] };
                mma_f16(oc[nj*2+0], pa[ks], b2a);
                uint32_t b2b[2] = { bf[1], bf[3] };
                mma_f16(oc[nj*2+1], pa[ks], b2b);
            }
        }
        __syncthreads();
        if (t + 2 < TILES_PER_CH) {
            uint32_t base = sKV + (t & 1) * 16384;
            int n0 = n0base + (t + 2) * 64;
            for (int i = tid; i < 1024; i += 128) {
                int sel = i >> 9;
                int row = (i >> 3) & 63;
                int c4 = i & 7;
                CP_ASYNC16(base + sel*8192 + row*128 + ((c4 ^ (row&7)) << 4),
                           gYh + ((size_t)(b*SEQ + n0 + row))*QKV_N
                               + (sel ? 2*CDIM : CDIM) + h*HD + c4*8);
            }
        }
        CP_COMMIT();
    }

    const size_t fbase = ((size_t)bh*NCH + ch)*4096;
    const int r0a = w*16 + g, r1a = r0a + 8;
    #pragma unroll
    for (int u = 0; u < 8; u++) {
        int col = u*8 + 2*c;
        *(float2*)&gFp[fbase + (size_t)r0a*64 + col] = make_float2(oc[u][0], oc[u][1]);
        *(float2*)&gFp[fbase + (size_t)r1a*64 + col] = make_float2(oc[u][2], oc[u][3]);
    }
    if (c == 0) {
        gMp[(bh*NCH+ch)*64 + r0a] = m0;
        gMp[(bh*NCH+ch)*64 + r1a] = m1;
        gSp[(bh*NCH+ch)*64 + r0a] = s0;
        gSp[(bh*NCH+ch)*64 + r1a] = s1;
    }
}

// ---------------- combine flash partials + T^T = (W2inv @ F)^T ---------------
// fine-grained column split: grid (NBH, 16), each block owns 4 d-columns.
__global__ void __launch_bounds__(256) k3_combine()
{
    __shared__ float wgt[NCH*64];
    __shared__ float sF[64*5];       // 64 rows x 4 cols (+1 pad)
    __shared__ float sW[64*64];
    const int bh = blockIdx.x;
    const int d0 = blockIdx.y * 4;
    const int tid = threadIdx.x;

    if (tid < 64) {
        float M = -1e30f;
        for (int c = 0; c < NCH; c++) M = fmaxf(M, gMp[(bh*NCH + c)*64 + tid]);
        float denom = 0.f;
        for (int c = 0; c < NCH; c++)
            denom += __expf(gMp[(bh*NCH + c)*64 + tid] - M) * gSp[(bh*NCH + c)*64 + tid];
        float invd = 1.f / denom;
        for (int c = 0; c < NCH; c++)
            wgt[c*64 + tid] = __expf(gMp[(bh*NCH + c)*64 + tid] - M) * invd;
    }
    for (int e = tid; e < 4096; e += 256) sW[e] = gW2inv[bh*4096 + e];
    __syncthreads();

    // F slice: 64 rows x 4 cols — one element per thread
    {
        int l = tid >> 2, dd = tid & 3;
        float f = 0.f;
        #pragma unroll 4
        for (int c = 0; c < NCH; c++)
            f += gFp[((size_t)bh * NCH + c) * 4096 + l*64 + d0 + dd] * wgt[c*64 + l];
        sF[l*5 + dd] = f;
    }
    __syncthreads();

    // T slice = W2inv @ F_slice — one output element per thread (64 x 4)
    {
        const int i = tid >> 2, j = tid & 3;
        float cc = 0.f;
        #pragma unroll 8
        for (int k = 0; k < 64; k++)
            cc += sW[i*64 + k] * sF[k*5 + j];
        gTth[bh*4096 + (d0 + j)*64 + i] = __float2half(cc);
    }
}

// ---------------- kernel_1 @ T -> gATh : K/T resident, 4 q-tiles per block ---
#define K4_TILES 4
#define K4_SMEM (8192 + 8192 + 2*16384)   // K + T + double-buffered Q

__global__ void __launch_bounds__(256) k4_out()
{
    extern __shared__ __align__(128) char sm4[];
    const uint32_t sK  = smem_u32(sm4);
    const uint32_t sT  = sK + 8192;
    const uint32_t sQb = sT + 8192;

    const int bh = blockIdx.y;
    const int b = bh >> 3, h = bh & 7;
    const int qt0 = blockIdx.x * K4_TILES;
    const int tid = threadIdx.x;
    const int lane = tid & 31;
    const int w = tid >> 5;
    const int g = lane >> 2, c = lane & 3;
    const int lrow = lane & 15, lhalf = lane >> 4;

    for (int i = tid; i < 512; i += 256) {
        int row = i >> 3, c4 = i & 7;
        uint32_t swz = (uint32_t)((c4 ^ (row & 7)) << 4);
        CP_ASYNC16(sK + row*128 + swz,
                   gYh + ((size_t)(b*SEQ + row*LMSTRIDE))*QKV_N + CDIM + h*HD + c4*8);
        CP_ASYNC16(sT + row*128 + swz,
                   gTth + bh*4096 + row*64 + c4*8);
    }
    for (int i = tid; i < 1024; i += 256) {
        int row = i >> 3, c4 = i & 7;
        uint32_t swz = (uint32_t)((c4 ^ (row & 7)) << 4);
        CP_ASYNC16(sQb + row*128 + swz,
                   gYh + ((size_t)(b*SEQ + qt0*128 + row))*QKV_N + h*HD + c4*8);
    }
    CP_COMMIT();

    for (int t = 0; t < K4_TILES; t++) {
        CP_WAIT0();
        __syncthreads();
        const uint32_t sQ = sQb + (t & 1) * 16384;
        const int n0 = (qt0 + t) * 128;

        if (t + 1 < K4_TILES) {
            const uint32_t nQ = sQb + ((t + 1) & 1) * 16384;
            const int nn0 = (qt0 + t + 1) * 128;
            for (int i = tid; i < 1024; i += 256) {
                int row = i >> 3, c4 = i & 7;
                uint32_t swz = (uint32_t)((c4 ^ (row & 7)) << 4);
                CP_ASYNC16(nQ + row*128 + swz,
                           gYh + ((size_t)(b*SEQ + nn0 + row))*QKV_N + h*HD + c4*8);
            }
        }
        CP_COMMIT();

        float sc[8][4];
        #pragma unroll
        for (int u = 0; u < 8; u++) { sc[u][0]=sc[u][1]=sc[u][2]=sc[u][3]=0.f; }
        #pragma unroll
        for (int ks = 0; ks < 4; ks++) {
            uint32_t af[4];
            const int qr = w*16 + lrow;
            ldsm_x4(af, sQ + qr*128 + (((ks*2+lhalf) ^ (qr&7)) << 4));
            #pragma unroll
            for (int nj = 0; nj < 4; nj++) {
                uint32_t bf[4];
                const int kr = nj*16 + lrow;
                ldsm_x4(bf, sK + kr*128 + (((ks*2+lhalf) ^ (kr&7)) << 4));
                uint32_t b2a[2] = { bf[0], bf[2] };
                mma_f16(sc[nj*2+0], af, b2a);
                uint32_t b2b[2] = { bf[1], bf[3] };
                mma_f16(sc[nj*2+1], af, b2b);
            }
        }
        float tm0 = -1e30f, tm1 = -1e30f;
        #pragma unroll
        for (int u = 0; u < 8; u++) {
            sc[u][0]*=SCALE; sc[u][1]*=SCALE; sc[u][2]*=SCALE; sc[u][3]*=SCALE;
            tm0 = fmaxf(tm0, fmaxf(sc[u][0], sc[u][1]));
            tm1 = fmaxf(tm1, fmaxf(sc[u][2], sc[u][3]));
        }
        tm0 = fmaxf(tm0, __shfl_xor_sync(0xffffffffu, tm0, 1));
        tm0 = fmaxf(tm0, __shfl_xor_sync(0xffffffffu, tm0, 2));
        tm1 = fmaxf(tm1, __shfl_xor_sync(0xffffffffu, tm1, 1));
        tm1 = fmaxf(tm1, __shfl_xor_sync(0xffffffffu, tm1, 2));
        float rs0 = 0.f, rs1 = 0.f;
        uint32_t pa[4][4];
        #pragma unroll
        for (int u = 0; u < 8; u++) {
            float p0 = __expf(sc[u][0]-tm0), p1 = __expf(sc[u][1]-tm0);
            float p2 = __expf(sc[u][2]-tm1), p3 = __expf(sc[u][3]-tm1);
            rs0 += p0 + p1; rs1 += p2 + p3;
            __half2 hA = __floats2half2_rn(p0, p1);
            __half2 hB = __floats2half2_rn(p2, p3);
            pa[u>>1][(u&1)*2+0] = *(uint32_t*)&hA;
            pa[u>>1][(u&1)*2+1] = *(uint32_t*)&hB;
        }
        rs0 += __shfl_xor_sync(0xffffffffu, rs0, 1);
        rs0 += __shfl_xor_sync(0xffffffffu, rs0, 2);
        rs1 += __shfl_xor_sync(0xffffffffu, rs1, 1);
        rs1 += __shfl_xor_sync(0xffffffffu, rs1, 2);
        const float inv0 = 1.f / rs0, inv1 = 1.f / rs1;

        float oc[8][4];
        #pragma unroll
        for (int u = 0; u < 8; u++) { oc[u][0]=oc[u][1]=oc[u][2]=oc[u][3]=0.f; }
        #pragma unroll
        for (int ks = 0; ks < 4; ks++) {
            #pragma unroll
            for (int nj = 0; nj < 4; nj++) {
                uint32_t bf[4];
                const int tr = nj*16 + lrow;
                ldsm_x4(bf, sT + tr*128 + (((ks*2+lhalf) ^ (tr&7)) << 4));
                uint32_t b2a[2] = { bf[0], bf[2] };
                mma_f16(oc[nj*2+0], pa[ks], b2a);
                uint32_t b2b[2] = { bf[1], bf[3] };
                mma_f16(oc[nj*2+1], pa[ks], b2b);
            }
        }

        const int r0a = w*16 + g;
        #pragma unroll
        for (int u = 0; u < 8; u++) {
            int col = u*8 + 2*c;
            __half2 hA = __floats2half2_rn(oc[u][0]*inv0, oc[u][1]*inv0);
            __half2 hB = __floats2half2_rn(oc[u][2]*inv1, oc[u][3]*inv1);
            *(uint32_t*)&gATh[((size_t)(b*SEQ + n0 + r0a))*CDIM + h*HD + col]     = *(uint32_t*)&hA;
            *(uint32_t*)&gATh[((size_t)(b*SEQ + n0 + r0a + 8))*CDIM + h*HD + col] = *(uint32_t*)&hB;
        }
        __syncthreads();
    }
}

// ---------------- launcher ---------------------------------------------------
extern "C" void kernel_launch(void* const* d_in, const int* in_sizes, int n_in,
                              void* d_out, int out_size)
{
    const float* x     = (const float*)d_in[0];
    const float* Wqkv  = (const float*)d_in[1];
    const float* bqkv  = (const float*)d_in[2];
    const float* Wproj = (const float*)d_in[3];
    const float* bproj = (const float*)d_in[4];
    float* out = (float*)d_out;

    cudaFuncSetAttribute(gemm_h, cudaFuncAttributeMaxDynamicSharedMemorySize, SMEM_GEMMH);
    cudaFuncSetAttribute(k3k2,   cudaFuncAttributeMaxDynamicSharedMemorySize, K3K2_SMEM);
    cudaFuncSetAttribute(k4_out, cudaFuncAttributeMaxDynamicSharedMemorySize, K4_SMEM);

    __half *pXh, *pWqkvh, *pWph, *pYh, *pATh;
    cudaGetSymbolAddress((void**)&pXh,    gXh);
    cudaGetSymbolAddress((void**)&pWqkvh, gWqkvh);
    cudaGetSymbolAddress((void**)&pWph,   gWph);
    cudaGetSymbolAddress((void**)&pYh,    gYh);
    cudaGetSymbolAddress((void**)&pATh,   gATh);

    // 0. fused fp32 -> fp16 conversion (x | Wqkv | Wproj)
    {
        int ntot = BN_TOK * CDIM + QKV_N * CDIM + CDIM * CDIM;
        cvt_all<<<(ntot/8 + 255)/256, 256>>>(x, Wqkv, Wproj);
    }

    // 1. QKV projection -> fp16 gYh
    gemm_h<<<dim3(QKV_N/128, BN_TOK/128), 256, SMEM_GEMMH>>>(pXh, pWqkvh, bqkv, pYh, BN_TOK, QKV_N, CDIM, 1);
    // 2+3. newton inverse AND flash partials concurrently (heterogeneous grid)
    k3k2<<<NBH + FLASH_BLOCKS, 128, K3K2_SMEM>>>();
    k3_combine<<<dim3(NBH, 16), 256>>>();
    // 4. out = softmax(q k_lm^T) @ T -> gATh fp16 (4 q-tiles/block, K/T resident)
    k4_out<<<dim3(SEQ/128/K4_TILES, NBH), 256, K4_SMEM>>>();
    // 5. projection: out = gATh @ Wproj^T + bproj (fp32 out)
    gemm_h<<<dim3(CDIM/128, BN_TOK/128), 256, SMEM_GEMMH>>>(pATh, pWph, bproj, out, BN_TOK, CDIM, CDIM, 0);
}

// round 14
// speedup vs baseline: 1.1804x; 1.0005x over previous
#include <cuda_runtime.h>
#include <cuda_fp16.h>
#include <cstdint>

// ---------------- problem constants ----------------
#define BDIM     4
#define SEQ      8192
#define CDIM     512
#define NH       8
#define HD       64
#define NLM      64
#define LMSTRIDE 128           // SEQ / NLM
#define BN_TOK   (BDIM*SEQ)    // 32768
#define QKV_N    (3*CDIM)      // 1536
#define NBH      (BDIM*NH)     // 32
#define NCH      16            // key chunks for kernel_3 flash
#define KEYS_PER_CH (SEQ/NCH)  // 512
#define TILES_PER_CH (KEYS_PER_CH/64) // 8
#define SCALE    0.125f        // hd^-0.5

// ---------------- device scratch (no runtime allocs allowed) ----------------
__device__ __half gXh[(size_t)BN_TOK * CDIM];    // x in fp16
__device__ __half gWqkvh[QKV_N * CDIM];          // Wqkv in fp16
__device__ __half gWph[CDIM * CDIM];             // Wproj in fp16
__device__ __half gYh[(size_t)BN_TOK * QKV_N];   // qkv activations fp16
__device__ __half gATh[(size_t)BN_TOK * CDIM];   // attention output fp16
__device__ float  gW2inv[NBH*64*64];
__device__ __half gTth[NBH*64*64];               // (W2inv @ F)^T fp16, [bh][hd][lm]
__device__ float  gFp[(size_t)NBH*NCH*64*64];    // flash partial accumulators
__device__ float  gMp[NBH*NCH*64];
__device__ float  gSp[NBH*NCH*64];

// ---------------- ptx helpers ------------------------------------------------
__device__ __forceinline__ uint32_t smem_u32(const void* p) {
    uint32_t a;
    asm("{ .reg .u64 t; cvta.to.shared.u64 t, %1; cvt.u32.u64 %0, t; }" : "=r"(a) : "l"(p));
    return a;
}
__device__ __forceinline__ void mma_f16(float* d, const uint32_t* a, const uint32_t* b) {
    asm volatile(
        "mma.sync.aligned.m16n8k16.row.col.f32.f16.f16.f32 "
        "{%0,%1,%2,%3}, {%4,%5,%6,%7}, {%8,%9}, {%0,%1,%2,%3};"
        : "+f"(d[0]), "+f"(d[1]), "+f"(d[2]), "+f"(d[3])
        : "r"(a[0]), "r"(a[1]), "r"(a[2]), "r"(a[3]),
          "r"(b[0]), "r"(b[1]));
}
__device__ __forceinline__ void ldsm_x4(uint32_t* r, uint32_t addr) {
    asm volatile("ldmatrix.sync.aligned.m8n8.x4.shared.b16 {%0,%1,%2,%3}, [%4];"
                 : "=r"(r[0]), "=r"(r[1]), "=r"(r[2]), "=r"(r[3]) : "r"(addr));
}
__device__ __forceinline__ void ldsm_x4_t(uint32_t* r, uint32_t addr) {
    asm volatile("ldmatrix.sync.aligned.m8n8.x4.trans.shared.b16 {%0,%1,%2,%3}, [%4];"
                 : "=r"(r[0]), "=r"(r[1]), "=r"(r[2]), "=r"(r[3]) : "r"(addr));
}
#define CP_ASYNC16(dst, src) \
    asm volatile("cp.async.cg.shared.global [%0], [%1], 16;" :: "r"(dst), "l"(src) : "memory")
#define CP_COMMIT() asm volatile("cp.async.commit_group;" ::: "memory")
#define CP_WAIT1()  asm volatile("cp.async.wait_group 1;" ::: "memory")
#define CP_WAIT0()  asm volatile("cp.async.wait_group 0;" ::: "memory")

// ---------------- fused fp32 -> fp16 conversion (x | Wqkv | Wproj) -----------
__global__ void __launch_bounds__(256) cvt_all(const float* __restrict__ x,
                                               const float* __restrict__ wqkv,
                                               const float* __restrict__ wproj)
{
    const int nx = BN_TOK * CDIM;
    const int nw = QKV_N * CDIM;
    const int np = CDIM * CDIM;
    int i = (blockIdx.x * blockDim.x + threadIdx.x) * 8;
    const float* s;
    __half* d;
    if (i < nx)               { s = x + i;              d = gXh + i; }
    else if (i < nx + nw)     { s = wqkv + (i - nx);    d = gWqkvh + (i - nx); }
    else if (i < nx + nw + np){ s = wproj + (i - nx - nw); d = gWph + (i - nx - nw); }
    else return;
    float4 a = *(const float4*)(s);
    float4 b = *(const float4*)(s + 4);
    __half2 h0 = __floats2half2_rn(a.x, a.y);
    __half2 h1 = __floats2half2_rn(a.z, a.w);
    __half2 h2 = __floats2half2_rn(b.x, b.y);
    __half2 h3 = __floats2half2_rn(b.z, b.w);
    uint4 o;
    o.x = *(uint32_t*)&h0; o.y = *(uint32_t*)&h1;
    o.z = *(uint32_t*)&h2; o.w = *(uint32_t*)&h3;
    *(uint4*)d = o;
}

// ---------------- fp16 tensor-core GEMM (round-6 best config) ----------------
#define STG_BYTES 32768          // 16KB A + 16KB B per stage
#define SMEM_GEMMH (3 * STG_BYTES)

__device__ __forceinline__ void stage_copy(uint32_t sbase, const __half* A,
                                           const __half* B, int bm, int bn,
                                           int K, int k0, int tid)
{
    #pragma unroll
    for (int i = 0; i < 4; i++) {
        int lin = tid + i * 256;
        int row = lin >> 3;
        int c   = lin & 7;
        uint32_t dA = sbase + row * 128 + ((c ^ (row & 7)) << 4);
        CP_ASYNC16(dA, A + (size_t)(bm + row) * K + k0 + c * 8);
        uint32_t dB = sbase + 16384 + row * 128 + ((c ^ (row & 7)) << 4);
        CP_ASYNC16(dB, B + (size_t)(bn + row) * K + k0 + c * 8);
    }
}

__global__ void __launch_bounds__(256) gemm_h(const __half* __restrict__ A,
                                              const __half* __restrict__ B,
                                              const float* __restrict__ bias,
                                              void* __restrict__ Cv,
                                              int M, int N, int K, int half_out)
{
    extern __shared__ __align__(128) char smg[];
    const uint32_t sb = smem_u32(smg);

    const int bm = blockIdx.y * 128;
    const int bn = blockIdx.x * 128;
    const int tid  = threadIdx.x;
    const int lane = tid & 31;
    const int warp = tid >> 5;
    const int wm = (warp & 1) * 64;
    const int wn = (warp >> 1) * 32;
    const int g = lane >> 2;
    const int c = lane & 3;
    const int lrow = lane & 15;
    const int lhalf = lane >> 4;

    float acc[4][4][4];
    #pragma unroll
    for (int mi = 0; mi < 4; mi++)
        #pragma unroll
        for (int t = 0; t < 4; t++)
            #pragma unroll
            for (int r = 0; r < 4; r++) acc[mi][t][r] = 0.f;

    const int KT = K >> 6;

    stage_copy(sb, A, B, bm, bn, K, 0, tid);
    CP_COMMIT();
    stage_copy(sb + STG_BYTES, A, B, bm, bn, K, 64, tid);
    CP_COMMIT();

    for (int kt = 0; kt < KT; kt++) {
        CP_WAIT1();
        __syncthreads();

        if (kt + 2 < KT)
            stage_copy(sb + ((kt + 2) % 3) * STG_BYTES, A, B, bm, bn, K, (kt + 2) * 64, tid);
        CP_COMMIT();

        const uint32_t aBase = sb + (kt % 3) * STG_BYTES;
        const uint32_t bBase = aBase + 16384;

        #pragma unroll
        for (int ks = 0; ks < 4; ks++) {
            uint32_t af[4][4], bf[2][4];
            #pragma unroll
            for (int mi = 0; mi < 4; mi++) {
                const int row = wm + mi * 16 + lrow;
                const int ch  = (ks * 2 + lhalf) ^ (row & 7);
                ldsm_x4(af[mi], aBase + row * 128 + (ch << 4));
            }
            #pragma unroll
            for (int nj = 0; nj < 2; nj++) {
                const int row = wn + nj * 16 + lrow;
                const int ch  = (ks * 2 + lhalf) ^ (row & 7);
                ldsm_x4(bf[nj], bBase + row * 128 + (ch << 4));
            }
            #pragma unroll
            for (int mi = 0; mi < 4; mi++) {
                #pragma unroll
                for (int t = 0; t < 4; t++) {
                    const int nj = t >> 1, sub = t & 1;
                    uint32_t b2[2] = { bf[nj][sub], bf[nj][sub + 2] };
                    mma_f16(acc[mi][t], af[mi], b2);
                }
            }
        }
    }

    if (half_out) {
        __half* C = (__half*)Cv;
        #pragma unroll
        for (int mi = 0; mi < 4; mi++) {
            const int row = bm + wm + mi * 16 + g;
            #pragma unroll
            for (int t = 0; t < 4; t++) {
                const int col = bn + wn + (t >> 1) * 16 + (t & 1) * 8 + 2 * c;
                const float b0 = bias[col], b1 = bias[col + 1];
                __half2 o0 = __floats2half2_rn(acc[mi][t][0] + b0, acc[mi][t][1] + b1);
                __half2 o1 = __floats2half2_rn(acc[mi][t][2] + b0, acc[mi][t][3] + b1);
                *(uint32_t*)(C + (size_t)row * N + col)       = *(uint32_t*)&o0;
                *(uint32_t*)(C + (size_t)(row + 8) * N + col) = *(uint32_t*)&o1;
            }
        }
    } else {
        float* C = (float*)Cv;
        #pragma unroll
        for (int mi = 0; mi < 4; mi++) {
            const int row = bm + wm + mi * 16 + g;
            #pragma unroll
            for (int t = 0; t < 4; t++) {
                const int col = bn + wn + (t >> 1) * 16 + (t & 1) * 8 + 2 * c;
                const float b0 = bias[col], b1 = bias[col + 1];
                float2 o0 = make_float2(acc[mi][t][0] + b0, acc[mi][t][1] + b1);
                float2 o1 = make_float2(acc[mi][t][2] + b0, acc[mi][t][3] + b1);
                *(float2*)(C + (size_t)row * N + col)       = o0;
                *(float2*)(C + (size_t)(row + 8) * N + col) = o1;
            }
        }
    }
}

// ---------------- 64x64 fp32 helpers for 128 threads (4x8 tiles) -------------
__device__ __forceinline__ void mm64_nt8(float* C, int ldc,
                                         const float* A, int lda,
                                         const float* B, int ldb,
                                         float scale, int tid)
{
    const int i0 = (tid >> 3) * 4, j0 = (tid & 7) * 8;
    float c[4][8] = {};
    #pragma unroll 4
    for (int d = 0; d < 64; d++) {
        float a[4], bv[8];
        #pragma unroll
        for (int ii = 0; ii < 4; ii++) a[ii]  = A[(i0+ii)*lda + d];
        #pragma unroll
        for (int jj = 0; jj < 8; jj++) bv[jj] = B[(j0+jj)*ldb + d];
        #pragma unroll
        for (int ii = 0; ii < 4; ii++)
            #pragma unroll
            for (int jj = 0; jj < 8; jj++)
                c[ii][jj] += a[ii] * bv[jj];
    }
    #pragma unroll
    for (int ii = 0; ii < 4; ii++)
        #pragma unroll
        for (int jj = 0; jj < 8; jj++)
            C[(i0+ii)*ldc + j0+jj] = scale * c[ii][jj];
}

__device__ __forceinline__ void mm64_nn8(float* C, int ldc,
                                         const float* A, int lda,
                                         const float* B, int ldb, int tid)
{
    const int i0 = (tid >> 3) * 4, j0 = (tid & 7) * 8;
    float c[4][8] = {};
    #pragma unroll 4
    for (int k = 0; k < 64; k++) {
        float a[4], bv[8];
        #pragma unroll
        for (int ii = 0; ii < 4; ii++) a[ii]  = A[(i0+ii)*lda + k];
        #pragma unroll
        for (int jj = 0; jj < 8; jj++) bv[jj] = B[k*ldb + j0+jj];
        #pragma unroll
        for (int ii = 0; ii < 4; ii++)
            #pragma unroll
            for (int jj = 0; jj < 8; jj++)
                c[ii][jj] += a[ii] * bv[jj];
    }
    #pragma unroll
    for (int ii = 0; ii < 4; ii++)
        #pragma unroll
        for (int jj = 0; jj < 8; jj++)
            C[(i0+ii)*ldc + j0+jj] = c[ii][jj];
}

// ---------------- newton branch (128 threads, 3 smem matrices) ----------------
__device__ void k2_newton_body(char* smraw, int bh, int tid)
{
    float* S  = (float*)smraw;
    float* Z  = S  + 4160;
    float* T1 = Z  + 4160;
    __shared__ float red[4];

    const int b = bh >> 3, h = bh & 7;

    for (int e = tid; e < 4096; e += 128) {
        int l = e >> 6, d = e & 63;
        size_t base = (size_t)(b * SEQ + l * LMSTRIDE) * QKV_N + h * HD + d;
        Z [l*65 + d] = __half2float(gYh[base]);
        T1[l*65 + d] = __half2float(gYh[base + CDIM]);
    }
    __syncthreads();

    mm64_nt8(S, 65, Z, 65, T1, 65, SCALE, tid);
    __syncthreads();
    if (tid < 64) {
        float mx = -1e30f;
        for (int j = 0; j < 64; j++) mx = fmaxf(mx, S[tid*65 + j]);
        float s = 0.f;
        for (int j = 0; j < 64; j++) { float p = __expf(S[tid*65+j] - mx); S[tid*65+j] = p; s += p; }
        float inv = 1.f / s;
        for (int j = 0; j < 64; j++) S[tid*65 + j] *= inv;
    }
    __syncthreads();

    float part = 0.f;
    for (int e = tid; e < 4096; e += 128) {
        int i = e >> 6, j = e & 63;
        float v = S[i*65 + j];
        part += v * v;
    }
    #pragma unroll
    for (int o = 16; o; o >>= 1) part += __shfl_xor_sync(0xffffffffu, part, o);
    if ((tid & 31) == 0) red[tid >> 5] = part;
    __syncthreads();
    float fro2 = fmaxf(red[0]+red[1]+red[2]+red[3], 1e-12f);
    float invf = 1.f / fro2;

    for (int e = tid; e < 4096; e += 128) {
        int i = e >> 6, j = e & 63;
        Z[j*65 + i] = S[i*65 + j] * invf;
    }
    __syncthreads();

    const int i0 = (tid >> 3) * 4, j0 = (tid & 7) * 8;
    for (int it = 0; it < 6; it++) {
        mm64_nn8(T1, 65, S, 65, Z, 65, tid);
        __syncthreads();
        float cc[4][8];
        #pragma unroll
        for (int ii = 0; ii < 4; ii++)
            #pragma unroll
            for (int jj = 0; jj < 8; jj++)
                cc[ii][jj] = 2.f * Z[(i0+ii)*65 + j0+jj];
        #pragma unroll 4
        for (int k = 0; k < 64; k++) {
            float a[4], bv[8];
            #pragma unroll
            for (int ii = 0; ii < 4; ii++) a[ii]  = Z[(i0+ii)*65 + k];
            #pragma unroll
            for (int jj = 0; jj < 8; jj++) bv[jj] = T1[k*65 + j0+jj];
            #pragma unroll
            for (int ii = 0; ii < 4; ii++)
                #pragma unroll
                for (int jj = 0; jj < 8; jj++)
                    cc[ii][jj] -= a[ii] * bv[jj];
        }
        __syncthreads();
        #pragma unroll
        for (int ii = 0; ii < 4; ii++)
            #pragma unroll
            for (int jj = 0; jj < 8; jj++)
                Z[(i0+ii)*65 + j0+jj] = cc[ii][jj];
        __syncthreads();
    }

    for (int e = tid; e < 4096; e += 128) {
        int i = e >> 6, j = e & 63;
        gW2inv[bh*4096 + i*64 + j] = Z[i*65 + j];
    }
}

// ---------------- unified flash + newton kernel -------------------------------
#define K3K2_SMEM 49920
#define FLASH_BLOCKS (NBH*NCH)

__global__ void __launch_bounds__(128) k3k2()
{
    extern __shared__ __align__(128) char smu[];
    const int blk = blockIdx.x;
    const int tid = threadIdx.x;

    if (blk < NBH) {
        k2_newton_body(smu, blk, tid);
        return;
    }

    const uint32_t sQ  = smem_u32(smu);
    const uint32_t sKV = sQ + 8192;

    const int fblk = blk - NBH;
    const int bh = fblk & (NBH - 1);
    const int ch = fblk >> 5;
    const int b = bh >> 3, h = bh & 7;
    const int lane = tid & 31;
    const int w = tid >> 5;
    const int g = lane >> 2, c = lane & 3;
    const int lrow = lane & 15, lhalf = lane >> 4;
    const int n0base = ch * KEYS_PER_CH;

    for (int i = tid; i < 512; i += 128) {
        int row = i >> 3, c4 = i & 7;
        CP_ASYNC16(sQ + row*128 + ((c4 ^ (row&7)) << 4),
                   gYh + ((size_t)(b*SEQ + row*LMSTRIDE))*QKV_N + h*HD + c4*8);
    }
    #pragma unroll
    for (int st = 0; st < 2; st++) {
        uint32_t base = sKV + st * 16384;
        for (int i = tid; i < 1024; i += 128) {
            int sel = i >> 9;
            int row = (i >> 3) & 63;
            int c4 = i & 7;
            CP_ASYNC16(base + sel*8192 + row*128 + ((c4 ^ (row&7)) << 4),
                       gYh + ((size_t)(b*SEQ + n0base + st*64 + row))*QKV_N
                           + (sel ? 2*CDIM : CDIM) + h*HD + c4*8);
        }
        CP_COMMIT();
    }

    float m0 = -1e30f, m1 = -1e30f, s0 = 0.f, s1 = 0.f;
    float oc[8][4];
    #pragma unroll
    for (int u = 0; u < 8; u++) { oc[u][0]=oc[u][1]=oc[u][2]=oc[u][3]=0.f; }

    for (int t = 0; t < TILES_PER_CH; t++) {
        CP_WAIT1();
        __syncthreads();
        const uint32_t kb = sKV + (t & 1) * 16384;
        const uint32_t vb = kb + 8192;

        float sc[8][4];
        #pragma unroll
        for (int u = 0; u < 8; u++) { sc[u][0]=sc[u][1]=sc[u][2]=sc[u][3]=0.f; }
        #pragma unroll
        for (int ks = 0; ks < 4; ks++) {
            uint32_t af[4];
            const int qr = w*16 + lrow;
            ldsm_x4(af, sQ + qr*128 + (((ks*2+lhalf) ^ (qr&7)) << 4));
            #pragma unroll
            for (int nj = 0; nj < 4; nj++) {
                uint32_t bf[4];
                const int kr = nj*16 + lrow;
                ldsm_x4(bf, kb + kr*128 + (((ks*2+lhalf) ^ (kr&7)) << 4));
                uint32_t b2a[2] = { bf[0], bf[2] };
                mma_f16(sc[nj*2+0], af, b2a);
                uint32_t b2b[2] = { bf[1], bf[3] };
                mma_f16(sc[nj*2+1], af, b2b);
            }
        }
        float tm0 = -1e30f, tm1 = -1e30f;
        #pragma unroll
        for (int u = 0; u < 8; u++) {
            sc[u][0]*=SCALE; sc[u][1]*=SCALE; sc[u][2]*=SCALE; sc[u][3]*=SCALE;
            tm0 = fmaxf(tm0, fmaxf(sc[u][0], sc[u][1]));
            tm1 = fmaxf(tm1, fmaxf(sc[u][2], sc[u][3]));
        }
        tm0 = fmaxf(tm0, __shfl_xor_sync(0xffffffffu, tm0, 1));
        tm0 = fmaxf(tm0, __shfl_xor_sync(0xffffffffu, tm0, 2));
        tm1 = fmaxf(tm1, __shfl_xor_sync(0xffffffffu, tm1, 1));
        tm1 = fmaxf(tm1, __shfl_xor_sync(0xffffffffu, tm1, 2));
        const float mn0 = fmaxf(m0, tm0), mn1 = fmaxf(m1, tm1);
        const float cr0 = __expf(m0 - mn0), cr1 = __expf(m1 - mn1);
        float rs0 = 0.f, rs1 = 0.f;
        uint32_t pa[4][4];
        #pragma unroll
        for (int u = 0; u < 8; u++) {
            float p0 = __expf(sc[u][0]-mn0), p1 = __expf(sc[u][1]-mn0);
            float p2 = __expf(sc[u][2]-mn1), p3 = __expf(sc[u][3]-mn1);
            rs0 += p0 + p1; rs1 += p2 + p3;
            __half2 hA = __floats2half2_rn(p0, p1);
            __half2 hB = __floats2half2_rn(p2, p3);
            pa[u>>1][(u&1)*2+0] = *(uint32_t*)&hA;
            pa[u>>1][(u&1)*2+1] = *(uint32_t*)&hB;
        }
        rs0 += __shfl_xor_sync(0xffffffffu, rs0, 1);
        rs0 += __shfl_xor_sync(0xffffffffu, rs0, 2);
        rs1 += __shfl_xor_sync(0xffffffffu, rs1, 1);
        rs1 += __shfl_xor_sync(0xffffffffu, rs1, 2);
        s0 = s0*cr0 + rs0; s1 = s1*cr1 + rs1;
        m0 = mn0; m1 = mn1;
        #pragma unroll
        for (int u = 0; u < 8; u++) {
            oc[u][0]*=cr0; oc[u][1]*=cr0; oc[u][2]*=cr1; oc[u][3]*=cr1;
        }
        #pragma unroll
        for (int ks = 0; ks < 4; ks++) {
            #pragma unroll
            for (int nj = 0; nj < 4; nj++) {
                uint32_t bf[4];
                const int rk = ks*16 + (lane&7) + ((lane>>4)&1)*8;
                const int cn = nj*2 + ((lane>>3)&1);
                ldsm_x4_t(bf, vb + rk*128 + (((cn ^ (rk&7))) << 4));
                uint32_t b2a[2] = { bf[0], bf[2] };
                mma_f16(oc[nj*2+0], pa[ks], b2a);
                uint32_t b2b[2] = { bf[1], bf[3] };
                mma_f16(oc[nj*2+1], pa[ks], b2b);
            }
        }
        __syncthreads();
        if (t + 2 < TILES_PER_CH) {
            uint32_t base = sKV + (t & 1) * 16384;
            int n0 = n0base + (t + 2) * 64;
            for (int i = tid; i < 1024; i += 128) {
                int sel = i >> 9;
                int row = (i >> 3) & 63;
                int c4 = i & 7;
                CP_ASYNC16(base + sel*8192 + row*128 + ((c4 ^ (row&7)) << 4),
                           gYh + ((size_t)(b*SEQ + n0 + row))*QKV_N
                               + (sel ? 2*CDIM : CDIM) + h*HD + c4*8);
            }
        }
        CP_COMMIT();
    }

    const size_t fbase = ((size_t)bh*NCH + ch)*4096;
    const int r0a = w*16 + g, r1a = r0a + 8;
    #pragma unroll
    for (int u = 0; u < 8; u++) {
        int col = u*8 + 2*c;
        *(float2*)&gFp[fbase + (size_t)r0a*64 + col] = make_float2(oc[u][0], oc[u][1]);
        *(float2*)&gFp[fbase + (size_t)r1a*64 + col] = make_float2(oc[u][2], oc[u][3]);
    }
    if (c == 0) {
        gMp[(bh*NCH+ch)*64 + r0a] = m0;
        gMp[(bh*NCH+ch)*64 + r1a] = m1;
        gSp[(bh*NCH+ch)*64 + r0a] = s0;
        gSp[(bh*NCH+ch)*64 + r1a] = s1;
    }
}

// ---------------- combine flash partials + T^T = (W2inv @ F)^T ---------------
// grid (NBH, 16), each block owns 4 d-columns. wgt phase parallel over 256 thr:
// thread (cg = tid>>6, l = tid&63) covers chunks [cg*4, cg*4+4).
__global__ void __launch_bounds__(256) k3_combine()
{
    __shared__ float wgt[NCH*64];
    __shared__ float redm[4][64];
    __shared__ float redd[4][64];
    __shared__ float sF[64*5];       // 64 rows x 4 cols (+1 pad)
    __shared__ float sW[64*64];
    const int bh = blockIdx.x;
    const int d0 = blockIdx.y * 4;
    const int tid = threadIdx.x;
    const int cg = tid >> 6;         // chunk group 0..3
    const int l  = tid & 63;         // landmark row

    // phase A: parallel max over this thread's 4 chunks (cache gMp/gSp in regs)
    float mloc[4], sloc[4];
    #pragma unroll
    for (int k = 0; k < 4; k++) {
        int c = cg * 4 + k;
        mloc[k] = gMp[(bh*NCH + c)*64 + l];
        sloc[k] = gSp[(bh*NCH + c)*64 + l];
    }
    float mg = fmaxf(fmaxf(mloc[0], mloc[1]), fmaxf(mloc[2], mloc[3]));
    redm[cg][l] = mg;
    // also start loading sW (independent)
    for (int e = tid; e < 4096; e += 256) sW[e] = gW2inv[bh*4096 + e];
    __syncthreads();
    const float M = fmaxf(fmaxf(redm[0][l], redm[1][l]),
                          fmaxf(redm[2][l], redm[3][l]));
    float dloc = 0.f;
    float eloc[4];
    #pragma unroll
    for (int k = 0; k < 4; k++) {
        eloc[k] = __expf(mloc[k] - M) * sloc[k];
        dloc += eloc[k];
    }
    redd[cg][l] = dloc;
    __syncthreads();
    const float denom = redd[0][l] + redd[1][l] + redd[2][l] + redd[3][l];
    const float invd = 1.f / denom;
    #pragma unroll
    for (int k = 0; k < 4; k++) {
        int c = cg * 4 + k;
        // wgt = exp(m_c - M) * invd  (eloc already includes s_c; divide back out)
        wgt[c*64 + l] = __expf(mloc[k] - M) * invd;
    }
    __syncthreads();

    // F slice: 64 rows x 4 cols — one element per thread
    {
        int lr = tid >> 2, dd = tid & 3;
        float f = 0.f;
        #pragma unroll 4
        for (int c = 0; c < NCH; c++)
            f += gFp[((size_t)bh * NCH + c) * 4096 + lr*64 + d0 + dd] * wgt[c*64 + lr];
        sF[lr*5 + dd] = f;
    }
    __syncthreads();

    // T slice = W2inv @ F_slice — one output element per thread (64 x 4)
    {
        const int i = tid >> 2, j = tid & 3;
        float cc = 0.f;
        #pragma unroll 8
        for (int k = 0; k < 64; k++)
            cc += sW[i*64 + k] * sF[k*5 + j];
        gTth[bh*4096 + (d0 + j)*64 + i] = __float2half(cc);
    }
}

// ---------------- kernel_1 @ T -> gATh : K/T resident, 4 q-tiles per block ---
#define K4_TILES 4
#define K4_SMEM (8192 + 8192 + 2*16384)   // K + T + double-buffered Q

__global__ void __launch_bounds__(256) k4_out()
{
    extern __shared__ __align__(128) char sm4[];
    const uint32_t sK  = smem_u32(sm4);
    const uint32_t sT  = sK + 8192;
    const uint32_t sQb = sT + 8192;

    const int bh = blockIdx.y;
    const int b = bh >> 3, h = bh & 7;
    const int qt0 = blockIdx.x * K4_TILES;
    const int tid = threadIdx.x;
    const int lane = tid & 31;
    const int w = tid >> 5;
    const int g = lane >> 2, c = lane & 3;
    const int lrow = lane & 15, lhalf = lane >> 4;

    for (int i = tid; i < 512; i += 256) {
        int row = i >> 3, c4 = i & 7;
        uint32_t swz = (uint32_t)((c4 ^ (row & 7)) << 4);
        CP_ASYNC16(sK + row*128 + swz,
                   gYh + ((size_t)(b*SEQ + row*LMSTRIDE))*QKV_N + CDIM + h*HD + c4*8);
        CP_ASYNC16(sT + row*128 + swz,
                   gTth + bh*4096 + row*64 + c4*8);
    }
    for (int i = tid; i < 1024; i += 256) {
        int row = i >> 3, c4 = i & 7;
        uint32_t swz = (uint32_t)((c4 ^ (row & 7)) << 4);
        CP_ASYNC16(sQb + row*128 + swz,
                   gYh + ((size_t)(b*SEQ + qt0*128 + row))*QKV_N + h*HD + c4*8);
    }
    CP_COMMIT();

    for (int t = 0; t < K4_TILES; t++) {
        CP_WAIT0();
        __syncthreads();
        const uint32_t sQ = sQb + (t & 1) * 16384;
        const int n0 = (qt0 + t) * 128;

        if (t + 1 < K4_TILES) {
            const uint32_t nQ = sQb + ((t + 1) & 1) * 16384;
            const int nn0 = (qt0 + t + 1) * 128;
            for (int i = tid; i < 1024; i += 256) {
                int row = i >> 3, c4 = i & 7;
                uint32_t swz = (uint32_t)((c4 ^ (row & 7)) << 4);
                CP_ASYNC16(nQ + row*128 + swz,
                           gYh + ((size_t)(b*SEQ + nn0 + row))*QKV_N + h*HD + c4*8);
            }
        }
        CP_COMMIT();

        float sc[8][4];
        #pragma unroll
        for (int u = 0; u < 8; u++) { sc[u][0]=sc[u][1]=sc[u][2]=sc[u][3]=0.f; }
        #pragma unroll
        for (int ks = 0; ks < 4; ks++) {
            uint32_t af[4];
            const int qr = w*16 + lrow;
            ldsm_x4(af, sQ + qr*128 + (((ks*2+lhalf) ^ (qr&7)) << 4));
            #pragma unroll
            for (int nj = 0; nj < 4; nj++) {
                uint32_t bf[4];
                const int kr = nj*16 + lrow;
                ldsm_x4(bf, sK + kr*128 + (((ks*2+lhalf) ^ (kr&7)) << 4));
                uint32_t b2a[2] = { bf[0], bf[2] };
                mma_f16(sc[nj*2+0], af, b2a);
                uint32_t b2b[2] = { bf[1], bf[3] };
                mma_f16(sc[nj*2+1], af, b2b);
            }
        }
        float tm0 = -1e30f, tm1 = -1e30f;
        #pragma unroll
        for (int u = 0; u < 8; u++) {
            sc[u][0]*=SCALE; sc[u][1]*=SCALE; sc[u][2]*=SCALE; sc[u][3]*=SCALE;
            tm0 = fmaxf(tm0, fmaxf(sc[u][0], sc[u][1]));
            tm1 = fmaxf(tm1, fmaxf(sc[u][2], sc[u][3]));
        }
        tm0 = fmaxf(tm0, __shfl_xor_sync(0xffffffffu, tm0, 1));
        tm0 = fmaxf(tm0, __shfl_xor_sync(0xffffffffu, tm0, 2));
        tm1 = fmaxf(tm1, __shfl_xor_sync(0xffffffffu, tm1, 1));
        tm1 = fmaxf(tm1, __shfl_xor_sync(0xffffffffu, tm1, 2));
        float rs0 = 0.f, rs1 = 0.f;
        uint32_t pa[4][4];
        #pragma unroll
        for (int u = 0; u < 8; u++) {
            float p0 = __expf(sc[u][0]-tm0), p1 = __expf(sc[u][1]-tm0);
            float p2 = __expf(sc[u][2]-tm1), p3 = __expf(sc[u][3]-tm1);
            rs0 += p0 + p1; rs1 += p2 + p3;
            __half2 hA = __floats2half2_rn(p0, p1);
            __half2 hB = __floats2half2_rn(p2, p3);
            pa[u>>1][(u&1)*2+0] = *(uint32_t*)&hA;
            pa[u>>1][(u&1)*2+1] = *(uint32_t*)&hB;
        }
        rs0 += __shfl_xor_sync(0xffffffffu, rs0, 1);
        rs0 += __shfl_xor_sync(0xffffffffu, rs0, 2);
        rs1 += __shfl_xor_sync(0xffffffffu, rs1, 1);
        rs1 += __shfl_xor_sync(0xffffffffu, rs1, 2);
        const float inv0 = 1.f / rs0, inv1 = 1.f / rs1;

        float oc[8][4];
        #pragma unroll
        for (int u = 0; u < 8; u++) { oc[u][0]=oc[u][1]=oc[u][2]=oc[u][3]=0.f; }
        #pragma unroll
        for (int ks = 0; ks < 4; ks++) {
            #pragma unroll
            for (int nj = 0; nj < 4; nj++) {
                uint32_t bf[4];
                const int tr = nj*16 + lrow;
                ldsm_x4(bf, sT + tr*128 + (((ks*2+lhalf) ^ (tr&7)) << 4));
                uint32_t b2a[2] = { bf[0], bf[2] };
                mma_f16(oc[nj*2+0], pa[ks], b2a);
                uint32_t b2b[2] = { bf[1], bf[3] };
                mma_f16(oc[nj*2+1], pa[ks], b2b);
            }
        }

        const int r0a = w*16 + g;
        #pragma unroll
        for (int u = 0; u < 8; u++) {
            int col = u*8 + 2*c;
            __half2 hA = __floats2half2_rn(oc[u][0]*inv0, oc[u][1]*inv0);
            __half2 hB = __floats2half2_rn(oc[u][2]*inv1, oc[u][3]*inv1);
            *(uint32_t*)&gATh[((size_t)(b*SEQ + n0 + r0a))*CDIM + h*HD + col]     = *(uint32_t*)&hA;
            *(uint32_t*)&gATh[((size_t)(b*SEQ + n0 + r0a + 8))*CDIM + h*HD + col] = *(uint32_t*)&hB;
        }
        __syncthreads();
    }
}

// ---------------- launcher ---------------------------------------------------
extern "C" void kernel_launch(void* const* d_in, const int* in_sizes, int n_in,
                              void* d_out, int out_size)
{
    const float* x     = (const float*)d_in[0];
    const float* Wqkv  = (const float*)d_in[1];
    const float* bqkv  = (const float*)d_in[2];
    const float* Wproj = (const float*)d_in[3];
    const float* bproj = (const float*)d_in[4];
    float* out = (float*)d_out;

    cudaFuncSetAttribute(gemm_h, cudaFuncAttributeMaxDynamicSharedMemorySize, SMEM_GEMMH);
    cudaFuncSetAttribute(k3k2,   cudaFuncAttributeMaxDynamicSharedMemorySize, K3K2_SMEM);
    cudaFuncSetAttribute(k4_out, cudaFuncAttributeMaxDynamicSharedMemorySize, K4_SMEM);

    __half *pXh, *pWqkvh, *pWph, *pYh, *pATh;
    cudaGetSymbolAddress((void**)&pXh,    gXh);
    cudaGetSymbolAddress((void**)&pWqkvh, gWqkvh);
    cudaGetSymbolAddress((void**)&pWph,   gWph);
    cudaGetSymbolAddress((void**)&pYh,    gYh);
    cudaGetSymbolAddress((void**)&pATh,   gATh);

    // 0. fused fp32 -> fp16 conversion (x | Wqkv | Wproj)
    {
        int ntot = BN_TOK * CDIM + QKV_N * CDIM + CDIM * CDIM;
        cvt_all<<<(ntot/8 + 255)/256, 256>>>(x, Wqkv, Wproj);
    }

    // 1. QKV projection -> fp16 gYh
    gemm_h<<<dim3(QKV_N/128, BN_TOK/128), 256, SMEM_GEMMH>>>(pXh, pWqkvh, bqkv, pYh, BN_TOK, QKV_N, CDIM, 1);
    // 2+3. newton inverse AND flash partials concurrently (heterogeneous grid)
    k3k2<<<NBH + FLASH_BLOCKS, 128, K3K2_SMEM>>>();
    k3_combine<<<dim3(NBH, 16), 256>>>();
    // 4. out = softmax(q k_lm^T) @ T -> gATh fp16 (4 q-tiles/block, K/T resident)
    k4_out<<<dim3(SEQ/128/K4_TILES, NBH), 256, K4_SMEM>>>();
    // 5. projection: out = gATh @ Wproj^T + bproj (fp32 out)
    gemm_h<<<dim3(CDIM/128, BN_TOK/128), 256, SMEM_GEMMH>>>(pATh, pWph, bproj, out, BN_TOK, CDIM, CDIM, 0);
}

// round 15
// speedup vs baseline: 1.1948x; 1.0122x over previous
#include <cuda_runtime.h>
#include <cuda_fp16.h>
#include <cstdint>

// ---------------- problem constants ----------------
#define BDIM     4
#define SEQ      8192
#define CDIM     512
#define NH       8
#define HD       64
#define NLM      64
#define LMSTRIDE 128           // SEQ / NLM
#define BN_TOK   (BDIM*SEQ)    // 32768
#define QKV_N    (3*CDIM)      // 1536
#define NBH      (BDIM*NH)     // 32
#define NCH      16            // key chunks for kernel_3 flash
#define KEYS_PER_CH (SEQ/NCH)  // 512
#define TILES_PER_CH (KEYS_PER_CH/64) // 8
#define SCALE    0.125f        // hd^-0.5

// ---------------- device scratch (no runtime allocs allowed) ----------------
__device__ __half gXh[(size_t)BN_TOK * CDIM];    // x in fp16
__device__ __half gWqkvh[QKV_N * CDIM];          // Wqkv in fp16
__device__ __half gWph[CDIM * CDIM];             // Wproj in fp16
__device__ __half gYh[(size_t)BN_TOK * QKV_N];   // qkv activations fp16
__device__ __half gATh[(size_t)BN_TOK * CDIM];   // attention output fp16
__device__ float  gW2inv[NBH*64*64];
__device__ __half gTth[NBH*64*64];               // (W2inv @ F)^T fp16, [bh][hd][lm]
__device__ float  gFp[(size_t)NBH*NCH*64*64];    // flash partial accumulators
__device__ float  gMp[NBH*NCH*64];
__device__ float  gSp[NBH*NCH*64];

// ---------------- ptx helpers ------------------------------------------------
__device__ __forceinline__ uint32_t smem_u32(const void* p) {
    uint32_t a;
    asm("{ .reg .u64 t; cvta.to.shared.u64 t, %1; cvt.u32.u64 %0, t; }" : "=r"(a) : "l"(p));
    return a;
}
__device__ __forceinline__ void mma_f16(float* d, const uint32_t* a, const uint32_t* b) {
    asm volatile(
        "mma.sync.aligned.m16n8k16.row.col.f32.f16.f16.f32 "
        "{%0,%1,%2,%3}, {%4,%5,%6,%7}, {%8,%9}, {%0,%1,%2,%3};"
        : "+f"(d[0]), "+f"(d[1]), "+f"(d[2]), "+f"(d[3])
        : "r"(a[0]), "r"(a[1]), "r"(a[2]), "r"(a[3]),
          "r"(b[0]), "r"(b[1]));
}
__device__ __forceinline__ void ldsm_x4(uint32_t* r, uint32_t addr) {
    asm volatile("ldmatrix.sync.aligned.m8n8.x4.shared.b16 {%0,%1,%2,%3}, [%4];"
                 : "=r"(r[0]), "=r"(r[1]), "=r"(r[2]), "=r"(r[3]) : "r"(addr));
}
__device__ __forceinline__ void ldsm_x4_t(uint32_t* r, uint32_t addr) {
    asm volatile("ldmatrix.sync.aligned.m8n8.x4.trans.shared.b16 {%0,%1,%2,%3}, [%4];"
                 : "=r"(r[0]), "=r"(r[1]), "=r"(r[2]), "=r"(r[3]) : "r"(addr));
}
#define CP_ASYNC16(dst, src) \
    asm volatile("cp.async.cg.shared.global [%0], [%1], 16;" :: "r"(dst), "l"(src) : "memory")
#define CP_COMMIT() asm volatile("cp.async.commit_group;" ::: "memory")
#define CP_WAIT1()  asm volatile("cp.async.wait_group 1;" ::: "memory")
#define CP_WAIT0()  asm volatile("cp.async.wait_group 0;" ::: "memory")

// ---------------- fused fp32 -> fp16 conversion (x | Wqkv | Wproj) -----------
__global__ void __launch_bounds__(256) cvt_all(const float* __restrict__ x,
                                               const float* __restrict__ wqkv,
                                               const float* __restrict__ wproj)
{
    const int nx = BN_TOK * CDIM;
    const int nw = QKV_N * CDIM;
    const int np = CDIM * CDIM;
    int i = (blockIdx.x * blockDim.x + threadIdx.x) * 8;
    const float* s;
    __half* d;
    if (i < nx)               { s = x + i;              d = gXh + i; }
    else if (i < nx + nw)     { s = wqkv + (i - nx);    d = gWqkvh + (i - nx); }
    else if (i < nx + nw + np){ s = wproj + (i - nx - nw); d = gWph + (i - nx - nw); }
    else return;
    float4 a = *(const float4*)(s);
    float4 b = *(const float4*)(s + 4);
    __half2 h0 = __floats2half2_rn(a.x, a.y);
    __half2 h1 = __floats2half2_rn(a.z, a.w);
    __half2 h2 = __floats2half2_rn(b.x, b.y);
    __half2 h3 = __floats2half2_rn(b.z, b.w);
    uint4 o;
    o.x = *(uint32_t*)&h0; o.y = *(uint32_t*)&h1;
    o.z = *(uint32_t*)&h2; o.w = *(uint32_t*)&h3;
    *(uint4*)d = o;
}

// ---------------- fp16 tensor-core GEMM (round-6 best config) ----------------
#define STG_BYTES 32768          // 16KB A + 16KB B per stage
#define SMEM_GEMMH (3 * STG_BYTES)

__device__ __forceinline__ void stage_copy(uint32_t sbase, const __half* A,
                                           const __half* B, int bm, int bn,
                                           int K, int k0, int tid)
{
    #pragma unroll
    for (int i = 0; i < 4; i++) {
        int lin = tid + i * 256;
        int row = lin >> 3;
        int c   = lin & 7;
        uint32_t dA = sbase + row * 128 + ((c ^ (row & 7)) << 4);
        CP_ASYNC16(dA, A + (size_t)(bm + row) * K + k0 + c * 8);
        uint32_t dB = sbase + 16384 + row * 128 + ((c ^ (row & 7)) << 4);
        CP_ASYNC16(dB, B + (size_t)(bn + row) * K + k0 + c * 8);
    }
}

__global__ void __launch_bounds__(256) gemm_h(const __half* __restrict__ A,
                                              const __half* __restrict__ B,
                                              const float* __restrict__ bias,
                                              void* __restrict__ Cv,
                                              int M, int N, int K, int half_out)
{
    extern __shared__ __align__(128) char smg[];
    const uint32_t sb = smem_u32(smg);

    const int bm = blockIdx.y * 128;
    const int bn = blockIdx.x * 128;
    const int tid  = threadIdx.x;
    const int lane = tid & 31;
    const int warp = tid >> 5;
    const int wm = (warp & 1) * 64;
    const int wn = (warp >> 1) * 32;
    const int g = lane >> 2;
    const int c = lane & 3;
    const int lrow = lane & 15;
    const int lhalf = lane >> 4;

    float acc[4][4][4];
    #pragma unroll
    for (int mi = 0; mi < 4; mi++)
        #pragma unroll
        for (int t = 0; t < 4; t++)
            #pragma unroll
            for (int r = 0; r < 4; r++) acc[mi][t][r] = 0.f;

    const int KT = K >> 6;

    stage_copy(sb, A, B, bm, bn, K, 0, tid);
    CP_COMMIT();
    stage_copy(sb + STG_BYTES, A, B, bm, bn, K, 64, tid);
    CP_COMMIT();

    for (int kt = 0; kt < KT; kt++) {
        CP_WAIT1();
        __syncthreads();

        if (kt + 2 < KT)
            stage_copy(sb + ((kt + 2) % 3) * STG_BYTES, A, B, bm, bn, K, (kt + 2) * 64, tid);
        CP_COMMIT();

        const uint32_t aBase = sb + (kt % 3) * STG_BYTES;
        const uint32_t bBase = aBase + 16384;

        #pragma unroll
        for (int ks = 0; ks < 4; ks++) {
            uint32_t af[4][4], bf[2][4];
            #pragma unroll
            for (int mi = 0; mi < 4; mi++) {
                const int row = wm + mi * 16 + lrow;
                const int ch  = (ks * 2 + lhalf) ^ (row & 7);
                ldsm_x4(af[mi], aBase + row * 128 + (ch << 4));
            }
            #pragma unroll
            for (int nj = 0; nj < 2; nj++) {
                const int row = wn + nj * 16 + lrow;
                const int ch  = (ks * 2 + lhalf) ^ (row & 7);
                ldsm_x4(bf[nj], bBase + row * 128 + (ch << 4));
            }
            #pragma unroll
            for (int mi = 0; mi < 4; mi++) {
                #pragma unroll
                for (int t = 0; t < 4; t++) {
                    const int nj = t >> 1, sub = t & 1;
                    uint32_t b2[2] = { bf[nj][sub], bf[nj][sub + 2] };
                    mma_f16(acc[mi][t], af[mi], b2);
                }
            }
        }
    }

    if (half_out) {
        __half* C = (__half*)Cv;
        #pragma unroll
        for (int mi = 0; mi < 4; mi++) {
            const int row = bm + wm + mi * 16 + g;
            #pragma unroll
            for (int t = 0; t < 4; t++) {
                const int col = bn + wn + (t >> 1) * 16 + (t & 1) * 8 + 2 * c;
                const float b0 = bias[col], b1 = bias[col + 1];
                __half2 o0 = __floats2half2_rn(acc[mi][t][0] + b0, acc[mi][t][1] + b1);
                __half2 o1 = __floats2half2_rn(acc[mi][t][2] + b0, acc[mi][t][3] + b1);
                *(uint32_t*)(C + (size_t)row * N + col)       = *(uint32_t*)&o0;
                *(uint32_t*)(C + (size_t)(row + 8) * N + col) = *(uint32_t*)&o1;
            }
        }
    } else {
        float* C = (float*)Cv;
        #pragma unroll
        for (int mi = 0; mi < 4; mi++) {
            const int row = bm + wm + mi * 16 + g;
            #pragma unroll
            for (int t = 0; t < 4; t++) {
                const int col = bn + wn + (t >> 1) * 16 + (t & 1) * 8 + 2 * c;
                const float b0 = bias[col], b1 = bias[col + 1];
                float2 o0 = make_float2(acc[mi][t][0] + b0, acc[mi][t][1] + b1);
                float2 o1 = make_float2(acc[mi][t][2] + b0, acc[mi][t][3] + b1);
                *(float2*)(C + (size_t)row * N + col)       = o0;
                *(float2*)(C + (size_t)(row + 8) * N + col) = o1;
            }
        }
    }
}

// ---------------- 64x64 fp32 helpers for 128 threads (4x8 tiles) -------------
__device__ __forceinline__ void mm64_nt8(float* C, int ldc,
                                         const float* A, int lda,
                                         const float* B, int ldb,
                                         float scale, int tid)
{
    const int i0 = (tid >> 3) * 4, j0 = (tid & 7) * 8;
    float c[4][8] = {};
    #pragma unroll 4
    for (int d = 0; d < 64; d++) {
        float a[4], bv[8];
        #pragma unroll
        for (int ii = 0; ii < 4; ii++) a[ii]  = A[(i0+ii)*lda + d];
        #pragma unroll
        for (int jj = 0; jj < 8; jj++) bv[jj] = B[(j0+jj)*ldb + d];
        #pragma unroll
        for (int ii = 0; ii < 4; ii++)
            #pragma unroll
            for (int jj = 0; jj < 8; jj++)
                c[ii][jj] += a[ii] * bv[jj];
    }
    #pragma unroll
    for (int ii = 0; ii < 4; ii++)
        #pragma unroll
        for (int jj = 0; jj < 8; jj++)
            C[(i0+ii)*ldc + j0+jj] = scale * c[ii][jj];
}

__device__ __forceinline__ void mm64_nn8(float* C, int ldc,
                                         const float* A, int lda,
                                         const float* B, int ldb, int tid)
{
    const int i0 = (tid >> 3) * 4, j0 = (tid & 7) * 8;
    float c[4][8] = {};
    #pragma unroll 4
    for (int k = 0; k < 64; k++) {
        float a[4], bv[8];
        #pragma unroll
        for (int ii = 0; ii < 4; ii++) a[ii]  = A[(i0+ii)*lda + k];
        #pragma unroll
        for (int jj = 0; jj < 8; jj++) bv[jj] = B[k*ldb + j0+jj];
        #pragma unroll
        for (int ii = 0; ii < 4; ii++)
            #pragma unroll
            for (int jj = 0; jj < 8; jj++)
                c[ii][jj] += a[ii] * bv[jj];
    }
    #pragma unroll
    for (int ii = 0; ii < 4; ii++)
        #pragma unroll
        for (int jj = 0; jj < 8; jj++)
            C[(i0+ii)*ldc + j0+jj] = c[ii][jj];
}

// ---------------- newton branch (128 threads, 3 smem matrices) ----------------
__device__ void k2_newton_body(char* smraw, int bh, int tid)
{
    float* S  = (float*)smraw;
    float* Z  = S  + 4160;
    float* T1 = Z  + 4160;
    __shared__ float red[4];

    const int b = bh >> 3, h = bh & 7;

    for (int e = tid; e < 4096; e += 128) {
        int l = e >> 6, d = e & 63;
        size_t base = (size_t)(b * SEQ + l * LMSTRIDE) * QKV_N + h * HD + d;
        Z [l*65 + d] = __half2float(gYh[base]);
        T1[l*65 + d] = __half2float(gYh[base + CDIM]);
    }
    __syncthreads();

    mm64_nt8(S, 65, Z, 65, T1, 65, SCALE, tid);
    __syncthreads();
    if (tid < 64) {
        float mx = -1e30f;
        for (int j = 0; j < 64; j++) mx = fmaxf(mx, S[tid*65 + j]);
        float s = 0.f;
        for (int j = 0; j < 64; j++) { float p = __expf(S[tid*65+j] - mx); S[tid*65+j] = p; s += p; }
        float inv = 1.f / s;
        for (int j = 0; j < 64; j++) S[tid*65 + j] *= inv;
    }
    __syncthreads();

    float part = 0.f;
    for (int e = tid; e < 4096; e += 128) {
        int i = e >> 6, j = e & 63;
        float v = S[i*65 + j];
        part += v * v;
    }
    #pragma unroll
    for (int o = 16; o; o >>= 1) part += __shfl_xor_sync(0xffffffffu, part, o);
    if ((tid & 31) == 0) red[tid >> 5] = part;
    __syncthreads();
    float fro2 = fmaxf(red[0]+red[1]+red[2]+red[3], 1e-12f);
    float invf = 1.f / fro2;

    for (int e = tid; e < 4096; e += 128) {
        int i = e >> 6, j = e & 63;
        Z[j*65 + i] = S[i*65 + j] * invf;
    }
    __syncthreads();

    const int i0 = (tid >> 3) * 4, j0 = (tid & 7) * 8;
    for (int it = 0; it < 6; it++) {
        mm64_nn8(T1, 65, S, 65, Z, 65, tid);
        __syncthreads();
        float cc[4][8];
        #pragma unroll
        for (int ii = 0; ii < 4; ii++)
            #pragma unroll
            for (int jj = 0; jj < 8; jj++)
                cc[ii][jj] = 2.f * Z[(i0+ii)*65 + j0+jj];
        #pragma unroll 4
        for (int k = 0; k < 64; k++) {
            float a[4], bv[8];
            #pragma unroll
            for (int ii = 0; ii < 4; ii++) a[ii]  = Z[(i0+ii)*65 + k];
            #pragma unroll
            for (int jj = 0; jj < 8; jj++) bv[jj] = T1[k*65 + j0+jj];
            #pragma unroll
            for (int ii = 0; ii < 4; ii++)
                #pragma unroll
                for (int jj = 0; jj < 8; jj++)
                    cc[ii][jj] -= a[ii] * bv[jj];
        }
        __syncthreads();
        #pragma unroll
        for (int ii = 0; ii < 4; ii++)
            #pragma unroll
            for (int jj = 0; jj < 8; jj++)
                Z[(i0+ii)*65 + j0+jj] = cc[ii][jj];
        __syncthreads();
    }

    for (int e = tid; e < 4096; e += 128) {
        int i = e >> 6, j = e & 63;
        gW2inv[bh*4096 + i*64 + j] = Z[i*65 + j];
    }
}

// ---------------- unified flash + newton kernel -------------------------------
#define K3K2_SMEM 49920
#define FLASH_BLOCKS (NBH*NCH)

__global__ void __launch_bounds__(128) k3k2()
{
    extern __shared__ __align__(128) char smu[];
    const int blk = blockIdx.x;
    const int tid = threadIdx.x;

    if (blk < NBH) {
        k2_newton_body(smu, blk, tid);
        return;
    }

    const uint32_t sQ  = smem_u32(smu);
    const uint32_t sKV = sQ + 8192;

    const int fblk = blk - NBH;
    const int bh = fblk & (NBH - 1);
    const int ch = fblk >> 5;
    const int b = bh >> 3, h = bh & 7;
    const int lane = tid & 31;
    const int w = tid >> 5;
    const int g = lane >> 2, c = lane & 3;
    const int lrow = lane & 15, lhalf = lane >> 4;
    const int n0base = ch * KEYS_PER_CH;

    for (int i = tid; i < 512; i += 128) {
        int row = i >> 3, c4 = i & 7;
        CP_ASYNC16(sQ + row*128 + ((c4 ^ (row&7)) << 4),
                   gYh + ((size_t)(b*SEQ + row*LMSTRIDE))*QKV_N + h*HD + c4*8);
    }
    #pragma unroll
    for (int st = 0; st < 2; st++) {
        uint32_t base = sKV + st * 16384;
        for (int i = tid; i < 1024; i += 128) {
            int sel = i >> 9;
            int row = (i >> 3) & 63;
            int c4 = i & 7;
            CP_ASYNC16(base + sel*8192 + row*128 + ((c4 ^ (row&7)) << 4),
                       gYh + ((size_t)(b*SEQ + n0base + st*64 + row))*QKV_N
                           + (sel ? 2*CDIM : CDIM) + h*HD + c4*8);
        }
        CP_COMMIT();
    }

    float m0 = -1e30f, m1 = -1e30f, s0 = 0.f, s1 = 0.f;
    float oc[8][4];
    #pragma unroll
    for (int u = 0; u < 8; u++) { oc[u][0]=oc[u][1]=oc[u][2]=oc[u][3]=0.f; }

    for (int t = 0; t < TILES_PER_CH; t++) {
        CP_WAIT1();
        __syncthreads();
        const uint32_t kb = sKV + (t & 1) * 16384;
        const uint32_t vb = kb + 8192;

        float sc[8][4];
        #pragma unroll
        for (int u = 0; u < 8; u++) { sc[u][0]=sc[u][1]=sc[u][2]=sc[u][3]=0.f; }
        #pragma unroll
        for (int ks = 0; ks < 4; ks++) {
            uint32_t af[4];
            const int qr = w*16 + lrow;
            ldsm_x4(af, sQ + qr*128 + (((ks*2+lhalf) ^ (qr&7)) << 4));
            #pragma unroll
            for (int nj = 0; nj < 4; nj++) {
                uint32_t bf[4];
                const int kr = nj*16 + lrow;
                ldsm_x4(bf, kb + kr*128 + (((ks*2+lhalf) ^ (kr&7)) << 4));
                uint32_t b2a[2] = { bf[0], bf[2] };
                mma_f16(sc[nj*2+0], af, b2a);
                uint32_t b2b[2] = { bf[1], bf[3] };
                mma_f16(sc[nj*2+1], af, b2b);
            }
        }
        float tm0 = -1e30f, tm1 = -1e30f;
        #pragma unroll
        for (int u = 0; u < 8; u++) {
            sc[u][0]*=SCALE; sc[u][1]*=SCALE; sc[u][2]*=SCALE; sc[u][3]*=SCALE;
            tm0 = fmaxf(tm0, fmaxf(sc[u][0], sc[u][1]));
            tm1 = fmaxf(tm1, fmaxf(sc[u][2], sc[u][3]));
        }
        tm0 = fmaxf(tm0, __shfl_xor_sync(0xffffffffu, tm0, 1));
        tm0 = fmaxf(tm0, __shfl_xor_sync(0xffffffffu, tm0, 2));
        tm1 = fmaxf(tm1, __shfl_xor_sync(0xffffffffu, tm1, 1));
        tm1 = fmaxf(tm1, __shfl_xor_sync(0xffffffffu, tm1, 2));
        const float mn0 = fmaxf(m0, tm0), mn1 = fmaxf(m1, tm1);
        const float cr0 = __expf(m0 - mn0), cr1 = __expf(m1 - mn1);
        float rs0 = 0.f, rs1 = 0.f;
        uint32_t pa[4][4];
        #pragma unroll
        for (int u = 0; u < 8; u++) {
            float p0 = __expf(sc[u][0]-mn0), p1 = __expf(sc[u][1]-mn0);
            float p2 = __expf(sc[u][2]-mn1), p3 = __expf(sc[u][3]-mn1);
            rs0 += p0 + p1; rs1 += p2 + p3;
            __half2 hA = __floats2half2_rn(p0, p1);
            __half2 hB = __floats2half2_rn(p2, p3);
            pa[u>>1][(u&1)*2+0] = *(uint32_t*)&hA;
            pa[u>>1][(u&1)*2+1] = *(uint32_t*)&hB;
        }
        rs0 += __shfl_xor_sync(0xffffffffu, rs0, 1);
        rs0 += __shfl_xor_sync(0xffffffffu, rs0, 2);
        rs1 += __shfl_xor_sync(0xffffffffu, rs1, 1);
        rs1 += __shfl_xor_sync(0xffffffffu, rs1, 2);
        s0 = s0*cr0 + rs0; s1 = s1*cr1 + rs1;
        m0 = mn0; m1 = mn1;
        #pragma unroll
        for (int u = 0; u < 8; u++) {
            oc[u][0]*=cr0; oc[u][1]*=cr0; oc[u][2]*=cr1; oc[u][3]*=cr1;
        }
        #pragma unroll
        for (int ks = 0; ks < 4; ks++) {
            #pragma unroll
            for (int nj = 0; nj < 4; nj++) {
                uint32_t bf[4];
                const int rk = ks*16 + (lane&7) + ((lane>>4)&1)*8;
                const int cn = nj*2 + ((lane>>3)&1);
                ldsm_x4_t(bf, vb + rk*128 + (((cn ^ (rk&7))) << 4));
                uint32_t b2a[2] = { bf[0], bf[2] };
                mma_f16(oc[nj*2+0], pa[ks], b2a);
                uint32_t b2b[2] = { bf[1], bf[3] };
                mma_f16(oc[nj*2+1], pa[ks], b2b);
            }
        }
        __syncthreads();
        if (t + 2 < TILES_PER_CH) {
            uint32_t base = sKV + (t & 1) * 16384;
            int n0 = n0base + (t + 2) * 64;
            for (int i = tid; i < 1024; i += 128) {
                int sel = i >> 9;
                int row = (i >> 3) & 63;
                int c4 = i & 7;
                CP_ASYNC16(base + sel*8192 + row*128 + ((c4 ^ (row&7)) << 4),
                           gYh + ((size_t)(b*SEQ + n0 + row))*QKV_N
                               + (sel ? 2*CDIM : CDIM) + h*HD + c4*8);
            }
        }
        CP_COMMIT();
    }

    const size_t fbase = ((size_t)bh*NCH + ch)*4096;
    const int r0a = w*16 + g, r1a = r0a + 8;
    #pragma unroll
    for (int u = 0; u < 8; u++) {
        int col = u*8 + 2*c;
        *(float2*)&gFp[fbase + (size_t)r0a*64 + col] = make_float2(oc[u][0], oc[u][1]);
        *(float2*)&gFp[fbase + (size_t)r1a*64 + col] = make_float2(oc[u][2], oc[u][3]);
    }
    if (c == 0) {
        gMp[(bh*NCH+ch)*64 + r0a] = m0;
        gMp[(bh*NCH+ch)*64 + r1a] = m1;
        gSp[(bh*NCH+ch)*64 + r0a] = s0;
        gSp[(bh*NCH+ch)*64 + r1a] = s1;
    }
}

// ---------------- combine flash partials + T^T = (W2inv @ F)^T ---------------
// grid (NBH, 16), each block owns 4 d-columns. Thread (cg = tid>>6, l = tid&63)
// owns chunks [cg*4, cg*4+4): computes their softmax weights in registers and
// gathers their gFp rows as float4, reducing across cg groups in smem.
__global__ void __launch_bounds__(256) k3_combine()
{
    __shared__ float redm[4][64];
    __shared__ float redd[4][64];
    __shared__ float sFp[4][64][4];
    __shared__ float sF[64*5];       // 64 rows x 4 cols (+1 pad)
    __shared__ float sW[64*64];
    const int bh = blockIdx.x;
    const int d0 = blockIdx.y * 4;
    const int tid = threadIdx.x;
    const int cg = tid >> 6;         // chunk group 0..3
    const int l  = tid & 63;         // landmark row

    // phase A: per-thread chunk stats (registers)
    float mloc[4], sloc[4];
    #pragma unroll
    for (int k = 0; k < 4; k++) {
        int c = cg * 4 + k;
        mloc[k] = gMp[(bh*NCH + c)*64 + l];
        sloc[k] = gSp[(bh*NCH + c)*64 + l];
    }
    redm[cg][l] = fmaxf(fmaxf(mloc[0], mloc[1]), fmaxf(mloc[2], mloc[3]));
    // sW load (float4, independent)
    for (int e = tid; e < 1024; e += 256)
        *(float4*)&sW[e*4] = *(const float4*)&gW2inv[bh*4096 + e*4];
    __syncthreads();
    const float M = fmaxf(fmaxf(redm[0][l], redm[1][l]),
                          fmaxf(redm[2][l], redm[3][l]));
    float wk[4];
    float dloc = 0.f;
    #pragma unroll
    for (int k = 0; k < 4; k++) {
        wk[k] = __expf(mloc[k] - M);
        dloc += wk[k] * sloc[k];
    }
    redd[cg][l] = dloc;
    __syncthreads();
    const float invd = 1.f / (redd[0][l] + redd[1][l] + redd[2][l] + redd[3][l]);

    // phase F: gather this thread's 4 chunks as float4, weighted accumulate
    float4 a4 = make_float4(0.f, 0.f, 0.f, 0.f);
    #pragma unroll
    for (int k = 0; k < 4; k++) {
        int c = cg * 4 + k;
        float4 v = *(const float4*)&gFp[((size_t)bh * NCH + c) * 4096 + l*64 + d0];
        float wgt = wk[k] * invd;
        a4.x += wgt * v.x; a4.y += wgt * v.y; a4.z += wgt * v.z; a4.w += wgt * v.w;
    }
    sFp[cg][l][0] = a4.x; sFp[cg][l][1] = a4.y;
    sFp[cg][l][2] = a4.z; sFp[cg][l][3] = a4.w;
    __syncthreads();
    // reduce over chunk groups into sF
    {
        const int lr = tid >> 2, j = tid & 3;
        sF[lr*5 + j] = sFp[0][lr][j] + sFp[1][lr][j] + sFp[2][lr][j] + sFp[3][lr][j];
    }
    __syncthreads();

    // phase T: T slice = W2inv @ F_slice — one output element per thread
    {
        const int i = tid >> 2, j = tid & 3;
        float cc = 0.f;
        #pragma unroll 8
        for (int k = 0; k < 64; k++)
            cc += sW[i*64 + k] * sF[k*5 + j];
        gTth[bh*4096 + (d0 + j)*64 + i] = __float2half(cc);
    }
}

// ---------------- kernel_1 @ T -> gATh : K/T resident, 4 q-tiles per block ---
#define K4_TILES 4
#define K4_SMEM (8192 + 8192 + 2*16384)   // K + T + double-buffered Q

__global__ void __launch_bounds__(256) k4_out()
{
    extern __shared__ __align__(128) char sm4[];
    const uint32_t sK  = smem_u32(sm4);
    const uint32_t sT  = sK + 8192;
    const uint32_t sQb = sT + 8192;

    const int bh = blockIdx.y;
    const int b = bh >> 3, h = bh & 7;
    const int qt0 = blockIdx.x * K4_TILES;
    const int tid = threadIdx.x;
    const int lane = tid & 31;
    const int w = tid >> 5;
    const int g = lane >> 2, c = lane & 3;
    const int lrow = lane & 15, lhalf = lane >> 4;

    for (int i = tid; i < 512; i += 256) {
        int row = i >> 3, c4 = i & 7;
        uint32_t swz = (uint32_t)((c4 ^ (row & 7)) << 4);
        CP_ASYNC16(sK + row*128 + swz,
                   gYh + ((size_t)(b*SEQ + row*LMSTRIDE))*QKV_N + CDIM + h*HD + c4*8);
        CP_ASYNC16(sT + row*128 + swz,
                   gTth + bh*4096 + row*64 + c4*8);
    }
    for (int i = tid; i < 1024; i += 256) {
        int row = i >> 3, c4 = i & 7;
        uint32_t swz = (uint32_t)((c4 ^ (row & 7)) << 4);
        CP_ASYNC16(sQb + row*128 + swz,
                   gYh + ((size_t)(b*SEQ + qt0*128 + row))*QKV_N + h*HD + c4*8);
    }
    CP_COMMIT();

    for (int t = 0; t < K4_TILES; t++) {
        CP_WAIT0();
        __syncthreads();
        const uint32_t sQ = sQb + (t & 1) * 16384;
        const int n0 = (qt0 + t) * 128;

        if (t + 1 < K4_TILES) {
            const uint32_t nQ = sQb + ((t + 1) & 1) * 16384;
            const int nn0 = (qt0 + t + 1) * 128;
            for (int i = tid; i < 1024; i += 256) {
                int row = i >> 3, c4 = i & 7;
                uint32_t swz = (uint32_t)((c4 ^ (row & 7)) << 4);
                CP_ASYNC16(nQ + row*128 + swz,
                           gYh + ((size_t)(b*SEQ + nn0 + row))*QKV_N + h*HD + c4*8);
            }
        }
        CP_COMMIT();

        float sc[8][4];
        #pragma unroll
        for (int u = 0; u < 8; u++) { sc[u][0]=sc[u][1]=sc[u][2]=sc[u][3]=0.f; }
        #pragma unroll
        for (int ks = 0; ks < 4; ks++) {
            uint32_t af[4];
            const int qr = w*16 + lrow;
            ldsm_x4(af, sQ + qr*128 + (((ks*2+lhalf) ^ (qr&7)) << 4));
            #pragma unroll
            for (int nj = 0; nj < 4; nj++) {
                uint32_t bf[4];
                const int kr = nj*16 + lrow;
                ldsm_x4(bf, sK + kr*128 + (((ks*2+lhalf) ^ (kr&7)) << 4));
                uint32_t b2a[2] = { bf[0], bf[2] };
                mma_f16(sc[nj*2+0], af, b2a);
                uint32_t b2b[2] = { bf[1], bf[3] };
                mma_f16(sc[nj*2+1], af, b2b);
            }
        }
        float tm0 = -1e30f, tm1 = -1e30f;
        #pragma unroll
        for (int u = 0; u < 8; u++) {
            sc[u][0]*=SCALE; sc[u][1]*=SCALE; sc[u][2]*=SCALE; sc[u][3]*=SCALE;
            tm0 = fmaxf(tm0, fmaxf(sc[u][0], sc[u][1]));
            tm1 = fmaxf(tm1, fmaxf(sc[u][2], sc[u][3]));
        }
        tm0 = fmaxf(tm0, __shfl_xor_sync(0xffffffffu, tm0, 1));
        tm0 = fmaxf(tm0, __shfl_xor_sync(0xffffffffu, tm0, 2));
        tm1 = fmaxf(tm1, __shfl_xor_sync(0xffffffffu, tm1, 1));
        tm1 = fmaxf(tm1, __shfl_xor_sync(0xffffffffu, tm1, 2));
        float rs0 = 0.f, rs1 = 0.f;
        uint32_t pa[4][4];
        #pragma unroll
        for (int u = 0; u < 8; u++) {
            float p0 = __expf(sc[u][0]-tm0), p1 = __expf(sc[u][1]-tm0);
            float p2 = __expf(sc[u][2]-tm1), p3 = __expf(sc[u][3]-tm1);
            rs0 += p0 + p1; rs1 += p2 + p3;
            __half2 hA = __floats2half2_rn(p0, p1);
            __half2 hB = __floats2half2_rn(p2, p3);
            pa[u>>1][(u&1)*2+0] = *(uint32_t*)&hA;
            pa[u>>1][(u&1)*2+1] = *(uint32_t*)&hB;
        }
        rs0 += __shfl_xor_sync(0xffffffffu, rs0, 1);
        rs0 += __shfl_xor_sync(0xffffffffu, rs0, 2);
        rs1 += __shfl_xor_sync(0xffffffffu, rs1, 1);
        rs1 += __shfl_xor_sync(0xffffffffu, rs1, 2);
        const float inv0 = 1.f / rs0, inv1 = 1.f / rs1;

        float oc[8][4];
        #pragma unroll
        for (int u = 0; u < 8; u++) { oc[u][0]=oc[u][1]=oc[u][2]=oc[u][3]=0.f; }
        #pragma unroll
        for (int ks = 0; ks < 4; ks++) {
            #pragma unroll
            for (int nj = 0; nj < 4; nj++) {
                uint32_t bf[4];
                const int tr = nj*16 + lrow;
                ldsm_x4(bf, sT + tr*128 + (((ks*2+lhalf) ^ (tr&7)) << 4));
                uint32_t b2a[2] = { bf[0], bf[2] };
                mma_f16(oc[nj*2+0], pa[ks], b2a);
                uint32_t b2b[2] = { bf[1], bf[3] };
                mma_f16(oc[nj*2+1], pa[ks], b2b);
            }
        }

        const int r0a = w*16 + g;
        #pragma unroll
        for (int u = 0; u < 8; u++) {
            int col = u*8 + 2*c;
            __half2 hA = __floats2half2_rn(oc[u][0]*inv0, oc[u][1]*inv0);
            __half2 hB = __floats2half2_rn(oc[u][2]*inv1, oc[u][3]*inv1);
            *(uint32_t*)&gATh[((size_t)(b*SEQ + n0 + r0a))*CDIM + h*HD + col]     = *(uint32_t*)&hA;
            *(uint32_t*)&gATh[((size_t)(b*SEQ + n0 + r0a + 8))*CDIM + h*HD + col] = *(uint32_t*)&hB;
        }
        __syncthreads();
    }
}

// ---------------- launcher ---------------------------------------------------
extern "C" void kernel_launch(void* const* d_in, const int* in_sizes, int n_in,
                              void* d_out, int out_size)
{
    const float* x     = (const float*)d_in[0];
    const float* Wqkv  = (const float*)d_in[1];
    const float* bqkv  = (const float*)d_in[2];
    const float* Wproj = (const float*)d_in[3];
    const float* bproj = (const float*)d_in[4];
    float* out = (float*)d_out;

    cudaFuncSetAttribute(gemm_h, cudaFuncAttributeMaxDynamicSharedMemorySize, SMEM_GEMMH);
    cudaFuncSetAttribute(k3k2,   cudaFuncAttributeMaxDynamicSharedMemorySize, K3K2_SMEM);
    cudaFuncSetAttribute(k4_out, cudaFuncAttributeMaxDynamicSharedMemorySize, K4_SMEM);

    __half *pXh, *pWqkvh, *pWph, *pYh, *pATh;
    cudaGetSymbolAddress((void**)&pXh,    gXh);
    cudaGetSymbolAddress((void**)&pWqkvh, gWqkvh);
    cudaGetSymbolAddress((void**)&pWph,   gWph);
    cudaGetSymbolAddress((void**)&pYh,    gYh);
    cudaGetSymbolAddress((void**)&pATh,   gATh);

    // 0. fused fp32 -> fp16 conversion (x | Wqkv | Wproj)
    {
        int ntot = BN_TOK * CDIM + QKV_N * CDIM + CDIM * CDIM;
        cvt_all<<<(ntot/8 + 255)/256, 256>>>(x, Wqkv, Wproj);
    }

    // 1. QKV projection -> fp16 gYh
    gemm_h<<<dim3(QKV_N/128, BN_TOK/128), 256, SMEM_GEMMH>>>(pXh, pWqkvh, bqkv, pYh, BN_TOK, QKV_N, CDIM, 1);
    // 2+3. newton inverse AND flash partials concurrently (heterogeneous grid)
    k3k2<<<NBH + FLASH_BLOCKS, 128, K3K2_SMEM>>>();
    k3_combine<<<dim3(NBH, 16), 256>>>();
    // 4. out = softmax(q k_lm^T) @ T -> gATh fp16 (4 q-tiles/block, K/T resident)
    k4_out<<<dim3(SEQ/128/K4_TILES, NBH), 256, K4_SMEM>>>();
    // 5. projection: out = gATh @ Wproj^T + bproj (fp32 out)
    gemm_h<<<dim3(CDIM/128, BN_TOK/128), 256, SMEM_GEMMH>>>(pATh, pWph, bproj, out, BN_TOK, CDIM, CDIM, 0);
}